// round 1
// baseline (speedup 1.0000x reference)
#include <cuda_runtime.h>
#include <cuda_bf16.h>
#include <math.h>

// ---------------- problem constants ----------------
#define BWIN   512          // B_ = num windows * batch
#define NTOK   144          // tokens per window
#define CDIM   512          // embed dim
#define HEADS  16
#define DHEAD  32
#define NW     64           // windows per image (mask count)
#define MROWS  (BWIN * NTOK)        // 73728
#define QKVC   (3 * CDIM)           // 1536
#define NPOS   (23 * 23)            // 529 cpb table positions
#define CPBH   512                  // cpb hidden

// ---------------- scratch (device globals; no allocations allowed) ------
__device__ float g_qkv [(size_t)MROWS * QKVC];   // 453 MB
__device__ float g_att [(size_t)MROWS * CDIM];   // 151 MB
__device__ float g_tbl [NPOS * HEADS];
__device__ float g_bias[(size_t)HEADS * NTOK * NTOK];

// =========================================================================
// GEMM  C[m][n] = sum_k A[m][k] * B[n][k]  (+ bias[n])     (NT, row-major)
// BM=BN=128, BK=16, 256 threads, 8x8 per thread
// =========================================================================
template <bool HAS_BIAS>
__global__ __launch_bounds__(256)
void gemm_nt_kernel(const float* __restrict__ A,
                    const float* __restrict__ B,
                    const float* __restrict__ bias,
                    float* __restrict__ C,
                    int M, int N, int K)
{
    __shared__ float As[16][128];
    __shared__ float Bs[16][128];

    const int tid = threadIdx.x;
    const int tx  = tid & 15;          // 0..15  (col group)
    const int ty  = tid >> 4;          // 0..15  (row group)

    const int rowBase = blockIdx.y * 128;
    const int colBase = blockIdx.x * 128;

    const float* Ablk = A + (size_t)rowBase * K;
    const float* Bblk = B + (size_t)colBase * K;

    float acc[8][8];
#pragma unroll
    for (int i = 0; i < 8; i++)
#pragma unroll
        for (int j = 0; j < 8; j++) acc[i][j] = 0.f;

    for (int k0 = 0; k0 < K; k0 += 16) {
        // ---- load 128x16 tiles of A and B (transposed into smem) ----
#pragma unroll
        for (int l = 0; l < 2; l++) {
            int f  = tid + l * 256;     // 0..511 float4 index
            int r  = f >> 2;            // row 0..127
            int kq = f & 3;             // float4 within the 16-wide k slab
            float4 va = *reinterpret_cast<const float4*>(Ablk + (size_t)r * K + k0 + kq * 4);
            As[kq * 4 + 0][r] = va.x;  As[kq * 4 + 1][r] = va.y;
            As[kq * 4 + 2][r] = va.z;  As[kq * 4 + 3][r] = va.w;
            float4 vb = *reinterpret_cast<const float4*>(Bblk + (size_t)r * K + k0 + kq * 4);
            Bs[kq * 4 + 0][r] = vb.x;  Bs[kq * 4 + 1][r] = vb.y;
            Bs[kq * 4 + 2][r] = vb.z;  Bs[kq * 4 + 3][r] = vb.w;
        }
        __syncthreads();

#pragma unroll
        for (int kk = 0; kk < 16; kk++) {
            float4 a0 = *reinterpret_cast<const float4*>(&As[kk][ty * 8]);
            float4 a1 = *reinterpret_cast<const float4*>(&As[kk][ty * 8 + 4]);
            float4 b0 = *reinterpret_cast<const float4*>(&Bs[kk][tx * 8]);
            float4 b1 = *reinterpret_cast<const float4*>(&Bs[kk][tx * 8 + 4]);
            float av[8] = {a0.x, a0.y, a0.z, a0.w, a1.x, a1.y, a1.z, a1.w};
            float bv[8] = {b0.x, b0.y, b0.z, b0.w, b1.x, b1.y, b1.z, b1.w};
#pragma unroll
            for (int i = 0; i < 8; i++)
#pragma unroll
                for (int j = 0; j < 8; j++) acc[i][j] += av[i] * bv[j];
        }
        __syncthreads();
    }

    // ---- epilogue ----
    float bv[8];
#pragma unroll
    for (int j = 0; j < 8; j++)
        bv[j] = HAS_BIAS ? bias[colBase + tx * 8 + j] : 0.f;

#pragma unroll
    for (int i = 0; i < 8; i++) {
        size_t row = (size_t)(rowBase + ty * 8 + i);
        float* cp  = C + row * N + colBase + tx * 8;
        float4 o0 = make_float4(acc[i][0] + bv[0], acc[i][1] + bv[1],
                                acc[i][2] + bv[2], acc[i][3] + bv[3]);
        float4 o1 = make_float4(acc[i][4] + bv[4], acc[i][5] + bv[5],
                                acc[i][6] + bv[6], acc[i][7] + bv[7]);
        *reinterpret_cast<float4*>(cp)     = o0;
        *reinterpret_cast<float4*>(cp + 4) = o1;
    }
}

// =========================================================================
// CPB MLP: tbl[p][h] = relu(rel_table[p] @ w1^T + b1) @ w2^T
// one block per position p (529), 512 threads (16 warps -> 16 heads)
// =========================================================================
__global__ __launch_bounds__(512)
void cpb_tbl_kernel(const float* __restrict__ rel_table,
                    const float* __restrict__ w1,
                    const float* __restrict__ b1,
                    const float* __restrict__ w2,
                    float* __restrict__ tbl)
{
    __shared__ float hid[CPBH];
    int p = blockIdx.x;
    float t0 = rel_table[2 * p], t1 = rel_table[2 * p + 1];
    int j = threadIdx.x;
    hid[j] = fmaxf(t0 * w1[2 * j] + t1 * w1[2 * j + 1] + b1[j], 0.f);
    __syncthreads();

    int warp = j >> 5, lane = j & 31;     // warp == head
    const float* w2h = w2 + warp * CPBH;
    float s = 0.f;
#pragma unroll
    for (int q = lane; q < CPBH; q += 32) s += hid[q] * w2h[q];
#pragma unroll
    for (int o = 16; o > 0; o >>= 1) s += __shfl_xor_sync(0xffffffffu, s, o);
    if (lane == 0) tbl[p * HEADS + warp] = s;
}

// bias[h][i][j] = 16 * sigmoid(tbl[rel_index[i][j]][h])
__global__ void bias_gather_kernel(const float* __restrict__ tbl,
                                   const int* __restrict__ rel_index,
                                   float* __restrict__ bias)
{
    int t = blockIdx.x * blockDim.x + threadIdx.x;
    const int TOT = HEADS * NTOK * NTOK;
    if (t >= TOT) return;
    int h  = t / (NTOK * NTOK);
    int ij = t % (NTOK * NTOK);
    float x = tbl[rel_index[ij] * HEADS + h];
    bias[(size_t)h * NTOK * NTOK + ij] = 16.f / (1.f + __expf(-x));
}

// =========================================================================
// Fused window attention: one CTA per (head, window).
//   q,k L2-normalized, scaled by exp(min(logit_scale, ln 100)),
//   + cpb bias + window mask, softmax, @ v.
// 256 threads = 8 warps. Each warp handles 2 query rows per iteration
// (9 iterations) to halve smem traffic for k and v reads.
// =========================================================================
__global__ __launch_bounds__(256)
void attn_kernel(const float* __restrict__ qkv,
                 const float* __restrict__ bias,
                 const float* __restrict__ mask,
                 const float* __restrict__ logit_scale,
                 float* __restrict__ out)
{
    __shared__ float kn[NTOK][DHEAD + 1];     // padded: j-strided reads conflict-free
    __shared__ float vs[NTOK][DHEAD];
    __shared__ float psm[8][2][NTOK];

    const int h = blockIdx.x;
    const int b = blockIdx.y;
    const int w = b & (NW - 1);

    const int tid = threadIdx.x, warp = tid >> 5, lane = tid & 31;
    const float* base  = qkv + (size_t)b * NTOK * QKVC + h * DHEAD;
    const float scale  = __expf(fminf(logit_scale[h], 4.60517018598809f)); // ln(100)

    // ---- load + normalize K, load V ----
    for (int i = warp; i < NTOK; i += 8) {
        float kd = base[(size_t)i * QKVC + CDIM + lane];
        float vd = base[(size_t)i * QKVC + 2 * CDIM + lane];
        float s = kd * kd;
#pragma unroll
        for (int o = 16; o > 0; o >>= 1) s += __shfl_xor_sync(0xffffffffu, s, o);
        kn[i][lane] = kd * rsqrtf(s);
        vs[i][lane] = vd;
    }
    __syncthreads();

    const float* biasH = bias + (size_t)h * NTOK * NTOK;
    const float* maskW = mask + (size_t)w * NTOK * NTOK;

    for (int r = warp; r < NTOK / 2; r += 8) {
        const int i0 = 2 * r, i1 = i0 + 1;

        // ---- normalized+scaled q for both rows, broadcast to all lanes ----
        float q0 = base[(size_t)i0 * QKVC + lane];
        float q1 = base[(size_t)i1 * QKVC + lane];
        float s0 = q0 * q0, s1 = q1 * q1;
#pragma unroll
        for (int o = 16; o > 0; o >>= 1) {
            s0 += __shfl_xor_sync(0xffffffffu, s0, o);
            s1 += __shfl_xor_sync(0xffffffffu, s1, o);
        }
        q0 *= rsqrtf(s0) * scale;
        q1 *= rsqrtf(s1) * scale;
        float qr0[DHEAD], qr1[DHEAD];
#pragma unroll
        for (int d = 0; d < DHEAD; d++) {
            qr0[d] = __shfl_sync(0xffffffffu, q0, d);
            qr1[d] = __shfl_sync(0xffffffffu, q1, d);
        }

        // ---- scores (144 per row; lane owns j = lane + 32t) ----
        float sc0[5], sc1[5];
        float mx0 = -1e30f, mx1 = -1e30f;
#pragma unroll
        for (int t = 0; t < 5; t++) {
            int j = lane + t * 32;
            if (j < NTOK) {
                float a0 = biasH[i0 * NTOK + j] + maskW[i0 * NTOK + j];
                float a1 = biasH[i1 * NTOK + j] + maskW[i1 * NTOK + j];
#pragma unroll
                for (int d = 0; d < DHEAD; d++) {
                    float kv = kn[j][d];
                    a0 += qr0[d] * kv;
                    a1 += qr1[d] * kv;
                }
                sc0[t] = a0; sc1[t] = a1;
                mx0 = fmaxf(mx0, a0); mx1 = fmaxf(mx1, a1);
            } else { sc0[t] = -1e30f; sc1[t] = -1e30f; }
        }
#pragma unroll
        for (int o = 16; o > 0; o >>= 1) {
            mx0 = fmaxf(mx0, __shfl_xor_sync(0xffffffffu, mx0, o));
            mx1 = fmaxf(mx1, __shfl_xor_sync(0xffffffffu, mx1, o));
        }
        float sum0 = 0.f, sum1 = 0.f;
#pragma unroll
        for (int t = 0; t < 5; t++) {
            int j = lane + t * 32;
            float e0 = __expf(sc0[t] - mx0);
            float e1 = __expf(sc1[t] - mx1);
            if (j >= NTOK) { e0 = 0.f; e1 = 0.f; }
            sc0[t] = e0; sc1[t] = e1;
            sum0 += e0; sum1 += e1;
        }
#pragma unroll
        for (int o = 16; o > 0; o >>= 1) {
            sum0 += __shfl_xor_sync(0xffffffffu, sum0, o);
            sum1 += __shfl_xor_sync(0xffffffffu, sum1, o);
        }
        float inv0 = 1.f / sum0, inv1 = 1.f / sum1;
#pragma unroll
        for (int t = 0; t < 5; t++) {
            int j = lane + t * 32;
            if (j < NTOK) {
                psm[warp][0][j] = sc0[t] * inv0;
                psm[warp][1][j] = sc1[t] * inv1;
            }
        }
        __syncwarp();

        // ---- p @ V : lane owns dim d = lane ----
        float a0 = 0.f, a1 = 0.f;
#pragma unroll 8
        for (int j = 0; j < NTOK; j++) {
            float vv = vs[j][lane];
            a0 += psm[warp][0][j] * vv;
            a1 += psm[warp][1][j] * vv;
        }
        out[((size_t)b * NTOK + i0) * CDIM + h * DHEAD + lane] = a0;
        out[((size_t)b * NTOK + i1) * CDIM + h * DHEAD + lane] = a1;
    }
}

// =========================================================================
// launch
// =========================================================================
extern "C" void kernel_launch(void* const* d_in, const int* in_sizes, int n_in,
                              void* d_out, int out_size)
{
    const float* x           = (const float*)d_in[0];   // (512,144,512)
    const float* mask        = (const float*)d_in[1];   // (64,144,144)
    const float* qkv_w       = (const float*)d_in[2];   // (1536,512)
    const float* logit_scale = (const float*)d_in[3];   // (16,1,1)
    const float* cpb_w1      = (const float*)d_in[4];   // (512,2)
    const float* cpb_b1      = (const float*)d_in[5];   // (512,)
    const float* cpb_w2      = (const float*)d_in[6];   // (16,512)
    const float* proj_w      = (const float*)d_in[7];   // (512,512)
    const float* proj_b      = (const float*)d_in[8];   // (512,)
    const float* rel_table   = (const float*)d_in[9];   // (1,23,23,2)
    const int*   rel_index   = (const int*)d_in[10];    // (144,144)
    float* out = (float*)d_out;

    float *qkv, *att, *tbl, *bias;
    cudaGetSymbolAddress((void**)&qkv,  g_qkv);
    cudaGetSymbolAddress((void**)&att,  g_att);
    cudaGetSymbolAddress((void**)&tbl,  g_tbl);
    cudaGetSymbolAddress((void**)&bias, g_bias);

    // 1) QKV projection: (73728,512) x (1536,512)^T -> (73728,1536)
    {
        dim3 grid(QKVC / 128, MROWS / 128);
        gemm_nt_kernel<false><<<grid, 256>>>(x, qkv_w, nullptr, qkv, MROWS, QKVC, CDIM);
    }

    // 2) relative position bias table + gather (tiny)
    cpb_tbl_kernel<<<NPOS, CPBH>>>(rel_table, cpb_w1, cpb_b1, cpb_w2, tbl);
    {
        int tot = HEADS * NTOK * NTOK;
        bias_gather_kernel<<<(tot + 255) / 256, 256>>>(tbl, rel_index, bias);
    }

    // 3) fused attention: one block per (head, window)
    {
        dim3 grid(HEADS, BWIN);
        attn_kernel<<<grid, 256>>>(qkv, bias, mask, logit_scale, att);
    }

    // 4) output projection: (73728,512) x (512,512)^T + bias -> out
    {
        dim3 grid(CDIM / 128, MROWS / 128);
        gemm_nt_kernel<true><<<grid, 256>>>(att, proj_w, proj_b, out, MROWS, CDIM, CDIM);
    }
}

// round 2
// speedup vs baseline: 2.3193x; 2.3193x over previous
#include <cuda_runtime.h>
#include <cuda_bf16.h>
#include <math.h>
#include <stdint.h>

// ---------------- problem constants ----------------
#define BWIN   512
#define NTOK   144
#define CDIM   512
#define HEADS  16
#define DHEAD  32
#define NW     64
#define MROWS  (BWIN * NTOK)        // 73728
#define QKVC   (3 * CDIM)           // 1536
#define NPOS   (23 * 23)
#define CPBH   512

// ---------------- scratch ----------------
__device__ float g_qkv [(size_t)MROWS * QKVC];
__device__ float g_att [(size_t)MROWS * CDIM];
__device__ float g_tbl [NPOS * HEADS];
__device__ float g_bias[(size_t)HEADS * NTOK * NTOK];

__device__ __forceinline__ uint32_t s2u(const void* p) {
    return (uint32_t)__cvta_generic_to_shared(p);
}
__device__ __forceinline__ uint32_t cvt_tf32(float x) {
    uint32_t u; asm("cvt.rna.tf32.f32 %0, %1;" : "=r"(u) : "f"(x)); return u;
}

// =========================================================================
// TF32 tensor-core GEMM (NT):  C[m][n] = sum_k A[m][k]*B[n][k] (+bias[n])
// BM=BN=128, BK=16, 256 threads (8 warps, 4x2), warp tile 32x64,
// double-buffered smem, ldmatrix fragment loads, mma.sync m16n8k8 tf32.
// =========================================================================
#define GBK   16
#define GLD   20            // smem row stride in floats (16 + 4 pad)

template <bool HAS_BIAS>
__global__ __launch_bounds__(256, 2)
void gemm_tf32_nt(const float* __restrict__ A,
                  const float* __restrict__ B,
                  const float* __restrict__ bias,
                  float* __restrict__ C,
                  int M, int N, int K)
{
    __shared__ uint32_t As[2][128 * GLD];
    __shared__ uint32_t Bs[2][128 * GLD];

    const int tid  = threadIdx.x;
    const int lane = tid & 31;
    const int warp = tid >> 5;
    const int warpM = (warp & 3) * 32;
    const int warpN = (warp >> 2) * 64;
    const int rowBase = blockIdx.y * 128;
    const int colBase = blockIdx.x * 128;

    // global load: each thread handles rows r and r+64, one float4 of k each
    const int r  = tid >> 2;          // 0..63
    const int kq = tid & 3;           // float4 slot in 16-wide k slab
    const float* Ag = A + (size_t)(rowBase + r) * K + kq * 4;
    const float* Bg = B + (size_t)(colBase + r) * K + kq * 4;

    float4 ra0, ra1, rb0, rb1;

    float acc[2][8][4];
#pragma unroll
    for (int mi = 0; mi < 2; mi++)
#pragma unroll
        for (int ni = 0; ni < 8; ni++)
#pragma unroll
            for (int c = 0; c < 4; c++) acc[mi][ni][c] = 0.f;

    // ldmatrix per-lane byte offsets (within one buffer)
    const uint32_t aOff = (uint32_t)((warpM + (lane & 7) + ((lane >> 3) & 1) * 8) * GLD) * 4
                        + (uint32_t)(lane >> 4) * 16;
    const uint32_t bOff = (uint32_t)((warpN + (lane & 7) + ((lane & 16) ? 8 : 0)) * GLD) * 4
                        + (uint32_t)((lane >> 3) & 1) * 16;
    const uint32_t asBase = s2u(As);
    const uint32_t bsBase = s2u(Bs);

#define G_LOAD(it)  {                                            \
        const float* ap = Ag + (it) * GBK;                       \
        const float* bp = Bg + (it) * GBK;                       \
        ra0 = *(const float4*)(ap);                              \
        ra1 = *(const float4*)(ap + (size_t)64 * K);             \
        rb0 = *(const float4*)(bp);                              \
        rb1 = *(const float4*)(bp + (size_t)64 * K);             \
    }
#define G_STS(buf)  {                                                              \
        uint4 u;                                                                   \
        u.x=cvt_tf32(ra0.x); u.y=cvt_tf32(ra0.y); u.z=cvt_tf32(ra0.z); u.w=cvt_tf32(ra0.w); \
        *(uint4*)&As[buf][r * GLD + kq * 4] = u;                                   \
        u.x=cvt_tf32(ra1.x); u.y=cvt_tf32(ra1.y); u.z=cvt_tf32(ra1.z); u.w=cvt_tf32(ra1.w); \
        *(uint4*)&As[buf][(r + 64) * GLD + kq * 4] = u;                            \
        u.x=cvt_tf32(rb0.x); u.y=cvt_tf32(rb0.y); u.z=cvt_tf32(rb0.z); u.w=cvt_tf32(rb0.w); \
        *(uint4*)&Bs[buf][r * GLD + kq * 4] = u;                                   \
        u.x=cvt_tf32(rb1.x); u.y=cvt_tf32(rb1.y); u.z=cvt_tf32(rb1.z); u.w=cvt_tf32(rb1.w); \
        *(uint4*)&Bs[buf][(r + 64) * GLD + kq * 4] = u;                            \
    }

    G_LOAD(0); G_STS(0); __syncthreads();

    const int NIT = K / GBK;
    for (int it = 0; it < NIT; ++it) {
        const int buf = it & 1;
        if (it + 1 < NIT) G_LOAD(it + 1);

        const uint32_t aB = asBase + (uint32_t)buf * (128 * GLD * 4);
        const uint32_t bB = bsBase + (uint32_t)buf * (128 * GLD * 4);

#pragma unroll
        for (int kk = 0; kk < 2; kk++) {
            uint32_t a[2][4], bf[8][2];
#pragma unroll
            for (int mi = 0; mi < 2; mi++) {
                uint32_t addr = aB + aOff + (uint32_t)(mi * 16 * GLD * 4) + (uint32_t)(kk * 32);
                asm volatile("ldmatrix.sync.aligned.m8n8.x4.shared.b16 {%0,%1,%2,%3}, [%4];"
                    : "=r"(a[mi][0]), "=r"(a[mi][1]), "=r"(a[mi][2]), "=r"(a[mi][3])
                    : "r"(addr));
            }
#pragma unroll
            for (int p = 0; p < 4; p++) {
                uint32_t addr = bB + bOff + (uint32_t)(p * 16 * GLD * 4) + (uint32_t)(kk * 32);
                uint32_t r0, r1, r2, r3;
                asm volatile("ldmatrix.sync.aligned.m8n8.x4.shared.b16 {%0,%1,%2,%3}, [%4];"
                    : "=r"(r0), "=r"(r1), "=r"(r2), "=r"(r3)
                    : "r"(addr));
                bf[2 * p][0] = r0; bf[2 * p][1] = r1;
                bf[2 * p + 1][0] = r2; bf[2 * p + 1][1] = r3;
            }
#pragma unroll
            for (int mi = 0; mi < 2; mi++)
#pragma unroll
                for (int ni = 0; ni < 8; ni++)
                    asm volatile(
                        "mma.sync.aligned.m16n8k8.row.col.f32.tf32.tf32.f32 "
                        "{%0,%1,%2,%3},{%4,%5,%6,%7},{%8,%9},{%0,%1,%2,%3};"
                        : "+f"(acc[mi][ni][0]), "+f"(acc[mi][ni][1]),
                          "+f"(acc[mi][ni][2]), "+f"(acc[mi][ni][3])
                        : "r"(a[mi][0]), "r"(a[mi][1]), "r"(a[mi][2]), "r"(a[mi][3]),
                          "r"(bf[ni][0]), "r"(bf[ni][1]));
        }
        if (it + 1 < NIT) G_STS(buf ^ 1);
        __syncthreads();
    }

    // epilogue: c0,c1 @ (g, 2c), c2,c3 @ (g+8, 2c)
    const int g = lane >> 2;
    const int cq = (lane & 3) * 2;
#pragma unroll
    for (int mi = 0; mi < 2; mi++) {
        const int row0 = rowBase + warpM + mi * 16 + g;
#pragma unroll
        for (int ni = 0; ni < 8; ni++) {
            const int col = colBase + warpN + ni * 8 + cq;
            float b0 = 0.f, b1 = 0.f;
            if (HAS_BIAS) { b0 = bias[col]; b1 = bias[col + 1]; }
            *(float2*)&C[(size_t)row0 * N + col] =
                make_float2(acc[mi][ni][0] + b0, acc[mi][ni][1] + b1);
            *(float2*)&C[(size_t)(row0 + 8) * N + col] =
                make_float2(acc[mi][ni][2] + b0, acc[mi][ni][3] + b1);
        }
    }
#undef G_LOAD
#undef G_STS
}

// =========================================================================
// CPB MLP table (tiny)
// =========================================================================
__global__ __launch_bounds__(512)
void cpb_tbl_kernel(const float* __restrict__ rel_table,
                    const float* __restrict__ w1,
                    const float* __restrict__ b1,
                    const float* __restrict__ w2,
                    float* __restrict__ tbl)
{
    __shared__ float hid[CPBH];
    int p = blockIdx.x;
    float t0 = rel_table[2 * p], t1 = rel_table[2 * p + 1];
    int j = threadIdx.x;
    hid[j] = fmaxf(t0 * w1[2 * j] + t1 * w1[2 * j + 1] + b1[j], 0.f);
    __syncthreads();

    int warp = j >> 5, lane = j & 31;
    const float* w2h = w2 + warp * CPBH;
    float s = 0.f;
#pragma unroll
    for (int q = lane; q < CPBH; q += 32) s += hid[q] * w2h[q];
#pragma unroll
    for (int o = 16; o > 0; o >>= 1) s += __shfl_xor_sync(0xffffffffu, s, o);
    if (lane == 0) tbl[p * HEADS + warp] = s;
}

__global__ void bias_gather_kernel(const float* __restrict__ tbl,
                                   const int* __restrict__ rel_index,
                                   float* __restrict__ bias)
{
    int t = blockIdx.x * blockDim.x + threadIdx.x;
    const int TOT = HEADS * NTOK * NTOK;
    if (t >= TOT) return;
    int h  = t / (NTOK * NTOK);
    int ij = t % (NTOK * NTOK);
    float x = tbl[rel_index[ij] * HEADS + h];
    bias[(size_t)h * NTOK * NTOK + ij] = 16.f / (1.f + __expf(-x));
}

// =========================================================================
// Fused window attention: one CTA per (head, window), 8 warps.
// 4 query rows per warp per iteration (quarters k-tile LDS traffic),
// psm interleaved [j][2] so PV reads are LDS.64 broadcasts.
// =========================================================================
__global__ __launch_bounds__(256)
void attn_kernel(const float* __restrict__ qkv,
                 const float* __restrict__ bias,
                 const float* __restrict__ mask,
                 const float* __restrict__ logit_scale,
                 float* __restrict__ out)
{
    __shared__ float kn [NTOK][DHEAD + 1];   // 19.0 KB
    __shared__ float vsm[NTOK][DHEAD];       // 18.4 KB
    __shared__ float psm[8][NTOK][2];        //  9.2 KB   total 46.6 KB

    const int h = blockIdx.x;
    const int b = blockIdx.y;
    const int w = b & (NW - 1);

    const int tid = threadIdx.x, warp = tid >> 5, lane = tid & 31;
    const float* base = qkv + (size_t)b * NTOK * QKVC + h * DHEAD;
    const float scale = __expf(fminf(logit_scale[h], 4.60517018598809f));

    // ---- load + normalize K, load V ----
    for (int i = warp; i < NTOK; i += 8) {
        float kd = base[(size_t)i * QKVC + CDIM + lane];
        float vd = base[(size_t)i * QKVC + 2 * CDIM + lane];
        float s = kd * kd;
#pragma unroll
        for (int o = 16; o > 0; o >>= 1) s += __shfl_xor_sync(0xffffffffu, s, o);
        kn[i][lane]  = kd * rsqrtf(s);
        vsm[i][lane] = vd;
    }
    __syncthreads();

    const float* biasH = bias + (size_t)h * NTOK * NTOK;
    const float* maskW = mask + (size_t)w * NTOK * NTOK;

    for (int rg = warp; rg < NTOK / 4; rg += 8) {
        const int i0 = 4 * rg;

        // lane-owned normalized+scaled q (4 rows)
        float qv[4];
#pragma unroll
        for (int rr = 0; rr < 4; rr++) {
            qv[rr] = base[(size_t)(i0 + rr) * QKVC + lane];
            float s = qv[rr] * qv[rr];
#pragma unroll
            for (int o = 16; o > 0; o >>= 1) s += __shfl_xor_sync(0xffffffffu, s, o);
            qv[rr] *= rsqrtf(s) * scale;
        }

        // init scores with bias+mask
        float acc[4][5];
#pragma unroll
        for (int t = 0; t < 5; t++) {
            int j = lane + 32 * t;
            if (j < NTOK) {
#pragma unroll
                for (int rr = 0; rr < 4; rr++)
                    acc[rr][t] = biasH[(i0 + rr) * NTOK + j] + maskW[(i0 + rr) * NTOK + j];
            } else {
#pragma unroll
                for (int rr = 0; rr < 4; rr++) acc[rr][t] = -1e30f;
            }
        }

        // qk^T in 8-dim chunks: broadcast q chunk via shfl, stream kn once per 4 rows
#pragma unroll
        for (int dc = 0; dc < 4; dc++) {
            float qr[4][8];
#pragma unroll
            for (int rr = 0; rr < 4; rr++)
#pragma unroll
                for (int d8 = 0; d8 < 8; d8++)
                    qr[rr][d8] = __shfl_sync(0xffffffffu, qv[rr], dc * 8 + d8);
#pragma unroll
            for (int t = 0; t < 5; t++) {
                int j = lane + 32 * t;
                if (j < NTOK) {
#pragma unroll
                    for (int d8 = 0; d8 < 8; d8++) {
                        float kv = kn[j][dc * 8 + d8];
                        acc[0][t] += qr[0][d8] * kv;
                        acc[1][t] += qr[1][d8] * kv;
                        acc[2][t] += qr[2][d8] * kv;
                        acc[3][t] += qr[3][d8] * kv;
                    }
                }
            }
        }

        // softmax per row (normalize into acc)
        float inv[4];
#pragma unroll
        for (int rr = 0; rr < 4; rr++) {
            float mx = -1e30f;
#pragma unroll
            for (int t = 0; t < 5; t++) mx = fmaxf(mx, acc[rr][t]);
#pragma unroll
            for (int o = 16; o > 0; o >>= 1)
                mx = fmaxf(mx, __shfl_xor_sync(0xffffffffu, mx, o));
            float sum = 0.f;
#pragma unroll
            for (int t = 0; t < 5; t++) {
                int j = lane + 32 * t;
                float e = (j < NTOK) ? __expf(acc[rr][t] - mx) : 0.f;
                acc[rr][t] = e;
                sum += e;
            }
#pragma unroll
            for (int o = 16; o > 0; o >>= 1) sum += __shfl_xor_sync(0xffffffffu, sum, o);
            inv[rr] = 1.f / sum;
        }

        // PV: two passes of 2 rows, psm interleaved for LDS.64 broadcast reads
#pragma unroll
        for (int pp = 0; pp < 2; pp++) {
#pragma unroll
            for (int t = 0; t < 5; t++) {
                int j = lane + 32 * t;
                if (j < NTOK) {
                    psm[warp][j][0] = acc[2 * pp][t]     * inv[2 * pp];
                    psm[warp][j][1] = acc[2 * pp + 1][t] * inv[2 * pp + 1];
                }
            }
            __syncwarp();
            float a0 = 0.f, a1 = 0.f;
#pragma unroll 4
            for (int j = 0; j < NTOK; j++) {
                float2 p = *(const float2*)&psm[warp][j][0];
                float vv = vsm[j][lane];
                a0 += p.x * vv;
                a1 += p.y * vv;
            }
            out[((size_t)b * NTOK + i0 + 2 * pp)     * CDIM + h * DHEAD + lane] = a0;
            out[((size_t)b * NTOK + i0 + 2 * pp + 1) * CDIM + h * DHEAD + lane] = a1;
            __syncwarp();
        }
    }
}

// =========================================================================
// launch
// =========================================================================
extern "C" void kernel_launch(void* const* d_in, const int* in_sizes, int n_in,
                              void* d_out, int out_size)
{
    const float* x           = (const float*)d_in[0];
    const float* mask        = (const float*)d_in[1];
    const float* qkv_w       = (const float*)d_in[2];
    const float* logit_scale = (const float*)d_in[3];
    const float* cpb_w1      = (const float*)d_in[4];
    const float* cpb_b1      = (const float*)d_in[5];
    const float* cpb_w2      = (const float*)d_in[6];
    const float* proj_w      = (const float*)d_in[7];
    const float* proj_b      = (const float*)d_in[8];
    const float* rel_table   = (const float*)d_in[9];
    const int*   rel_index   = (const int*)d_in[10];
    float* out = (float*)d_out;

    float *qkv, *att, *tbl, *bias;
    cudaGetSymbolAddress((void**)&qkv,  g_qkv);
    cudaGetSymbolAddress((void**)&att,  g_att);
    cudaGetSymbolAddress((void**)&tbl,  g_tbl);
    cudaGetSymbolAddress((void**)&bias, g_bias);

    // 1) QKV projection (tf32 tensor cores)
    {
        dim3 grid(QKVC / 128, MROWS / 128);
        gemm_tf32_nt<false><<<grid, 256>>>(x, qkv_w, nullptr, qkv, MROWS, QKVC, CDIM);
    }

    // 2) relative position bias table + gather
    cpb_tbl_kernel<<<NPOS, CPBH>>>(rel_table, cpb_w1, cpb_b1, cpb_w2, tbl);
    {
        int tot = HEADS * NTOK * NTOK;
        bias_gather_kernel<<<(tot + 255) / 256, 256>>>(tbl, rel_index, bias);
    }

    // 3) fused attention
    {
        dim3 grid(HEADS, BWIN);
        attn_kernel<<<grid, 256>>>(qkv, bias, mask, logit_scale, att);
    }

    // 4) output projection (tf32 tensor cores)
    {
        dim3 grid(CDIM / 128, MROWS / 128);
        gemm_tf32_nt<true><<<grid, 256>>>(att, proj_w, proj_b, out, MROWS, CDIM, CDIM);
    }
}

// round 3
// speedup vs baseline: 2.8284x; 1.2195x over previous
#include <cuda_runtime.h>
#include <cuda_bf16.h>
#include <math.h>
#include <stdint.h>

// ---------------- problem constants ----------------
#define BWIN   512
#define NTOK   144
#define CDIM   512
#define HEADS  16
#define DHEAD  32
#define NW     64
#define MROWS  (BWIN * NTOK)        // 73728
#define QKVC   (3 * CDIM)           // 1536
#define NPOS   (23 * 23)
#define CPBH   512

// ---------------- scratch ----------------
__device__ float g_qkv [(size_t)MROWS * QKVC];
__device__ float g_att [(size_t)MROWS * CDIM];
__device__ float g_tbl [NPOS * HEADS];
__device__ float g_bias[(size_t)HEADS * NTOK * NTOK];

__device__ __forceinline__ uint32_t s2u(const void* p) {
    return (uint32_t)__cvta_generic_to_shared(p);
}
__device__ __forceinline__ uint32_t cvt_tf32(float x) {
    uint32_t u; asm("cvt.rna.tf32.f32 %0, %1;" : "=r"(u) : "f"(x)); return u;
}
__device__ __forceinline__ void tf32_split(float x, uint32_t& hi, uint32_t& lo) {
    hi = cvt_tf32(x);
    lo = cvt_tf32(x - __uint_as_float(hi));
}

#define MMA_TF32(d, a0,a1,a2,a3, b0,b1)                                        \
    asm volatile("mma.sync.aligned.m16n8k8.row.col.f32.tf32.tf32.f32 "         \
                 "{%0,%1,%2,%3},{%4,%5,%6,%7},{%8,%9},{%0,%1,%2,%3};"          \
                 : "+f"(d[0]), "+f"(d[1]), "+f"(d[2]), "+f"(d[3])              \
                 : "r"(a0), "r"(a1), "r"(a2), "r"(a3), "r"(b0), "r"(b1))

#define LDSM_X4(r0,r1,r2,r3, addr)                                             \
    asm volatile("ldmatrix.sync.aligned.m8n8.x4.shared.b16 {%0,%1,%2,%3}, [%4];" \
                 : "=r"(r0), "=r"(r1), "=r"(r2), "=r"(r3) : "r"(addr))

// =========================================================================
// TF32 tensor-core GEMM (NT):  C[m][n] = sum_k A[m][k]*B[n][k] (+bias[n])
// (unchanged from R2 — passing at ~tf32 precision)
// =========================================================================
#define GBK   16
#define GLD   20

template <bool HAS_BIAS>
__global__ __launch_bounds__(256, 2)
void gemm_tf32_nt(const float* __restrict__ A,
                  const float* __restrict__ B,
                  const float* __restrict__ bias,
                  float* __restrict__ C,
                  int M, int N, int K)
{
    __shared__ uint32_t As[2][128 * GLD];
    __shared__ uint32_t Bs[2][128 * GLD];

    const int tid  = threadIdx.x;
    const int lane = tid & 31;
    const int warp = tid >> 5;
    const int warpM = (warp & 3) * 32;
    const int warpN = (warp >> 2) * 64;
    const int rowBase = blockIdx.y * 128;
    const int colBase = blockIdx.x * 128;

    const int r  = tid >> 2;
    const int kq = tid & 3;
    const float* Ag = A + (size_t)(rowBase + r) * K + kq * 4;
    const float* Bg = B + (size_t)(colBase + r) * K + kq * 4;

    float4 ra0, ra1, rb0, rb1;

    float acc[2][8][4];
#pragma unroll
    for (int mi = 0; mi < 2; mi++)
#pragma unroll
        for (int ni = 0; ni < 8; ni++)
#pragma unroll
            for (int c = 0; c < 4; c++) acc[mi][ni][c] = 0.f;

    const uint32_t aOff = (uint32_t)((warpM + (lane & 7) + ((lane >> 3) & 1) * 8) * GLD) * 4
                        + (uint32_t)(lane >> 4) * 16;
    const uint32_t bOff = (uint32_t)((warpN + (lane & 7) + ((lane & 16) ? 8 : 0)) * GLD) * 4
                        + (uint32_t)((lane >> 3) & 1) * 16;
    const uint32_t asBase = s2u(As);
    const uint32_t bsBase = s2u(Bs);

#define G_LOAD(it)  {                                            \
        const float* ap = Ag + (it) * GBK;                       \
        const float* bp = Bg + (it) * GBK;                       \
        ra0 = *(const float4*)(ap);                              \
        ra1 = *(const float4*)(ap + (size_t)64 * K);             \
        rb0 = *(const float4*)(bp);                              \
        rb1 = *(const float4*)(bp + (size_t)64 * K);             \
    }
#define G_STS(buf)  {                                                              \
        uint4 u;                                                                   \
        u.x=cvt_tf32(ra0.x); u.y=cvt_tf32(ra0.y); u.z=cvt_tf32(ra0.z); u.w=cvt_tf32(ra0.w); \
        *(uint4*)&As[buf][r * GLD + kq * 4] = u;                                   \
        u.x=cvt_tf32(ra1.x); u.y=cvt_tf32(ra1.y); u.z=cvt_tf32(ra1.z); u.w=cvt_tf32(ra1.w); \
        *(uint4*)&As[buf][(r + 64) * GLD + kq * 4] = u;                            \
        u.x=cvt_tf32(rb0.x); u.y=cvt_tf32(rb0.y); u.z=cvt_tf32(rb0.z); u.w=cvt_tf32(rb0.w); \
        *(uint4*)&Bs[buf][r * GLD + kq * 4] = u;                                   \
        u.x=cvt_tf32(rb1.x); u.y=cvt_tf32(rb1.y); u.z=cvt_tf32(rb1.z); u.w=cvt_tf32(rb1.w); \
        *(uint4*)&Bs[buf][(r + 64) * GLD + kq * 4] = u;                            \
    }

    G_LOAD(0); G_STS(0); __syncthreads();

    const int NIT = K / GBK;
    for (int it = 0; it < NIT; ++it) {
        const int buf = it & 1;
        if (it + 1 < NIT) G_LOAD(it + 1);

        const uint32_t aB = asBase + (uint32_t)buf * (128 * GLD * 4);
        const uint32_t bB = bsBase + (uint32_t)buf * (128 * GLD * 4);

#pragma unroll
        for (int kk = 0; kk < 2; kk++) {
            uint32_t a[2][4], bf[8][2];
#pragma unroll
            for (int mi = 0; mi < 2; mi++) {
                uint32_t addr = aB + aOff + (uint32_t)(mi * 16 * GLD * 4) + (uint32_t)(kk * 32);
                LDSM_X4(a[mi][0], a[mi][1], a[mi][2], a[mi][3], addr);
            }
#pragma unroll
            for (int p = 0; p < 4; p++) {
                uint32_t addr = bB + bOff + (uint32_t)(p * 16 * GLD * 4) + (uint32_t)(kk * 32);
                uint32_t r0, r1, r2, r3;
                LDSM_X4(r0, r1, r2, r3, addr);
                bf[2 * p][0] = r0; bf[2 * p][1] = r1;
                bf[2 * p + 1][0] = r2; bf[2 * p + 1][1] = r3;
            }
#pragma unroll
            for (int mi = 0; mi < 2; mi++)
#pragma unroll
                for (int ni = 0; ni < 8; ni++)
                    MMA_TF32(acc[mi][ni], a[mi][0], a[mi][1], a[mi][2], a[mi][3],
                             bf[ni][0], bf[ni][1]);
        }
        if (it + 1 < NIT) G_STS(buf ^ 1);
        __syncthreads();
    }

    const int g = lane >> 2;
    const int cq = (lane & 3) * 2;
#pragma unroll
    for (int mi = 0; mi < 2; mi++) {
        const int row0 = rowBase + warpM + mi * 16 + g;
#pragma unroll
        for (int ni = 0; ni < 8; ni++) {
            const int col = colBase + warpN + ni * 8 + cq;
            float b0 = 0.f, b1 = 0.f;
            if (HAS_BIAS) { b0 = bias[col]; b1 = bias[col + 1]; }
            *(float2*)&C[(size_t)row0 * N + col] =
                make_float2(acc[mi][ni][0] + b0, acc[mi][ni][1] + b1);
            *(float2*)&C[(size_t)(row0 + 8) * N + col] =
                make_float2(acc[mi][ni][2] + b0, acc[mi][ni][3] + b1);
        }
    }
#undef G_LOAD
#undef G_STS
}

// =========================================================================
// CPB MLP table + bias gather (tiny, unchanged)
// =========================================================================
__global__ __launch_bounds__(512)
void cpb_tbl_kernel(const float* __restrict__ rel_table,
                    const float* __restrict__ w1,
                    const float* __restrict__ b1,
                    const float* __restrict__ w2,
                    float* __restrict__ tbl)
{
    __shared__ float hid[CPBH];
    int p = blockIdx.x;
    float t0 = rel_table[2 * p], t1 = rel_table[2 * p + 1];
    int j = threadIdx.x;
    hid[j] = fmaxf(t0 * w1[2 * j] + t1 * w1[2 * j + 1] + b1[j], 0.f);
    __syncthreads();

    int warp = j >> 5, lane = j & 31;
    const float* w2h = w2 + warp * CPBH;
    float s = 0.f;
#pragma unroll
    for (int q = lane; q < CPBH; q += 32) s += hid[q] * w2h[q];
#pragma unroll
    for (int o = 16; o > 0; o >>= 1) s += __shfl_xor_sync(0xffffffffu, s, o);
    if (lane == 0) tbl[p * HEADS + warp] = s;
}

__global__ void bias_gather_kernel(const float* __restrict__ tbl,
                                   const int* __restrict__ rel_index,
                                   float* __restrict__ bias)
{
    int t = blockIdx.x * blockDim.x + threadIdx.x;
    const int TOT = HEADS * NTOK * NTOK;
    if (t >= TOT) return;
    int h  = t / (NTOK * NTOK);
    int ij = t % (NTOK * NTOK);
    float x = tbl[rel_index[ij] * HEADS + h];
    bias[(size_t)h * NTOK * NTOK + ij] = 16.f / (1.f + __expf(-x));
}

// =========================================================================
// Tensor-core window attention, 3xTF32 (near-fp32 precision).
// One CTA per (head, window). 9 warps; warp w owns query rows [16w, 16w+16).
// Phase 1: K-hat hi/lo -> smem.  QK^T via mma. softmax in fragments.
// Phase 2: V^T hi/lo -> same smem.  PV via mma (A=P from fragment shuffles).
// =========================================================================
#define KSTRIDE 36           // words per kn row (32 + 4 pad)
#define VSTRIDE 148          // words per vT row (144 + 4 pad)
#define ATTN_SMEM_W (2 * NTOK * KSTRIDE)   // 10368 words = 41472 B (>= vT's 9472)

__global__ __launch_bounds__(288)
void attn_tc_kernel(const float* __restrict__ qkv,
                    const float* __restrict__ bias,
                    const float* __restrict__ mask,
                    const float* __restrict__ logit_scale,
                    float* __restrict__ out)
{
    __shared__ __align__(16) uint32_t smem[ATTN_SMEM_W];

    const int h = blockIdx.x;
    const int b = blockIdx.y;
    const int w = b & (NW - 1);

    const int tid  = threadIdx.x;
    const int lane = tid & 31;
    const int warp = tid / 32;           // 0..8
    const int g  = lane >> 2;            // 0..7
    const int t  = lane & 3;             // 0..3
    const int R0 = warp * 16;

    const float scale = __expf(fminf(logit_scale[h], 4.60517018598809f));
    const float* base = qkv + (size_t)b * NTOK * QKVC + h * DHEAD;

    uint32_t* knHi = smem;
    uint32_t* knLo = smem + NTOK * KSTRIDE;
    const uint32_t knHiB = s2u(knHi);
    const uint32_t knLoB = s2u(knLo);

    // ---------- Q fragments (registers), normalized + scaled ----------
    // qf[kk][0]:(g, 8kk+t)  [1]:(g+8, 8kk+t)  [2]:(g, 8kk+t+4)  [3]:(g+8, ...)
    float qf[4][4];
    {
        const float* q0 = base + (size_t)(R0 + g) * QKVC;
        const float* q1 = base + (size_t)(R0 + g + 8) * QKVC;
#pragma unroll
        for (int kk = 0; kk < 4; kk++) {
            qf[kk][0] = q0[8 * kk + t];
            qf[kk][1] = q1[8 * kk + t];
            qf[kk][2] = q0[8 * kk + t + 4];
            qf[kk][3] = q1[8 * kk + t + 4];
        }
        float s0 = 0.f, s1 = 0.f;
#pragma unroll
        for (int kk = 0; kk < 4; kk++) {
            s0 += qf[kk][0] * qf[kk][0] + qf[kk][2] * qf[kk][2];
            s1 += qf[kk][1] * qf[kk][1] + qf[kk][3] * qf[kk][3];
        }
        s0 += __shfl_xor_sync(0xffffffffu, s0, 1);
        s0 += __shfl_xor_sync(0xffffffffu, s0, 2);
        s1 += __shfl_xor_sync(0xffffffffu, s1, 1);
        s1 += __shfl_xor_sync(0xffffffffu, s1, 2);
        float r0 = rsqrtf(s0) * scale, r1 = rsqrtf(s1) * scale;
#pragma unroll
        for (int kk = 0; kk < 4; kk++) {
            qf[kk][0] *= r0; qf[kk][2] *= r0;
            qf[kk][1] *= r1; qf[kk][3] *= r1;
        }
    }

    // ---------- Phase 1 prep: normalized K (hi/lo) into smem ----------
#pragma unroll
    for (int i = 0; i < 16; i++) {
        int j = R0 + i;
        float kv = base[(size_t)j * QKVC + CDIM + lane];
        float s = kv * kv;
#pragma unroll
        for (int o = 16; o > 0; o >>= 1) s += __shfl_xor_sync(0xffffffffu, s, o);
        kv *= rsqrtf(s);
        uint32_t hi, lo; tf32_split(kv, hi, lo);
        knHi[j * KSTRIDE + lane] = hi;
        knLo[j * KSTRIDE + lane] = lo;
    }
    __syncthreads();

    // ---------- QK^T : scores acc[18][4] ----------
    float acc[18][4];
#pragma unroll
    for (int nt = 0; nt < 18; nt++)
#pragma unroll
        for (int c = 0; c < 4; c++) acc[nt][c] = 0.f;

    const uint32_t ldsmRow = (uint32_t)((lane & 7) + ((lane & 16) ? 8 : 0));
    const uint32_t ldsmCol = (uint32_t)((lane >> 3) & 1) * 16;

#pragma unroll
    for (int kk = 0; kk < 4; kk++) {
        uint32_t ah[4], al[4];
#pragma unroll
        for (int i = 0; i < 4; i++) tf32_split(qf[kk][i], ah[i], al[i]);
#pragma unroll
        for (int gN = 0; gN < 9; gN++) {
            uint32_t off = (uint32_t)(gN * 16 + ldsmRow) * (KSTRIDE * 4) + ldsmCol + kk * 32;
            uint32_t bh0, bh1, bh2, bh3, bl0, bl1, bl2, bl3;
            LDSM_X4(bh0, bh1, bh2, bh3, knHiB + off);
            LDSM_X4(bl0, bl1, bl2, bl3, knLoB + off);
            MMA_TF32(acc[2 * gN],     ah[0], ah[1], ah[2], ah[3], bh0, bh1);
            MMA_TF32(acc[2 * gN],     ah[0], ah[1], ah[2], ah[3], bl0, bl1);
            MMA_TF32(acc[2 * gN],     al[0], al[1], al[2], al[3], bh0, bh1);
            MMA_TF32(acc[2 * gN + 1], ah[0], ah[1], ah[2], ah[3], bh2, bh3);
            MMA_TF32(acc[2 * gN + 1], ah[0], ah[1], ah[2], ah[3], bl2, bl3);
            MMA_TF32(acc[2 * gN + 1], al[0], al[1], al[2], al[3], bh2, bh3);
        }
    }

    // ---------- bias + mask + softmax (unnormalized exp in acc) ----------
    {
        const float* biasR0 = bias + (size_t)h * NTOK * NTOK + (size_t)(R0 + g) * NTOK + 2 * t;
        const float* biasR1 = biasR0 + 8 * NTOK;
        const float* maskR0 = mask + (size_t)w * NTOK * NTOK + (size_t)(R0 + g) * NTOK + 2 * t;
        const float* maskR1 = maskR0 + 8 * NTOK;
#pragma unroll
        for (int nt = 0; nt < 18; nt++) {
            float2 bb0 = *(const float2*)(biasR0 + 8 * nt);
            float2 mm0 = *(const float2*)(maskR0 + 8 * nt);
            float2 bb1 = *(const float2*)(biasR1 + 8 * nt);
            float2 mm1 = *(const float2*)(maskR1 + 8 * nt);
            acc[nt][0] += bb0.x + mm0.x;
            acc[nt][1] += bb0.y + mm0.y;
            acc[nt][2] += bb1.x + mm1.x;
            acc[nt][3] += bb1.y + mm1.y;
        }
    }
    float inv0, inv1;
    {
        float mx0 = -1e30f, mx1 = -1e30f;
#pragma unroll
        for (int nt = 0; nt < 18; nt++) {
            mx0 = fmaxf(mx0, fmaxf(acc[nt][0], acc[nt][1]));
            mx1 = fmaxf(mx1, fmaxf(acc[nt][2], acc[nt][3]));
        }
        mx0 = fmaxf(mx0, __shfl_xor_sync(0xffffffffu, mx0, 1));
        mx0 = fmaxf(mx0, __shfl_xor_sync(0xffffffffu, mx0, 2));
        mx1 = fmaxf(mx1, __shfl_xor_sync(0xffffffffu, mx1, 1));
        mx1 = fmaxf(mx1, __shfl_xor_sync(0xffffffffu, mx1, 2));
        float sm0 = 0.f, sm1 = 0.f;
#pragma unroll
        for (int nt = 0; nt < 18; nt++) {
            acc[nt][0] = __expf(acc[nt][0] - mx0);
            acc[nt][1] = __expf(acc[nt][1] - mx0);
            acc[nt][2] = __expf(acc[nt][2] - mx1);
            acc[nt][3] = __expf(acc[nt][3] - mx1);
            sm0 += acc[nt][0] + acc[nt][1];
            sm1 += acc[nt][2] + acc[nt][3];
        }
        sm0 += __shfl_xor_sync(0xffffffffu, sm0, 1);
        sm0 += __shfl_xor_sync(0xffffffffu, sm0, 2);
        sm1 += __shfl_xor_sync(0xffffffffu, sm1, 1);
        sm1 += __shfl_xor_sync(0xffffffffu, sm1, 2);
        inv0 = 1.f / sm0;
        inv1 = 1.f / sm1;
    }

    // ---------- Phase 2 prep: V^T (hi/lo) into the SAME smem ----------
    __syncthreads();                       // everyone done reading kn
    uint32_t* vtHi = smem;
    uint32_t* vtLo = smem + DHEAD * VSTRIDE;
    const uint32_t vtHiB = s2u(vtHi);
    const uint32_t vtLoB = s2u(vtLo);
#pragma unroll
    for (int i = 0; i < 16; i++) {
        int j = R0 + i;
        float vv = base[(size_t)j * QKVC + 2 * CDIM + lane];
        uint32_t hi, lo; tf32_split(vv, hi, lo);
        vtHi[lane * VSTRIDE + j] = hi;     // transpose scatter (4-way conflict, once)
        vtLo[lane * VSTRIDE + j] = lo;
    }
    __syncthreads();

    // ---------- PV : out = P @ V  (A = P via fragment shuffles) ----------
    float pv[4][4];
#pragma unroll
    for (int nt = 0; nt < 4; nt++)
#pragma unroll
        for (int c = 0; c < 4; c++) pv[nt][c] = 0.f;

    const int src1 = (lane & 28) | (t >> 1);
    const int src2 = src1 + 2;
    const bool oddc = (t & 1);

#pragma unroll
    for (int kk = 0; kk < 18; kk++) {
        float s00 = __shfl_sync(0xffffffffu, acc[kk][0], src1);
        float s01 = __shfl_sync(0xffffffffu, acc[kk][1], src1);
        float s02 = __shfl_sync(0xffffffffu, acc[kk][0], src2);
        float s03 = __shfl_sync(0xffffffffu, acc[kk][1], src2);
        float s10 = __shfl_sync(0xffffffffu, acc[kk][2], src1);
        float s11 = __shfl_sync(0xffffffffu, acc[kk][3], src1);
        float s12 = __shfl_sync(0xffffffffu, acc[kk][2], src2);
        float s13 = __shfl_sync(0xffffffffu, acc[kk][3], src2);
        float a0 = oddc ? s01 : s00;   // P(g,    8kk+t)
        float a1 = oddc ? s11 : s10;   // P(g+8,  8kk+t)
        float a2 = oddc ? s03 : s02;   // P(g,    8kk+t+4)
        float a3 = oddc ? s13 : s12;   // P(g+8,  8kk+t+4)
        uint32_t ah[4], al[4];
        tf32_split(a0, ah[0], al[0]);
        tf32_split(a1, ah[1], al[1]);
        tf32_split(a2, ah[2], al[2]);
        tf32_split(a3, ah[3], al[3]);
#pragma unroll
        for (int p = 0; p < 2; p++) {
            uint32_t off = (uint32_t)(p * 16 + ldsmRow) * (VSTRIDE * 4) + ldsmCol + kk * 32;
            uint32_t bh0, bh1, bh2, bh3, bl0, bl1, bl2, bl3;
            LDSM_X4(bh0, bh1, bh2, bh3, vtHiB + off);
            LDSM_X4(bl0, bl1, bl2, bl3, vtLoB + off);
            MMA_TF32(pv[2 * p],     ah[0], ah[1], ah[2], ah[3], bh0, bh1);
            MMA_TF32(pv[2 * p],     ah[0], ah[1], ah[2], ah[3], bl0, bl1);
            MMA_TF32(pv[2 * p],     al[0], al[1], al[2], al[3], bh0, bh1);
            MMA_TF32(pv[2 * p + 1], ah[0], ah[1], ah[2], ah[3], bh2, bh3);
            MMA_TF32(pv[2 * p + 1], ah[0], ah[1], ah[2], ah[3], bl2, bl3);
            MMA_TF32(pv[2 * p + 1], al[0], al[1], al[2], al[3], bh2, bh3);
        }
    }

    // ---------- epilogue: normalize + store ----------
    {
        float* o0 = out + ((size_t)b * NTOK + R0 + g) * CDIM + h * DHEAD + 2 * t;
        float* o1 = o0 + (size_t)8 * CDIM;
#pragma unroll
        for (int nt = 0; nt < 4; nt++) {
            *(float2*)(o0 + 8 * nt) = make_float2(pv[nt][0] * inv0, pv[nt][1] * inv0);
            *(float2*)(o1 + 8 * nt) = make_float2(pv[nt][2] * inv1, pv[nt][3] * inv1);
        }
    }
}

// =========================================================================
// launch
// =========================================================================
extern "C" void kernel_launch(void* const* d_in, const int* in_sizes, int n_in,
                              void* d_out, int out_size)
{
    const float* x           = (const float*)d_in[0];
    const float* mask        = (const float*)d_in[1];
    const float* qkv_w       = (const float*)d_in[2];
    const float* logit_scale = (const float*)d_in[3];
    const float* cpb_w1      = (const float*)d_in[4];
    const float* cpb_b1      = (const float*)d_in[5];
    const float* cpb_w2      = (const float*)d_in[6];
    const float* proj_w      = (const float*)d_in[7];
    const float* proj_b      = (const float*)d_in[8];
    const float* rel_table   = (const float*)d_in[9];
    const int*   rel_index   = (const int*)d_in[10];
    float* out = (float*)d_out;

    float *qkv, *att, *tbl, *bias;
    cudaGetSymbolAddress((void**)&qkv,  g_qkv);
    cudaGetSymbolAddress((void**)&att,  g_att);
    cudaGetSymbolAddress((void**)&tbl,  g_tbl);
    cudaGetSymbolAddress((void**)&bias, g_bias);

    // 1) QKV projection (tf32 tensor cores)
    {
        dim3 grid(QKVC / 128, MROWS / 128);
        gemm_tf32_nt<false><<<grid, 256>>>(x, qkv_w, nullptr, qkv, MROWS, QKVC, CDIM);
    }

    // 2) relative position bias table + gather
    cpb_tbl_kernel<<<NPOS, CPBH>>>(rel_table, cpb_w1, cpb_b1, cpb_w2, tbl);
    {
        int tot = HEADS * NTOK * NTOK;
        bias_gather_kernel<<<(tot + 255) / 256, 256>>>(tbl, rel_index, bias);
    }

    // 3) tensor-core attention (3xTF32)
    {
        dim3 grid(HEADS, BWIN);
        attn_tc_kernel<<<grid, 288>>>(qkv, bias, mask, logit_scale, att);
    }

    // 4) output projection (tf32 tensor cores)
    {
        dim3 grid(CDIM / 128, MROWS / 128);
        gemm_tf32_nt<true><<<grid, 256>>>(att, proj_w, proj_b, out, MROWS, CDIM, CDIM);
    }
}

// round 4
// speedup vs baseline: 2.8694x; 1.0145x over previous
#include <cuda_runtime.h>
#include <cuda_bf16.h>
#include <math.h>
#include <stdint.h>

// ---------------- problem constants ----------------
#define BWIN   512
#define NTOK   144
#define CDIM   512
#define HEADS  16
#define DHEAD  32
#define NW     64
#define MROWS  (BWIN * NTOK)        // 73728
#define QKVC   (3 * CDIM)           // 1536
#define NPOS   (23 * 23)
#define CPBH   512

// ---------------- scratch ----------------
__device__ float g_qkv [(size_t)MROWS * QKVC];
__device__ float g_att [(size_t)MROWS * CDIM];
__device__ float g_tbl [NPOS * HEADS];
__device__ float g_bias[(size_t)HEADS * NTOK * NTOK];

__device__ __forceinline__ uint32_t s2u(const void* p) {
    return (uint32_t)__cvta_generic_to_shared(p);
}
__device__ __forceinline__ uint32_t cvt_tf32(float x) {
    uint32_t u; asm("cvt.rna.tf32.f32 %0, %1;" : "=r"(u) : "f"(x)); return u;
}
__device__ __forceinline__ void tf32_split(float x, uint32_t& hi, uint32_t& lo) {
    hi = cvt_tf32(x);
    lo = cvt_tf32(x - __uint_as_float(hi));
}

#define MMA_TF32(d, a0,a1,a2,a3, b0,b1)                                        \
    asm volatile("mma.sync.aligned.m16n8k8.row.col.f32.tf32.tf32.f32 "         \
                 "{%0,%1,%2,%3},{%4,%5,%6,%7},{%8,%9},{%0,%1,%2,%3};"          \
                 : "+f"(d[0]), "+f"(d[1]), "+f"(d[2]), "+f"(d[3])              \
                 : "r"(a0), "r"(a1), "r"(a2), "r"(a3), "r"(b0), "r"(b1))

#define LDSM_X4(r0,r1,r2,r3, addr)                                             \
    asm volatile("ldmatrix.sync.aligned.m8n8.x4.shared.b16 {%0,%1,%2,%3}, [%4];" \
                 : "=r"(r0), "=r"(r1), "=r"(r2), "=r"(r3) : "r"(addr))

// =========================================================================
// TF32 tensor-core GEMM (NT) — unchanged from R3
// =========================================================================
#define GBK   16
#define GLD   20

template <bool HAS_BIAS>
__global__ __launch_bounds__(256, 2)
void gemm_tf32_nt(const float* __restrict__ A,
                  const float* __restrict__ B,
                  const float* __restrict__ bias,
                  float* __restrict__ C,
                  int M, int N, int K)
{
    __shared__ uint32_t As[2][128 * GLD];
    __shared__ uint32_t Bs[2][128 * GLD];

    const int tid  = threadIdx.x;
    const int lane = tid & 31;
    const int warp = tid >> 5;
    const int warpM = (warp & 3) * 32;
    const int warpN = (warp >> 2) * 64;
    const int rowBase = blockIdx.y * 128;
    const int colBase = blockIdx.x * 128;

    const int r  = tid >> 2;
    const int kq = tid & 3;
    const float* Ag = A + (size_t)(rowBase + r) * K + kq * 4;
    const float* Bg = B + (size_t)(colBase + r) * K + kq * 4;

    float4 ra0, ra1, rb0, rb1;

    float acc[2][8][4];
#pragma unroll
    for (int mi = 0; mi < 2; mi++)
#pragma unroll
        for (int ni = 0; ni < 8; ni++)
#pragma unroll
            for (int c = 0; c < 4; c++) acc[mi][ni][c] = 0.f;

    const uint32_t aOff = (uint32_t)((warpM + (lane & 7) + ((lane >> 3) & 1) * 8) * GLD) * 4
                        + (uint32_t)(lane >> 4) * 16;
    const uint32_t bOff = (uint32_t)((warpN + (lane & 7) + ((lane & 16) ? 8 : 0)) * GLD) * 4
                        + (uint32_t)((lane >> 3) & 1) * 16;
    const uint32_t asBase = s2u(As);
    const uint32_t bsBase = s2u(Bs);

#define G_LOAD(it)  {                                            \
        const float* ap = Ag + (it) * GBK;                       \
        const float* bp = Bg + (it) * GBK;                       \
        ra0 = *(const float4*)(ap);                              \
        ra1 = *(const float4*)(ap + (size_t)64 * K);             \
        rb0 = *(const float4*)(bp);                              \
        rb1 = *(const float4*)(bp + (size_t)64 * K);             \
    }
#define G_STS(buf)  {                                                              \
        uint4 u;                                                                   \
        u.x=cvt_tf32(ra0.x); u.y=cvt_tf32(ra0.y); u.z=cvt_tf32(ra0.z); u.w=cvt_tf32(ra0.w); \
        *(uint4*)&As[buf][r * GLD + kq * 4] = u;                                   \
        u.x=cvt_tf32(ra1.x); u.y=cvt_tf32(ra1.y); u.z=cvt_tf32(ra1.z); u.w=cvt_tf32(ra1.w); \
        *(uint4*)&As[buf][(r + 64) * GLD + kq * 4] = u;                            \
        u.x=cvt_tf32(rb0.x); u.y=cvt_tf32(rb0.y); u.z=cvt_tf32(rb0.z); u.w=cvt_tf32(rb0.w); \
        *(uint4*)&Bs[buf][r * GLD + kq * 4] = u;                                   \
        u.x=cvt_tf32(rb1.x); u.y=cvt_tf32(rb1.y); u.z=cvt_tf32(rb1.z); u.w=cvt_tf32(rb1.w); \
        *(uint4*)&Bs[buf][(r + 64) * GLD + kq * 4] = u;                            \
    }

    G_LOAD(0); G_STS(0); __syncthreads();

    const int NIT = K / GBK;
    for (int it = 0; it < NIT; ++it) {
        const int buf = it & 1;
        if (it + 1 < NIT) G_LOAD(it + 1);

        const uint32_t aB = asBase + (uint32_t)buf * (128 * GLD * 4);
        const uint32_t bB = bsBase + (uint32_t)buf * (128 * GLD * 4);

#pragma unroll
        for (int kk = 0; kk < 2; kk++) {
            uint32_t a[2][4], bf[8][2];
#pragma unroll
            for (int mi = 0; mi < 2; mi++) {
                uint32_t addr = aB + aOff + (uint32_t)(mi * 16 * GLD * 4) + (uint32_t)(kk * 32);
                LDSM_X4(a[mi][0], a[mi][1], a[mi][2], a[mi][3], addr);
            }
#pragma unroll
            for (int p = 0; p < 4; p++) {
                uint32_t addr = bB + bOff + (uint32_t)(p * 16 * GLD * 4) + (uint32_t)(kk * 32);
                uint32_t r0, r1, r2, r3;
                LDSM_X4(r0, r1, r2, r3, addr);
                bf[2 * p][0] = r0; bf[2 * p][1] = r1;
                bf[2 * p + 1][0] = r2; bf[2 * p + 1][1] = r3;
            }
#pragma unroll
            for (int mi = 0; mi < 2; mi++)
#pragma unroll
                for (int ni = 0; ni < 8; ni++)
                    MMA_TF32(acc[mi][ni], a[mi][0], a[mi][1], a[mi][2], a[mi][3],
                             bf[ni][0], bf[ni][1]);
        }
        if (it + 1 < NIT) G_STS(buf ^ 1);
        __syncthreads();
    }

    const int g = lane >> 2;
    const int cq = (lane & 3) * 2;
#pragma unroll
    for (int mi = 0; mi < 2; mi++) {
        const int row0 = rowBase + warpM + mi * 16 + g;
#pragma unroll
        for (int ni = 0; ni < 8; ni++) {
            const int col = colBase + warpN + ni * 8 + cq;
            float b0 = 0.f, b1 = 0.f;
            if (HAS_BIAS) { b0 = bias[col]; b1 = bias[col + 1]; }
            *(float2*)&C[(size_t)row0 * N + col] =
                make_float2(acc[mi][ni][0] + b0, acc[mi][ni][1] + b1);
            *(float2*)&C[(size_t)(row0 + 8) * N + col] =
                make_float2(acc[mi][ni][2] + b0, acc[mi][ni][3] + b1);
        }
    }
#undef G_LOAD
#undef G_STS
}

// =========================================================================
// CPB MLP table + bias gather (tiny, unchanged)
// =========================================================================
__global__ __launch_bounds__(512)
void cpb_tbl_kernel(const float* __restrict__ rel_table,
                    const float* __restrict__ w1,
                    const float* __restrict__ b1,
                    const float* __restrict__ w2,
                    float* __restrict__ tbl)
{
    __shared__ float hid[CPBH];
    int p = blockIdx.x;
    float t0 = rel_table[2 * p], t1 = rel_table[2 * p + 1];
    int j = threadIdx.x;
    hid[j] = fmaxf(t0 * w1[2 * j] + t1 * w1[2 * j + 1] + b1[j], 0.f);
    __syncthreads();

    int warp = j >> 5, lane = j & 31;
    const float* w2h = w2 + warp * CPBH;
    float s = 0.f;
#pragma unroll
    for (int q = lane; q < CPBH; q += 32) s += hid[q] * w2h[q];
#pragma unroll
    for (int o = 16; o > 0; o >>= 1) s += __shfl_xor_sync(0xffffffffu, s, o);
    if (lane == 0) tbl[p * HEADS + warp] = s;
}

__global__ void bias_gather_kernel(const float* __restrict__ tbl,
                                   const int* __restrict__ rel_index,
                                   float* __restrict__ bias)
{
    int t = blockIdx.x * blockDim.x + threadIdx.x;
    const int TOT = HEADS * NTOK * NTOK;
    if (t >= TOT) return;
    int h  = t / (NTOK * NTOK);
    int ij = t % (NTOK * NTOK);
    float x = tbl[rel_index[ij] * HEADS + h];
    bias[(size_t)h * NTOK * NTOK + ij] = 16.f / (1.f + __expf(-x));
}

// =========================================================================
// Tensor-core window attention v2 (3xTF32), 18 warps / CTA.
// Warp pair (p, p+9) owns query rows [16p,16p+16): half0 -> key cols 0..63,
// half1 -> cols 64..143. No-max softmax (scores bounded); sum exchanged via
// smem; PV partials combined pairwise. Dynamic smem ~101 KB.
// =========================================================================
#define KSTRIDE 36
#define VSTRIDE 148
#define PVSTR   18

#define KHI_OFF 0
#define KLO_OFF (NTOK * KSTRIDE)                       // 5184
#define VHI_OFF (2 * NTOK * KSTRIDE)                   // 10368
#define VLO_OFF (VHI_OFF + DHEAD * VSTRIDE)            // 15104
#define PVB_OFF (VLO_OFF + DHEAD * VSTRIDE)            // 19840
#define SUM_OFF (PVB_OFF + 9 * 32 * PVSTR)             // 25024
#define ATTN_SMEM_BYTES ((SUM_OFF + 9 * 2 * 16) * 4)   // 101248

__global__ __launch_bounds__(576, 1)
void attn_tc2_kernel(const float* __restrict__ qkv,
                     const float* __restrict__ bias,
                     const float* __restrict__ mask,
                     const float* __restrict__ logit_scale,
                     float* __restrict__ out)
{
    extern __shared__ __align__(16) uint32_t dsm[];

    const int h = blockIdx.x;
    const int b = blockIdx.y;
    const int w = b & (NW - 1);

    const int tid  = threadIdx.x;
    const int lane = tid & 31;
    const int warp = tid >> 5;           // 0..17
    const int pair = warp % 9;           // row tile
    const int half = warp / 9;           // 0: cols 0..63, 1: cols 64..143
    const int ng   = half ? 5 : 4;       // 16-col groups owned
    const int hbase = half ? 64 : 0;
    const int g  = lane >> 2;
    const int t  = lane & 3;
    const int R0 = pair * 16;

    const float scale = __expf(fminf(logit_scale[h], 4.60517018598809f));
    const float* base = qkv + (size_t)b * NTOK * QKVC + h * DHEAD;

    uint32_t* knHi = dsm + KHI_OFF;
    uint32_t* knLo = dsm + KLO_OFF;
    uint32_t* vtHi = dsm + VHI_OFF;
    uint32_t* vtLo = dsm + VLO_OFF;
    float*    pvb  = (float*)(dsm + PVB_OFF);
    float*    sumb = (float*)(dsm + SUM_OFF);
    const uint32_t knHiB = s2u(knHi);
    const uint32_t knLoB = s2u(knLo);
    const uint32_t vtHiB = s2u(vtHi);
    const uint32_t vtLoB = s2u(vtLo);

    // ---------- load K (normalized, hi/lo) and V^T (hi/lo): 8 rows/warp ----
#pragma unroll
    for (int i = 0; i < 8; i++) {
        int j = warp * 8 + i;
        float kv = base[(size_t)j * QKVC + CDIM + lane];
        float s = kv * kv;
#pragma unroll
        for (int o = 16; o > 0; o >>= 1) s += __shfl_xor_sync(0xffffffffu, s, o);
        kv *= rsqrtf(s);
        uint32_t khi, klo; tf32_split(kv, khi, klo);
        knHi[j * KSTRIDE + lane] = khi;
        knLo[j * KSTRIDE + lane] = klo;

        float vv = base[(size_t)j * QKVC + 2 * CDIM + lane];
        uint32_t vhi, vlo; tf32_split(vv, vhi, vlo);
        vtHi[lane * VSTRIDE + j] = vhi;
        vtLo[lane * VSTRIDE + j] = vlo;
    }

    // ---------- Q fragments (normalized + scaled) ----------
    float qf[4][4];
    {
        const float* q0 = base + (size_t)(R0 + g) * QKVC;
        const float* q1 = base + (size_t)(R0 + g + 8) * QKVC;
#pragma unroll
        for (int kk = 0; kk < 4; kk++) {
            qf[kk][0] = q0[8 * kk + t];
            qf[kk][1] = q1[8 * kk + t];
            qf[kk][2] = q0[8 * kk + t + 4];
            qf[kk][3] = q1[8 * kk + t + 4];
        }
        float s0 = 0.f, s1 = 0.f;
#pragma unroll
        for (int kk = 0; kk < 4; kk++) {
            s0 += qf[kk][0] * qf[kk][0] + qf[kk][2] * qf[kk][2];
            s1 += qf[kk][1] * qf[kk][1] + qf[kk][3] * qf[kk][3];
        }
        s0 += __shfl_xor_sync(0xffffffffu, s0, 1);
        s0 += __shfl_xor_sync(0xffffffffu, s0, 2);
        s1 += __shfl_xor_sync(0xffffffffu, s1, 1);
        s1 += __shfl_xor_sync(0xffffffffu, s1, 2);
        float r0 = rsqrtf(s0) * scale, r1 = rsqrtf(s1) * scale;
#pragma unroll
        for (int kk = 0; kk < 4; kk++) {
            qf[kk][0] *= r0; qf[kk][2] *= r0;
            qf[kk][1] *= r1; qf[kk][3] *= r1;
        }
    }
    __syncthreads();

    // ---------- QK^T (3xTF32) into acc[2*ng][4] ----------
    float acc[10][4];
#pragma unroll
    for (int nt = 0; nt < 10; nt++)
#pragma unroll
        for (int c = 0; c < 4; c++) acc[nt][c] = 0.f;

    const uint32_t ldsmRow = (uint32_t)((lane & 7) + ((lane & 16) ? 8 : 0));
    const uint32_t ldsmCol = (uint32_t)((lane >> 3) & 1) * 16;

#pragma unroll
    for (int kk = 0; kk < 4; kk++) {
        uint32_t ah[4], al[4];
#pragma unroll
        for (int i = 0; i < 4; i++) tf32_split(qf[kk][i], ah[i], al[i]);
#pragma unroll
        for (int gI = 0; gI < 5; gI++) {
            if (gI < ng) {
                uint32_t off = (uint32_t)(hbase + gI * 16 + ldsmRow) * (KSTRIDE * 4)
                             + ldsmCol + kk * 32;
                uint32_t bh0, bh1, bh2, bh3, bl0, bl1, bl2, bl3;
                LDSM_X4(bh0, bh1, bh2, bh3, knHiB + off);
                LDSM_X4(bl0, bl1, bl2, bl3, knLoB + off);
                MMA_TF32(acc[2 * gI],     ah[0], ah[1], ah[2], ah[3], bh0, bh1);
                MMA_TF32(acc[2 * gI],     ah[0], ah[1], ah[2], ah[3], bl0, bl1);
                MMA_TF32(acc[2 * gI],     al[0], al[1], al[2], al[3], bh0, bh1);
                MMA_TF32(acc[2 * gI + 1], ah[0], ah[1], ah[2], ah[3], bh2, bh3);
                MMA_TF32(acc[2 * gI + 1], ah[0], ah[1], ah[2], ah[3], bl2, bl3);
                MMA_TF32(acc[2 * gI + 1], al[0], al[1], al[2], al[3], bh2, bh3);
            }
        }
    }

    // ---------- bias + mask + exp (no-max: scores bounded), local sums ----
    float sm0 = 0.f, sm1 = 0.f;
    {
        const float* biasR0 = bias + (size_t)h * NTOK * NTOK + (size_t)(R0 + g) * NTOK + hbase + 2 * t;
        const float* biasR1 = biasR0 + 8 * NTOK;
        const float* maskR0 = mask + (size_t)w * NTOK * NTOK + (size_t)(R0 + g) * NTOK + hbase + 2 * t;
        const float* maskR1 = maskR0 + 8 * NTOK;
#pragma unroll
        for (int nt = 0; nt < 10; nt++) {
            if (nt < 2 * ng) {
                float2 bb0 = *(const float2*)(biasR0 + 8 * nt);
                float2 mm0 = *(const float2*)(maskR0 + 8 * nt);
                float2 bb1 = *(const float2*)(biasR1 + 8 * nt);
                float2 mm1 = *(const float2*)(maskR1 + 8 * nt);
                acc[nt][0] = __expf(acc[nt][0] + bb0.x + mm0.x);
                acc[nt][1] = __expf(acc[nt][1] + bb0.y + mm0.y);
                acc[nt][2] = __expf(acc[nt][2] + bb1.x + mm1.x);
                acc[nt][3] = __expf(acc[nt][3] + bb1.y + mm1.y);
                sm0 += acc[nt][0] + acc[nt][1];
                sm1 += acc[nt][2] + acc[nt][3];
            }
        }
        sm0 += __shfl_xor_sync(0xffffffffu, sm0, 1);
        sm0 += __shfl_xor_sync(0xffffffffu, sm0, 2);
        sm1 += __shfl_xor_sync(0xffffffffu, sm1, 1);
        sm1 += __shfl_xor_sync(0xffffffffu, sm1, 2);
        if (t == 0) {
            sumb[(pair * 2 + half) * 16 + g]     = sm0;
            sumb[(pair * 2 + half) * 16 + g + 8] = sm1;
        }
    }

    // ---------- PV (partial over owned cols), 3xTF32 ----------
    float pv[4][4];
#pragma unroll
    for (int nt = 0; nt < 4; nt++)
#pragma unroll
        for (int c = 0; c < 4; c++) pv[nt][c] = 0.f;

    const int src1 = (lane & 28) | (t >> 1);
    const int src2 = src1 + 2;
    const bool oddc = (t & 1);

#pragma unroll
    for (int kk2 = 0; kk2 < 10; kk2++) {
        if (kk2 < 2 * ng) {
            float s00 = __shfl_sync(0xffffffffu, acc[kk2][0], src1);
            float s01 = __shfl_sync(0xffffffffu, acc[kk2][1], src1);
            float s02 = __shfl_sync(0xffffffffu, acc[kk2][0], src2);
            float s03 = __shfl_sync(0xffffffffu, acc[kk2][1], src2);
            float s10 = __shfl_sync(0xffffffffu, acc[kk2][2], src1);
            float s11 = __shfl_sync(0xffffffffu, acc[kk2][3], src1);
            float s12 = __shfl_sync(0xffffffffu, acc[kk2][2], src2);
            float s13 = __shfl_sync(0xffffffffu, acc[kk2][3], src2);
            float a0 = oddc ? s01 : s00;
            float a1 = oddc ? s11 : s10;
            float a2 = oddc ? s03 : s02;
            float a3 = oddc ? s13 : s12;
            uint32_t ah[4], al[4];
            tf32_split(a0, ah[0], al[0]);
            tf32_split(a1, ah[1], al[1]);
            tf32_split(a2, ah[2], al[2]);
            tf32_split(a3, ah[3], al[3]);
            const int kkG = (hbase >> 3) + kk2;
#pragma unroll
            for (int p = 0; p < 2; p++) {
                uint32_t off = (uint32_t)(p * 16 + ldsmRow) * (VSTRIDE * 4)
                             + ldsmCol + (uint32_t)kkG * 32;
                uint32_t bh0, bh1, bh2, bh3, bl0, bl1, bl2, bl3;
                LDSM_X4(bh0, bh1, bh2, bh3, vtHiB + off);
                LDSM_X4(bl0, bl1, bl2, bl3, vtLoB + off);
                MMA_TF32(pv[2 * p],     ah[0], ah[1], ah[2], ah[3], bh0, bh1);
                MMA_TF32(pv[2 * p],     ah[0], ah[1], ah[2], ah[3], bl0, bl1);
                MMA_TF32(pv[2 * p],     al[0], al[1], al[2], al[3], bh0, bh1);
                MMA_TF32(pv[2 * p + 1], ah[0], ah[1], ah[2], ah[3], bh2, bh3);
                MMA_TF32(pv[2 * p + 1], ah[0], ah[1], ah[2], ah[3], bl2, bl3);
                MMA_TF32(pv[2 * p + 1], al[0], al[1], al[2], al[3], bh2, bh3);
            }
        }
    }

    // ---------- pairwise combine + epilogue ----------
    if (half == 1) {
        float* pb = pvb + (pair * 32 + lane) * PVSTR;
#pragma unroll
        for (int nt = 0; nt < 4; nt++) {
            *(float2*)(pb + nt * 4)     = make_float2(pv[nt][0], pv[nt][1]);
            *(float2*)(pb + nt * 4 + 2) = make_float2(pv[nt][2], pv[nt][3]);
        }
    }
    __syncthreads();
    if (half == 0) {
        const float inv0 = 1.f / (sm0 + sumb[(pair * 2 + 1) * 16 + g]);
        const float inv1 = 1.f / (sm1 + sumb[(pair * 2 + 1) * 16 + g + 8]);
        const float* pb = pvb + (pair * 32 + lane) * PVSTR;
        float* o0 = out + ((size_t)b * NTOK + R0 + g) * CDIM + h * DHEAD + 2 * t;
        float* o1 = o0 + (size_t)8 * CDIM;
#pragma unroll
        for (int nt = 0; nt < 4; nt++) {
            float2 q0 = *(const float2*)(pb + nt * 4);
            float2 q1 = *(const float2*)(pb + nt * 4 + 2);
            *(float2*)(o0 + 8 * nt) = make_float2((pv[nt][0] + q0.x) * inv0,
                                                  (pv[nt][1] + q0.y) * inv0);
            *(float2*)(o1 + 8 * nt) = make_float2((pv[nt][2] + q1.x) * inv1,
                                                  (pv[nt][3] + q1.y) * inv1);
        }
    }
}

// =========================================================================
// launch
// =========================================================================
extern "C" void kernel_launch(void* const* d_in, const int* in_sizes, int n_in,
                              void* d_out, int out_size)
{
    const float* x           = (const float*)d_in[0];
    const float* mask        = (const float*)d_in[1];
    const float* qkv_w       = (const float*)d_in[2];
    const float* logit_scale = (const float*)d_in[3];
    const float* cpb_w1      = (const float*)d_in[4];
    const float* cpb_b1      = (const float*)d_in[5];
    const float* cpb_w2      = (const float*)d_in[6];
    const float* proj_w      = (const float*)d_in[7];
    const float* proj_b      = (const float*)d_in[8];
    const float* rel_table   = (const float*)d_in[9];
    const int*   rel_index   = (const int*)d_in[10];
    float* out = (float*)d_out;

    float *qkv, *att, *tbl, *bias;
    cudaGetSymbolAddress((void**)&qkv,  g_qkv);
    cudaGetSymbolAddress((void**)&att,  g_att);
    cudaGetSymbolAddress((void**)&tbl,  g_tbl);
    cudaGetSymbolAddress((void**)&bias, g_bias);

    // 1) QKV projection (tf32 tensor cores)
    {
        dim3 grid(QKVC / 128, MROWS / 128);
        gemm_tf32_nt<false><<<grid, 256>>>(x, qkv_w, nullptr, qkv, MROWS, QKVC, CDIM);
    }

    // 2) relative position bias table + gather
    cpb_tbl_kernel<<<NPOS, CPBH>>>(rel_table, cpb_w1, cpb_b1, cpb_w2, tbl);
    {
        int tot = HEADS * NTOK * NTOK;
        bias_gather_kernel<<<(tot + 255) / 256, 256>>>(tbl, rel_index, bias);
    }

    // 3) tensor-core attention v2 (18 warps, dynamic smem)
    {
        cudaFuncSetAttribute(attn_tc2_kernel,
                             cudaFuncAttributeMaxDynamicSharedMemorySize,
                             ATTN_SMEM_BYTES);
        dim3 grid(HEADS, BWIN);
        attn_tc2_kernel<<<grid, 576, ATTN_SMEM_BYTES>>>(qkv, bias, mask, logit_scale, att);
    }

    // 4) output projection (tf32 tensor cores)
    {
        dim3 grid(CDIM / 128, MROWS / 128);
        gemm_tf32_nt<true><<<grid, 256>>>(att, proj_w, proj_b, out, MROWS, CDIM, CDIM);
    }
}

// round 6
// speedup vs baseline: 2.9958x; 1.0440x over previous
#include <cuda_runtime.h>
#include <cuda_bf16.h>
#include <math.h>
#include <stdint.h>

// ---------------- problem constants ----------------
#define BWIN   512
#define NTOK   144
#define CDIM   512
#define HEADS  16
#define DHEAD  32
#define NW     64
#define MROWS  (BWIN * NTOK)        // 73728
#define QKVC   (3 * CDIM)           // 1536
#define NPOS   (23 * 23)
#define CPBH   512

// ---------------- scratch ----------------
__device__ float g_qkv [(size_t)MROWS * QKVC];
__device__ float g_att [(size_t)MROWS * CDIM];
__device__ float g_tbl [NPOS * HEADS];
__device__ float g_bias[(size_t)HEADS * NTOK * NTOK];

__device__ __forceinline__ uint32_t s2u(const void* p) {
    return (uint32_t)__cvta_generic_to_shared(p);
}
__device__ __forceinline__ uint32_t cvt_tf32(float x) {
    uint32_t u; asm("cvt.rna.tf32.f32 %0, %1;" : "=r"(u) : "f"(x)); return u;
}
__device__ __forceinline__ void tf32_split(float x, uint32_t& hi, uint32_t& lo) {
    hi = cvt_tf32(x);
    lo = cvt_tf32(x - __uint_as_float(hi));
}

#define MMA_TF32(d, a0,a1,a2,a3, b0,b1)                                        \
    asm volatile("mma.sync.aligned.m16n8k8.row.col.f32.tf32.tf32.f32 "         \
                 "{%0,%1,%2,%3},{%4,%5,%6,%7},{%8,%9},{%0,%1,%2,%3};"          \
                 : "+f"(d[0]), "+f"(d[1]), "+f"(d[2]), "+f"(d[3])              \
                 : "r"(a0), "r"(a1), "r"(a2), "r"(a3), "r"(b0), "r"(b1))

#define LDSM_X4(r0,r1,r2,r3, addr)                                             \
    asm volatile("ldmatrix.sync.aligned.m8n8.x4.shared.b16 {%0,%1,%2,%3}, [%4];" \
                 : "=r"(r0), "=r"(r1), "=r"(r2), "=r"(r3) : "r"(addr))

// =========================================================================
// TF32 tensor-core GEMM v2 (NT): C[m][n] = sum_k A[m][k]*B[n][k] (+bias[n])
// CTA tile 128x256, BK=16, 8 warps with 64x64 warp tiles (2x less smem
// fragment re-read than 32x64). Double-buffered dynamic smem (61.4 KB).
// =========================================================================
#define GBK   16
#define GLD   20                       // words per smem row (16 + 4 pad)
#define ABUFW (128 * GLD)              // 2560 words per A buffer
#define BBUFW (256 * GLD)              // 5120 words per B buffer
#define GT_SMEM_BYTES ((2 * ABUFW + 2 * BBUFW) * 4)   // 61440

template <bool HAS_BIAS>
__global__ __launch_bounds__(256, 1)
void gemm_tf32_nt(const float* __restrict__ A,
                  const float* __restrict__ B,
                  const float* __restrict__ bias,
                  float* __restrict__ C,
                  int M, int N, int K)
{
    extern __shared__ __align__(16) uint32_t gsm[];
    uint32_t* As = gsm;                 // [2][ABUFW]
    uint32_t* Bs = gsm + 2 * ABUFW;     // [2][BBUFW]

    const int tid  = threadIdx.x;
    const int lane = tid & 31;
    const int warp = tid >> 5;
    const int warpM = (warp & 1) * 64;      // 2 M tiles of 64
    const int warpN = (warp >> 1) * 64;     // 4 N tiles of 64
    const int rowBase = blockIdx.y * 128;
    const int colBase = blockIdx.x * 256;

    // global staging: r = tid>>2 in 0..63, kq = float4 slot in 16-wide slab
    const int r  = tid >> 2;
    const int kq = tid & 3;
    const float* Ag = A + (size_t)(rowBase + r) * K + kq * 4;
    const float* Bg = B + (size_t)(colBase + r) * K + kq * 4;

    float4 ra0, ra1, rb0, rb1, rb2, rb3;

    float acc[4][8][4];
#pragma unroll
    for (int mi = 0; mi < 4; mi++)
#pragma unroll
        for (int ni = 0; ni < 8; ni++)
#pragma unroll
            for (int c = 0; c < 4; c++) acc[mi][ni][c] = 0.f;

    // ldmatrix per-lane byte offsets (proven layout from R2)
    const uint32_t aOff = (uint32_t)((warpM + (lane & 7) + ((lane >> 3) & 1) * 8) * GLD) * 4
                        + (uint32_t)(lane >> 4) * 16;
    const uint32_t bOff = (uint32_t)((warpN + (lane & 7) + ((lane & 16) ? 8 : 0)) * GLD) * 4
                        + (uint32_t)((lane >> 3) & 1) * 16;
    const uint32_t asBase = s2u(As);
    const uint32_t bsBase = s2u(Bs);

#define G_LOAD(it)  {                                            \
        const float* ap = Ag + (it) * GBK;                       \
        const float* bp = Bg + (it) * GBK;                       \
        ra0 = *(const float4*)(ap);                              \
        ra1 = *(const float4*)(ap + (size_t)64 * K);             \
        rb0 = *(const float4*)(bp);                              \
        rb1 = *(const float4*)(bp + (size_t)64 * K);             \
        rb2 = *(const float4*)(bp + (size_t)128 * K);            \
        rb3 = *(const float4*)(bp + (size_t)192 * K);            \
    }
#define CVT4(u, v) { u.x=cvt_tf32(v.x); u.y=cvt_tf32(v.y); u.z=cvt_tf32(v.z); u.w=cvt_tf32(v.w); }
#define G_STS(buf)  {                                                   \
        uint4 u;                                                        \
        CVT4(u, ra0); *(uint4*)&As[(buf)*ABUFW + r*GLD + kq*4] = u;     \
        CVT4(u, ra1); *(uint4*)&As[(buf)*ABUFW + (r+64)*GLD + kq*4] = u;\
        CVT4(u, rb0); *(uint4*)&Bs[(buf)*BBUFW + r*GLD + kq*4] = u;     \
        CVT4(u, rb1); *(uint4*)&Bs[(buf)*BBUFW + (r+64)*GLD + kq*4] = u;\
        CVT4(u, rb2); *(uint4*)&Bs[(buf)*BBUFW + (r+128)*GLD + kq*4] = u;\
        CVT4(u, rb3); *(uint4*)&Bs[(buf)*BBUFW + (r+192)*GLD + kq*4] = u;\
    }

    G_LOAD(0); G_STS(0); __syncthreads();

    const int NIT = K / GBK;
    for (int it = 0; it < NIT; ++it) {
        const int buf = it & 1;
        if (it + 1 < NIT) G_LOAD(it + 1);

        const uint32_t aB = asBase + (uint32_t)buf * (ABUFW * 4);
        const uint32_t bB = bsBase + (uint32_t)buf * (BBUFW * 4);

#pragma unroll
        for (int kk = 0; kk < 2; kk++) {
            uint32_t a[4][4], bf[8][2];
#pragma unroll
            for (int mi = 0; mi < 4; mi++) {
                uint32_t addr = aB + aOff + (uint32_t)(mi * 16 * GLD * 4) + (uint32_t)(kk * 32);
                LDSM_X4(a[mi][0], a[mi][1], a[mi][2], a[mi][3], addr);
            }
#pragma unroll
            for (int p = 0; p < 4; p++) {
                uint32_t addr = bB + bOff + (uint32_t)(p * 16 * GLD * 4) + (uint32_t)(kk * 32);
                uint32_t r0, r1, r2, r3;
                LDSM_X4(r0, r1, r2, r3, addr);
                bf[2 * p][0] = r0; bf[2 * p][1] = r1;
                bf[2 * p + 1][0] = r2; bf[2 * p + 1][1] = r3;
            }
#pragma unroll
            for (int mi = 0; mi < 4; mi++)
#pragma unroll
                for (int ni = 0; ni < 8; ni++)
                    MMA_TF32(acc[mi][ni], a[mi][0], a[mi][1], a[mi][2], a[mi][3],
                             bf[ni][0], bf[ni][1]);
        }
        if (it + 1 < NIT) G_STS(buf ^ 1);
        __syncthreads();
    }

    // epilogue
    const int g  = lane >> 2;
    const int cq = (lane & 3) * 2;
#pragma unroll
    for (int mi = 0; mi < 4; mi++) {
        const int row0 = rowBase + warpM + mi * 16 + g;
#pragma unroll
        for (int ni = 0; ni < 8; ni++) {
            const int col = colBase + warpN + ni * 8 + cq;
            float b0 = 0.f, b1 = 0.f;
            if (HAS_BIAS) { b0 = bias[col]; b1 = bias[col + 1]; }
            *(float2*)&C[(size_t)row0 * N + col] =
                make_float2(acc[mi][ni][0] + b0, acc[mi][ni][1] + b1);
            *(float2*)&C[(size_t)(row0 + 8) * N + col] =
                make_float2(acc[mi][ni][2] + b0, acc[mi][ni][3] + b1);
        }
    }
#undef G_LOAD
#undef G_STS
#undef CVT4
}

// =========================================================================
// CPB MLP table + bias gather (tiny, unchanged)
// =========================================================================
__global__ __launch_bounds__(512)
void cpb_tbl_kernel(const float* __restrict__ rel_table,
                    const float* __restrict__ w1,
                    const float* __restrict__ b1,
                    const float* __restrict__ w2,
                    float* __restrict__ tbl)
{
    __shared__ float hid[CPBH];
    int p = blockIdx.x;
    float t0 = rel_table[2 * p], t1 = rel_table[2 * p + 1];
    int j = threadIdx.x;
    hid[j] = fmaxf(t0 * w1[2 * j] + t1 * w1[2 * j + 1] + b1[j], 0.f);
    __syncthreads();

    int warp = j >> 5, lane = j & 31;
    const float* w2h = w2 + warp * CPBH;
    float s = 0.f;
#pragma unroll
    for (int q = lane; q < CPBH; q += 32) s += hid[q] * w2h[q];
#pragma unroll
    for (int o = 16; o > 0; o >>= 1) s += __shfl_xor_sync(0xffffffffu, s, o);
    if (lane == 0) tbl[p * HEADS + warp] = s;
}

__global__ void bias_gather_kernel(const float* __restrict__ tbl,
                                   const int* __restrict__ rel_index,
                                   float* __restrict__ bias)
{
    int t = blockIdx.x * blockDim.x + threadIdx.x;
    const int TOT = HEADS * NTOK * NTOK;
    if (t >= TOT) return;
    int h  = t / (NTOK * NTOK);
    int ij = t % (NTOK * NTOK);
    float x = tbl[rel_index[ij] * HEADS + h];
    bias[(size_t)h * NTOK * NTOK + ij] = 16.f / (1.f + __expf(-x));
}

// =========================================================================
// Tensor-core window attention v2 (3xTF32), 18 warps / CTA — unchanged R4
// =========================================================================
#define KSTRIDE 36
#define VSTRIDE 148
#define PVSTR   18

#define KHI_OFF 0
#define KLO_OFF (NTOK * KSTRIDE)
#define VHI_OFF (2 * NTOK * KSTRIDE)
#define VLO_OFF (VHI_OFF + DHEAD * VSTRIDE)
#define PVB_OFF (VLO_OFF + DHEAD * VSTRIDE)
#define SUM_OFF (PVB_OFF + 9 * 32 * PVSTR)
#define ATTN_SMEM_BYTES ((SUM_OFF + 9 * 2 * 16) * 4)

__global__ __launch_bounds__(576, 1)
void attn_tc2_kernel(const float* __restrict__ qkv,
                     const float* __restrict__ bias,
                     const float* __restrict__ mask,
                     const float* __restrict__ logit_scale,
                     float* __restrict__ out)
{
    extern __shared__ __align__(16) uint32_t dsm_a[];

    const int h = blockIdx.x;
    const int b = blockIdx.y;
    const int w = b & (NW - 1);

    const int tid  = threadIdx.x;
    const int lane = tid & 31;
    const int warp = tid >> 5;
    const int pair = warp % 9;
    const int half = warp / 9;
    const int ng   = half ? 5 : 4;
    const int hbase = half ? 64 : 0;
    const int g  = lane >> 2;
    const int t  = lane & 3;
    const int R0 = pair * 16;

    const float scale = __expf(fminf(logit_scale[h], 4.60517018598809f));
    const float* base = qkv + (size_t)b * NTOK * QKVC + h * DHEAD;

    uint32_t* knHi = dsm_a + KHI_OFF;
    uint32_t* knLo = dsm_a + KLO_OFF;
    uint32_t* vtHi = dsm_a + VHI_OFF;
    uint32_t* vtLo = dsm_a + VLO_OFF;
    float*    pvb  = (float*)(dsm_a + PVB_OFF);
    float*    sumb = (float*)(dsm_a + SUM_OFF);
    const uint32_t knHiB = s2u(knHi);
    const uint32_t knLoB = s2u(knLo);
    const uint32_t vtHiB = s2u(vtHi);
    const uint32_t vtLoB = s2u(vtLo);

#pragma unroll
    for (int i = 0; i < 8; i++) {
        int j = warp * 8 + i;
        float kv = base[(size_t)j * QKVC + CDIM + lane];
        float s = kv * kv;
#pragma unroll
        for (int o = 16; o > 0; o >>= 1) s += __shfl_xor_sync(0xffffffffu, s, o);
        kv *= rsqrtf(s);
        uint32_t khi, klo; tf32_split(kv, khi, klo);
        knHi[j * KSTRIDE + lane] = khi;
        knLo[j * KSTRIDE + lane] = klo;

        float vv = base[(size_t)j * QKVC + 2 * CDIM + lane];
        uint32_t vhi, vlo; tf32_split(vv, vhi, vlo);
        vtHi[lane * VSTRIDE + j] = vhi;
        vtLo[lane * VSTRIDE + j] = vlo;
    }

    float qf[4][4];
    {
        const float* q0 = base + (size_t)(R0 + g) * QKVC;
        const float* q1 = base + (size_t)(R0 + g + 8) * QKVC;
#pragma unroll
        for (int kk = 0; kk < 4; kk++) {
            qf[kk][0] = q0[8 * kk + t];
            qf[kk][1] = q1[8 * kk + t];
            qf[kk][2] = q0[8 * kk + t + 4];
            qf[kk][3] = q1[8 * kk + t + 4];
        }
        float s0 = 0.f, s1 = 0.f;
#pragma unroll
        for (int kk = 0; kk < 4; kk++) {
            s0 += qf[kk][0] * qf[kk][0] + qf[kk][2] * qf[kk][2];
            s1 += qf[kk][1] * qf[kk][1] + qf[kk][3] * qf[kk][3];
        }
        s0 += __shfl_xor_sync(0xffffffffu, s0, 1);
        s0 += __shfl_xor_sync(0xffffffffu, s0, 2);
        s1 += __shfl_xor_sync(0xffffffffu, s1, 1);
        s1 += __shfl_xor_sync(0xffffffffu, s1, 2);
        float r0 = rsqrtf(s0) * scale, r1 = rsqrtf(s1) * scale;
#pragma unroll
        for (int kk = 0; kk < 4; kk++) {
            qf[kk][0] *= r0; qf[kk][2] *= r0;
            qf[kk][1] *= r1; qf[kk][3] *= r1;
        }
    }
    __syncthreads();

    float acc[10][4];
#pragma unroll
    for (int nt = 0; nt < 10; nt++)
#pragma unroll
        for (int c = 0; c < 4; c++) acc[nt][c] = 0.f;

    const uint32_t ldsmRow = (uint32_t)((lane & 7) + ((lane & 16) ? 8 : 0));
    const uint32_t ldsmCol = (uint32_t)((lane >> 3) & 1) * 16;

#pragma unroll
    for (int kk = 0; kk < 4; kk++) {
        uint32_t ah[4], al[4];
#pragma unroll
        for (int i = 0; i < 4; i++) tf32_split(qf[kk][i], ah[i], al[i]);
#pragma unroll
        for (int gI = 0; gI < 5; gI++) {
            if (gI < ng) {
                uint32_t off = (uint32_t)(hbase + gI * 16 + ldsmRow) * (KSTRIDE * 4)
                             + ldsmCol + kk * 32;
                uint32_t bh0, bh1, bh2, bh3, bl0, bl1, bl2, bl3;
                LDSM_X4(bh0, bh1, bh2, bh3, knHiB + off);
                LDSM_X4(bl0, bl1, bl2, bl3, knLoB + off);
                MMA_TF32(acc[2 * gI],     ah[0], ah[1], ah[2], ah[3], bh0, bh1);
                MMA_TF32(acc[2 * gI],     ah[0], ah[1], ah[2], ah[3], bl0, bl1);
                MMA_TF32(acc[2 * gI],     al[0], al[1], al[2], al[3], bh0, bh1);
                MMA_TF32(acc[2 * gI + 1], ah[0], ah[1], ah[2], ah[3], bh2, bh3);
                MMA_TF32(acc[2 * gI + 1], ah[0], ah[1], ah[2], ah[3], bl2, bl3);
                MMA_TF32(acc[2 * gI + 1], al[0], al[1], al[2], al[3], bh2, bh3);
            }
        }
    }

    float sm0 = 0.f, sm1 = 0.f;
    {
        const float* biasR0 = bias + (size_t)h * NTOK * NTOK + (size_t)(R0 + g) * NTOK + hbase + 2 * t;
        const float* biasR1 = biasR0 + 8 * NTOK;
        const float* maskR0 = mask + (size_t)w * NTOK * NTOK + (size_t)(R0 + g) * NTOK + hbase + 2 * t;
        const float* maskR1 = maskR0 + 8 * NTOK;
#pragma unroll
        for (int nt = 0; nt < 10; nt++) {
            if (nt < 2 * ng) {
                float2 bb0 = *(const float2*)(biasR0 + 8 * nt);
                float2 mm0 = *(const float2*)(maskR0 + 8 * nt);
                float2 bb1 = *(const float2*)(biasR1 + 8 * nt);
                float2 mm1 = *(const float2*)(maskR1 + 8 * nt);
                acc[nt][0] = __expf(acc[nt][0] + bb0.x + mm0.x);
                acc[nt][1] = __expf(acc[nt][1] + bb0.y + mm0.y);
                acc[nt][2] = __expf(acc[nt][2] + bb1.x + mm1.x);
                acc[nt][3] = __expf(acc[nt][3] + bb1.y + mm1.y);
                sm0 += acc[nt][0] + acc[nt][1];
                sm1 += acc[nt][2] + acc[nt][3];
            }
        }
        sm0 += __shfl_xor_sync(0xffffffffu, sm0, 1);
        sm0 += __shfl_xor_sync(0xffffffffu, sm0, 2);
        sm1 += __shfl_xor_sync(0xffffffffu, sm1, 1);
        sm1 += __shfl_xor_sync(0xffffffffu, sm1, 2);
        if (t == 0) {
            sumb[(pair * 2 + half) * 16 + g]     = sm0;
            sumb[(pair * 2 + half) * 16 + g + 8] = sm1;
        }
    }

    float pv[4][4];
#pragma unroll
    for (int nt = 0; nt < 4; nt++)
#pragma unroll
        for (int c = 0; c < 4; c++) pv[nt][c] = 0.f;

    const int src1 = (lane & 28) | (t >> 1);
    const int src2 = src1 + 2;
    const bool oddc = (t & 1);

#pragma unroll
    for (int kk2 = 0; kk2 < 10; kk2++) {
        if (kk2 < 2 * ng) {
            float s00 = __shfl_sync(0xffffffffu, acc[kk2][0], src1);
            float s01 = __shfl_sync(0xffffffffu, acc[kk2][1], src1);
            float s02 = __shfl_sync(0xffffffffu, acc[kk2][0], src2);
            float s03 = __shfl_sync(0xffffffffu, acc[kk2][1], src2);
            float s10 = __shfl_sync(0xffffffffu, acc[kk2][2], src1);
            float s11 = __shfl_sync(0xffffffffu, acc[kk2][3], src1);
            float s12 = __shfl_sync(0xffffffffu, acc[kk2][2], src2);
            float s13 = __shfl_sync(0xffffffffu, acc[kk2][3], src2);
            float a0 = oddc ? s01 : s00;
            float a1 = oddc ? s11 : s10;
            float a2 = oddc ? s03 : s02;
            float a3 = oddc ? s13 : s12;
            uint32_t ah[4], al[4];
            tf32_split(a0, ah[0], al[0]);
            tf32_split(a1, ah[1], al[1]);
            tf32_split(a2, ah[2], al[2]);
            tf32_split(a3, ah[3], al[3]);
            const int kkG = (hbase >> 3) + kk2;
#pragma unroll
            for (int p = 0; p < 2; p++) {
                uint32_t off = (uint32_t)(p * 16 + ldsmRow) * (VSTRIDE * 4)
                             + ldsmCol + (uint32_t)kkG * 32;
                uint32_t bh0, bh1, bh2, bh3, bl0, bl1, bl2, bl3;
                LDSM_X4(bh0, bh1, bh2, bh3, vtHiB + off);
                LDSM_X4(bl0, bl1, bl2, bl3, vtLoB + off);
                MMA_TF32(pv[2 * p],     ah[0], ah[1], ah[2], ah[3], bh0, bh1);
                MMA_TF32(pv[2 * p],     ah[0], ah[1], ah[2], ah[3], bl0, bl1);
                MMA_TF32(pv[2 * p],     al[0], al[1], al[2], al[3], bh0, bh1);
                MMA_TF32(pv[2 * p + 1], ah[0], ah[1], ah[2], ah[3], bh2, bh3);
                MMA_TF32(pv[2 * p + 1], ah[0], ah[1], ah[2], ah[3], bl2, bl3);
                MMA_TF32(pv[2 * p + 1], al[0], al[1], al[2], al[3], bh2, bh3);
            }
        }
    }

    if (half == 1) {
        float* pb = pvb + (pair * 32 + lane) * PVSTR;
#pragma unroll
        for (int nt = 0; nt < 4; nt++) {
            *(float2*)(pb + nt * 4)     = make_float2(pv[nt][0], pv[nt][1]);
            *(float2*)(pb + nt * 4 + 2) = make_float2(pv[nt][2], pv[nt][3]);
        }
    }
    __syncthreads();
    if (half == 0) {
        const float inv0 = 1.f / (sm0 + sumb[(pair * 2 + 1) * 16 + g]);
        const float inv1 = 1.f / (sm1 + sumb[(pair * 2 + 1) * 16 + g + 8]);
        const float* pb = pvb + (pair * 32 + lane) * PVSTR;
        float* o0 = out + ((size_t)b * NTOK + R0 + g) * CDIM + h * DHEAD + 2 * t;
        float* o1 = o0 + (size_t)8 * CDIM;
#pragma unroll
        for (int nt = 0; nt < 4; nt++) {
            float2 q0 = *(const float2*)(pb + nt * 4);
            float2 q1 = *(const float2*)(pb + nt * 4 + 2);
            *(float2*)(o0 + 8 * nt) = make_float2((pv[nt][0] + q0.x) * inv0,
                                                  (pv[nt][1] + q0.y) * inv0);
            *(float2*)(o1 + 8 * nt) = make_float2((pv[nt][2] + q1.x) * inv1,
                                                  (pv[nt][3] + q1.y) * inv1);
        }
    }
}

// =========================================================================
// launch
// =========================================================================
extern "C" void kernel_launch(void* const* d_in, const int* in_sizes, int n_in,
                              void* d_out, int out_size)
{
    const float* x           = (const float*)d_in[0];
    const float* mask        = (const float*)d_in[1];
    const float* qkv_w       = (const float*)d_in[2];
    const float* logit_scale = (const float*)d_in[3];
    const float* cpb_w1      = (const float*)d_in[4];
    const float* cpb_b1      = (const float*)d_in[5];
    const float* cpb_w2      = (const float*)d_in[6];
    const float* proj_w      = (const float*)d_in[7];
    const float* proj_b      = (const float*)d_in[8];
    const float* rel_table   = (const float*)d_in[9];
    const int*   rel_index   = (const int*)d_in[10];
    float* out = (float*)d_out;

    float *qkv, *att, *tbl, *bias;
    cudaGetSymbolAddress((void**)&qkv,  g_qkv);
    cudaGetSymbolAddress((void**)&att,  g_att);
    cudaGetSymbolAddress((void**)&tbl,  g_tbl);
    cudaGetSymbolAddress((void**)&bias, g_bias);

    cudaFuncSetAttribute(gemm_tf32_nt<false>,
                         cudaFuncAttributeMaxDynamicSharedMemorySize, GT_SMEM_BYTES);
    cudaFuncSetAttribute(gemm_tf32_nt<true>,
                         cudaFuncAttributeMaxDynamicSharedMemorySize, GT_SMEM_BYTES);
    cudaFuncSetAttribute(attn_tc2_kernel,
                         cudaFuncAttributeMaxDynamicSharedMemorySize, ATTN_SMEM_BYTES);

    // 1) QKV projection: 73728 x 1536 x 512  (CTA tile 128x256)
    {
        dim3 grid(QKVC / 256, MROWS / 128);
        gemm_tf32_nt<false><<<grid, 256, GT_SMEM_BYTES>>>(x, qkv_w, nullptr, qkv,
                                                          MROWS, QKVC, CDIM);
    }

    // 2) relative position bias table + gather
    cpb_tbl_kernel<<<NPOS, CPBH>>>(rel_table, cpb_w1, cpb_b1, cpb_w2, tbl);
    {
        int tot = HEADS * NTOK * NTOK;
        bias_gather_kernel<<<(tot + 255) / 256, 256>>>(tbl, rel_index, bias);
    }

    // 3) tensor-core attention v2 (unchanged R4)
    {
        dim3 grid(HEADS, BWIN);
        attn_tc2_kernel<<<grid, 576, ATTN_SMEM_BYTES>>>(qkv, bias, mask, logit_scale, att);
    }

    // 4) output projection: 73728 x 512 x 512
    {
        dim3 grid(CDIM / 256, MROWS / 128);
        gemm_tf32_nt<true><<<grid, 256, GT_SMEM_BYTES>>>(att, proj_w, proj_b, out,
                                                         MROWS, CDIM, CDIM);
    }
}

// round 7
// speedup vs baseline: 3.9313x; 1.3123x over previous
#include <cuda_runtime.h>
#include <cuda_bf16.h>
#include <cuda_fp16.h>
#include <math.h>
#include <stdint.h>

// ---------------- problem constants ----------------
#define BWIN   512
#define NTOK   144
#define CDIM   512
#define HEADS  16
#define DHEAD  32
#define NW     64
#define MROWS  (BWIN * NTOK)        // 73728
#define QKVC   (3 * CDIM)           // 1536
#define NPOS   (23 * 23)
#define CPBH   512

// ---------------- scratch ----------------
__device__ float g_qkv [(size_t)MROWS * QKVC];
__device__ float g_att [(size_t)MROWS * CDIM];
__device__ float g_tbl [NPOS * HEADS];
__device__ float g_bias[(size_t)HEADS * NTOK * NTOK];

__device__ __forceinline__ uint32_t s2u(const void* p) {
    return (uint32_t)__cvta_generic_to_shared(p);
}
__device__ __forceinline__ uint32_t cvt_tf32(float x) {
    uint32_t u; asm("cvt.rna.tf32.f32 %0, %1;" : "=r"(u) : "f"(x)); return u;
}
__device__ __forceinline__ void tf32_split(float x, uint32_t& hi, uint32_t& lo) {
    hi = cvt_tf32(x);
    lo = cvt_tf32(x - __uint_as_float(hi));
}
__device__ __forceinline__ uint2 f4_to_h4(float4 v) {
    __half2 h0 = __float22half2_rn(make_float2(v.x, v.y));
    __half2 h1 = __float22half2_rn(make_float2(v.z, v.w));
    uint2 u;
    u.x = *(uint32_t*)&h0;
    u.y = *(uint32_t*)&h1;
    return u;
}

#define MMA_TF32(d, a0,a1,a2,a3, b0,b1)                                        \
    asm volatile("mma.sync.aligned.m16n8k8.row.col.f32.tf32.tf32.f32 "         \
                 "{%0,%1,%2,%3},{%4,%5,%6,%7},{%8,%9},{%0,%1,%2,%3};"          \
                 : "+f"(d[0]), "+f"(d[1]), "+f"(d[2]), "+f"(d[3])              \
                 : "r"(a0), "r"(a1), "r"(a2), "r"(a3), "r"(b0), "r"(b1))

#define MMA_F16(d, a0,a1,a2,a3, b0,b1)                                         \
    asm volatile("mma.sync.aligned.m16n8k16.row.col.f32.f16.f16.f32 "          \
                 "{%0,%1,%2,%3},{%4,%5,%6,%7},{%8,%9},{%0,%1,%2,%3};"          \
                 : "+f"(d[0]), "+f"(d[1]), "+f"(d[2]), "+f"(d[3])              \
                 : "r"(a0), "r"(a1), "r"(a2), "r"(a3), "r"(b0), "r"(b1))

#define LDSM_X4(r0,r1,r2,r3, addr)                                             \
    asm volatile("ldmatrix.sync.aligned.m8n8.x4.shared.b16 {%0,%1,%2,%3}, [%4];" \
                 : "=r"(r0), "=r"(r1), "=r"(r2), "=r"(r3) : "r"(addr))

// =========================================================================
// FP16 tensor-core GEMM (NT): C[m][n] = sum_k A[m][k]*B[n][k] (+bias[n])
// CTA tile 128x256, BK=32 halves (64B/row + 16B pad = 80B stride — same
// byte geometry as the proven tf32 kernel), 8 warps, 64x64 warp tiles,
// mma.m16n8k16.f16 (2x MACs/instr vs tf32), fp32 accumulate.
// =========================================================================
#define GBK    32                      // K elements per slab
#define GLDH   40                      // halves per smem row (32 + 8 pad)
#define ABUFH  (128 * GLDH)            // halves per A buffer
#define BBUFH  (256 * GLDH)            // halves per B buffer
#define GT_SMEM_BYTES ((2 * ABUFH + 2 * BBUFH) * 2)   // 61440

template <bool HAS_BIAS>
__global__ __launch_bounds__(256, 1)
void gemm_f16_nt(const float* __restrict__ A,
                 const float* __restrict__ B,
                 const float* __restrict__ bias,
                 float* __restrict__ C,
                 int M, int N, int K)
{
    extern __shared__ __align__(16) __half gsm[];
    __half* As = gsm;                   // [2][ABUFH]
    __half* Bs = gsm + 2 * ABUFH;       // [2][BBUFH]

    const int tid  = threadIdx.x;
    const int lane = tid & 31;
    const int warp = tid >> 5;
    const int warpM = (warp & 1) * 64;
    const int warpN = (warp >> 1) * 64;
    const int rowBase = blockIdx.y * 128;
    const int colBase = blockIdx.x * 256;

    // global staging: r = tid>>3 (0..31), kq = float4 slot (0..7) in 32-wide slab
    const int r  = tid >> 3;
    const int kq = tid & 7;
    const float* Ag = A + (size_t)(rowBase + r) * K + kq * 4;
    const float* Bg = B + (size_t)(colBase + r) * K + kq * 4;

    float4 ra[4], rb[8];

    float acc[4][8][4];
#pragma unroll
    for (int mi = 0; mi < 4; mi++)
#pragma unroll
        for (int ni = 0; ni < 8; ni++)
#pragma unroll
            for (int c = 0; c < 4; c++) acc[mi][ni][c] = 0.f;

    // ldmatrix per-lane byte offsets (identical formulas to proven tf32 code:
    // row stride 80B, 16B column chunks)
    const uint32_t aOff = (uint32_t)((warpM + (lane & 7) + ((lane >> 3) & 1) * 8) * (GLDH * 2))
                        + (uint32_t)(lane >> 4) * 16;
    const uint32_t bOff = (uint32_t)((warpN + (lane & 7) + ((lane & 16) ? 8 : 0)) * (GLDH * 2))
                        + (uint32_t)((lane >> 3) & 1) * 16;
    const uint32_t asBase = s2u(As);
    const uint32_t bsBase = s2u(Bs);

#define G_LOAD(it)  {                                                \
        const float* ap = Ag + (it) * GBK;                           \
        const float* bp = Bg + (it) * GBK;                           \
        ra[0] = *(const float4*)(ap);                                \
        ra[1] = *(const float4*)(ap + (size_t)32 * K);               \
        ra[2] = *(const float4*)(ap + (size_t)64 * K);               \
        ra[3] = *(const float4*)(ap + (size_t)96 * K);               \
        rb[0] = *(const float4*)(bp);                                \
        rb[1] = *(const float4*)(bp + (size_t)32 * K);               \
        rb[2] = *(const float4*)(bp + (size_t)64 * K);               \
        rb[3] = *(const float4*)(bp + (size_t)96 * K);               \
        rb[4] = *(const float4*)(bp + (size_t)128 * K);              \
        rb[5] = *(const float4*)(bp + (size_t)160 * K);              \
        rb[6] = *(const float4*)(bp + (size_t)192 * K);              \
        rb[7] = *(const float4*)(bp + (size_t)224 * K);              \
    }
#define G_STS(buf)  {                                                           \
        _Pragma("unroll")                                                       \
        for (int i = 0; i < 4; i++)                                             \
            *(uint2*)&As[(buf) * ABUFH + (r + 32 * i) * GLDH + kq * 4] = f4_to_h4(ra[i]); \
        _Pragma("unroll")                                                       \
        for (int i = 0; i < 8; i++)                                             \
            *(uint2*)&Bs[(buf) * BBUFH + (r + 32 * i) * GLDH + kq * 4] = f4_to_h4(rb[i]); \
    }

    G_LOAD(0); G_STS(0); __syncthreads();

    const int NIT = K / GBK;
    for (int it = 0; it < NIT; ++it) {
        const int buf = it & 1;
        if (it + 1 < NIT) G_LOAD(it + 1);

        const uint32_t aB = asBase + (uint32_t)buf * (ABUFH * 2);
        const uint32_t bB = bsBase + (uint32_t)buf * (BBUFH * 2);

#pragma unroll
        for (int kk = 0; kk < 2; kk++) {               // two K=16 steps (32B apart)
            uint32_t a[4][4], bf[8][2];
#pragma unroll
            for (int mi = 0; mi < 4; mi++) {
                uint32_t addr = aB + aOff + (uint32_t)(mi * 16 * GLDH * 2) + (uint32_t)(kk * 32);
                LDSM_X4(a[mi][0], a[mi][1], a[mi][2], a[mi][3], addr);
            }
#pragma unroll
            for (int p = 0; p < 4; p++) {
                uint32_t addr = bB + bOff + (uint32_t)(p * 16 * GLDH * 2) + (uint32_t)(kk * 32);
                uint32_t r0, r1, r2, r3;
                LDSM_X4(r0, r1, r2, r3, addr);
                bf[2 * p][0] = r0; bf[2 * p][1] = r1;
                bf[2 * p + 1][0] = r2; bf[2 * p + 1][1] = r3;
            }
#pragma unroll
            for (int mi = 0; mi < 4; mi++)
#pragma unroll
                for (int ni = 0; ni < 8; ni++)
                    MMA_F16(acc[mi][ni], a[mi][0], a[mi][1], a[mi][2], a[mi][3],
                            bf[ni][0], bf[ni][1]);
        }
        if (it + 1 < NIT) G_STS(buf ^ 1);
        __syncthreads();
    }

    // epilogue (fragment layout unchanged)
    const int g  = lane >> 2;
    const int cq = (lane & 3) * 2;
#pragma unroll
    for (int mi = 0; mi < 4; mi++) {
        const int row0 = rowBase + warpM + mi * 16 + g;
#pragma unroll
        for (int ni = 0; ni < 8; ni++) {
            const int col = colBase + warpN + ni * 8 + cq;
            float b0 = 0.f, b1 = 0.f;
            if (HAS_BIAS) { b0 = bias[col]; b1 = bias[col + 1]; }
            *(float2*)&C[(size_t)row0 * N + col] =
                make_float2(acc[mi][ni][0] + b0, acc[mi][ni][1] + b1);
            *(float2*)&C[(size_t)(row0 + 8) * N + col] =
                make_float2(acc[mi][ni][2] + b0, acc[mi][ni][3] + b1);
        }
    }
#undef G_LOAD
#undef G_STS
}

// =========================================================================
// CPB MLP table + bias gather (tiny, unchanged)
// =========================================================================
__global__ __launch_bounds__(512)
void cpb_tbl_kernel(const float* __restrict__ rel_table,
                    const float* __restrict__ w1,
                    const float* __restrict__ b1,
                    const float* __restrict__ w2,
                    float* __restrict__ tbl)
{
    __shared__ float hid[CPBH];
    int p = blockIdx.x;
    float t0 = rel_table[2 * p], t1 = rel_table[2 * p + 1];
    int j = threadIdx.x;
    hid[j] = fmaxf(t0 * w1[2 * j] + t1 * w1[2 * j + 1] + b1[j], 0.f);
    __syncthreads();

    int warp = j >> 5, lane = j & 31;
    const float* w2h = w2 + warp * CPBH;
    float s = 0.f;
#pragma unroll
    for (int q = lane; q < CPBH; q += 32) s += hid[q] * w2h[q];
#pragma unroll
    for (int o = 16; o > 0; o >>= 1) s += __shfl_xor_sync(0xffffffffu, s, o);
    if (lane == 0) tbl[p * HEADS + warp] = s;
}

__global__ void bias_gather_kernel(const float* __restrict__ tbl,
                                   const int* __restrict__ rel_index,
                                   float* __restrict__ bias)
{
    int t = blockIdx.x * blockDim.x + threadIdx.x;
    const int TOT = HEADS * NTOK * NTOK;
    if (t >= TOT) return;
    int h  = t / (NTOK * NTOK);
    int ij = t % (NTOK * NTOK);
    float x = tbl[rel_index[ij] * HEADS + h];
    bias[(size_t)h * NTOK * NTOK + ij] = 16.f / (1.f + __expf(-x));
}

// =========================================================================
// Tensor-core window attention v2 (3xTF32), 18 warps / CTA — unchanged
// =========================================================================
#define KSTRIDE 36
#define VSTRIDE 148
#define PVSTR   18

#define KHI_OFF 0
#define KLO_OFF (NTOK * KSTRIDE)
#define VHI_OFF (2 * NTOK * KSTRIDE)
#define VLO_OFF (VHI_OFF + DHEAD * VSTRIDE)
#define PVB_OFF (VLO_OFF + DHEAD * VSTRIDE)
#define SUM_OFF (PVB_OFF + 9 * 32 * PVSTR)
#define ATTN_SMEM_BYTES ((SUM_OFF + 9 * 2 * 16) * 4)

__global__ __launch_bounds__(576, 1)
void attn_tc2_kernel(const float* __restrict__ qkv,
                     const float* __restrict__ bias,
                     const float* __restrict__ mask,
                     const float* __restrict__ logit_scale,
                     float* __restrict__ out)
{
    extern __shared__ __align__(16) uint32_t dsm_a[];

    const int h = blockIdx.x;
    const int b = blockIdx.y;
    const int w = b & (NW - 1);

    const int tid  = threadIdx.x;
    const int lane = tid & 31;
    const int warp = tid >> 5;
    const int pair = warp % 9;
    const int half = warp / 9;
    const int ng   = half ? 5 : 4;
    const int hbase = half ? 64 : 0;
    const int g  = lane >> 2;
    const int t  = lane & 3;
    const int R0 = pair * 16;

    const float scale = __expf(fminf(logit_scale[h], 4.60517018598809f));
    const float* base = qkv + (size_t)b * NTOK * QKVC + h * DHEAD;

    uint32_t* knHi = dsm_a + KHI_OFF;
    uint32_t* knLo = dsm_a + KLO_OFF;
    uint32_t* vtHi = dsm_a + VHI_OFF;
    uint32_t* vtLo = dsm_a + VLO_OFF;
    float*    pvb  = (float*)(dsm_a + PVB_OFF);
    float*    sumb = (float*)(dsm_a + SUM_OFF);
    const uint32_t knHiB = s2u(knHi);
    const uint32_t knLoB = s2u(knLo);
    const uint32_t vtHiB = s2u(vtHi);
    const uint32_t vtLoB = s2u(vtLo);

#pragma unroll
    for (int i = 0; i < 8; i++) {
        int j = warp * 8 + i;
        float kv = base[(size_t)j * QKVC + CDIM + lane];
        float s = kv * kv;
#pragma unroll
        for (int o = 16; o > 0; o >>= 1) s += __shfl_xor_sync(0xffffffffu, s, o);
        kv *= rsqrtf(s);
        uint32_t khi, klo; tf32_split(kv, khi, klo);
        knHi[j * KSTRIDE + lane] = khi;
        knLo[j * KSTRIDE + lane] = klo;

        float vv = base[(size_t)j * QKVC + 2 * CDIM + lane];
        uint32_t vhi, vlo; tf32_split(vv, vhi, vlo);
        vtHi[lane * VSTRIDE + j] = vhi;
        vtLo[lane * VSTRIDE + j] = vlo;
    }

    float qf[4][4];
    {
        const float* q0 = base + (size_t)(R0 + g) * QKVC;
        const float* q1 = base + (size_t)(R0 + g + 8) * QKVC;
#pragma unroll
        for (int kk = 0; kk < 4; kk++) {
            qf[kk][0] = q0[8 * kk + t];
            qf[kk][1] = q1[8 * kk + t];
            qf[kk][2] = q0[8 * kk + t + 4];
            qf[kk][3] = q1[8 * kk + t + 4];
        }
        float s0 = 0.f, s1 = 0.f;
#pragma unroll
        for (int kk = 0; kk < 4; kk++) {
            s0 += qf[kk][0] * qf[kk][0] + qf[kk][2] * qf[kk][2];
            s1 += qf[kk][1] * qf[kk][1] + qf[kk][3] * qf[kk][3];
        }
        s0 += __shfl_xor_sync(0xffffffffu, s0, 1);
        s0 += __shfl_xor_sync(0xffffffffu, s0, 2);
        s1 += __shfl_xor_sync(0xffffffffu, s1, 1);
        s1 += __shfl_xor_sync(0xffffffffu, s1, 2);
        float r0 = rsqrtf(s0) * scale, r1 = rsqrtf(s1) * scale;
#pragma unroll
        for (int kk = 0; kk < 4; kk++) {
            qf[kk][0] *= r0; qf[kk][2] *= r0;
            qf[kk][1] *= r1; qf[kk][3] *= r1;
        }
    }
    __syncthreads();

    float acc[10][4];
#pragma unroll
    for (int nt = 0; nt < 10; nt++)
#pragma unroll
        for (int c = 0; c < 4; c++) acc[nt][c] = 0.f;

    const uint32_t ldsmRow = (uint32_t)((lane & 7) + ((lane & 16) ? 8 : 0));
    const uint32_t ldsmCol = (uint32_t)((lane >> 3) & 1) * 16;

#pragma unroll
    for (int kk = 0; kk < 4; kk++) {
        uint32_t ah[4], al[4];
#pragma unroll
        for (int i = 0; i < 4; i++) tf32_split(qf[kk][i], ah[i], al[i]);
#pragma unroll
        for (int gI = 0; gI < 5; gI++) {
            if (gI < ng) {
                uint32_t off = (uint32_t)(hbase + gI * 16 + ldsmRow) * (KSTRIDE * 4)
                             + ldsmCol + kk * 32;
                uint32_t bh0, bh1, bh2, bh3, bl0, bl1, bl2, bl3;
                LDSM_X4(bh0, bh1, bh2, bh3, knHiB + off);
                LDSM_X4(bl0, bl1, bl2, bl3, knLoB + off);
                MMA_TF32(acc[2 * gI],     ah[0], ah[1], ah[2], ah[3], bh0, bh1);
                MMA_TF32(acc[2 * gI],     ah[0], ah[1], ah[2], ah[3], bl0, bl1);
                MMA_TF32(acc[2 * gI],     al[0], al[1], al[2], al[3], bh0, bh1);
                MMA_TF32(acc[2 * gI + 1], ah[0], ah[1], ah[2], ah[3], bh2, bh3);
                MMA_TF32(acc[2 * gI + 1], ah[0], ah[1], ah[2], ah[3], bl2, bl3);
                MMA_TF32(acc[2 * gI + 1], al[0], al[1], al[2], al[3], bh2, bh3);
            }
        }
    }

    float sm0 = 0.f, sm1 = 0.f;
    {
        const float* biasR0 = bias + (size_t)h * NTOK * NTOK + (size_t)(R0 + g) * NTOK + hbase + 2 * t;
        const float* biasR1 = biasR0 + 8 * NTOK;
        const float* maskR0 = mask + (size_t)w * NTOK * NTOK + (size_t)(R0 + g) * NTOK + hbase + 2 * t;
        const float* maskR1 = maskR0 + 8 * NTOK;
#pragma unroll
        for (int nt = 0; nt < 10; nt++) {
            if (nt < 2 * ng) {
                float2 bb0 = *(const float2*)(biasR0 + 8 * nt);
                float2 mm0 = *(const float2*)(maskR0 + 8 * nt);
                float2 bb1 = *(const float2*)(biasR1 + 8 * nt);
                float2 mm1 = *(const float2*)(maskR1 + 8 * nt);
                acc[nt][0] = __expf(acc[nt][0] + bb0.x + mm0.x);
                acc[nt][1] = __expf(acc[nt][1] + bb0.y + mm0.y);
                acc[nt][2] = __expf(acc[nt][2] + bb1.x + mm1.x);
                acc[nt][3] = __expf(acc[nt][3] + bb1.y + mm1.y);
                sm0 += acc[nt][0] + acc[nt][1];
                sm1 += acc[nt][2] + acc[nt][3];
            }
        }
        sm0 += __shfl_xor_sync(0xffffffffu, sm0, 1);
        sm0 += __shfl_xor_sync(0xffffffffu, sm0, 2);
        sm1 += __shfl_xor_sync(0xffffffffu, sm1, 1);
        sm1 += __shfl_xor_sync(0xffffffffu, sm1, 2);
        if (t == 0) {
            sumb[(pair * 2 + half) * 16 + g]     = sm0;
            sumb[(pair * 2 + half) * 16 + g + 8] = sm1;
        }
    }

    float pv[4][4];
#pragma unroll
    for (int nt = 0; nt < 4; nt++)
#pragma unroll
        for (int c = 0; c < 4; c++) pv[nt][c] = 0.f;

    const int src1 = (lane & 28) | (t >> 1);
    const int src2 = src1 + 2;
    const bool oddc = (t & 1);

#pragma unroll
    for (int kk2 = 0; kk2 < 10; kk2++) {
        if (kk2 < 2 * ng) {
            float s00 = __shfl_sync(0xffffffffu, acc[kk2][0], src1);
            float s01 = __shfl_sync(0xffffffffu, acc[kk2][1], src1);
            float s02 = __shfl_sync(0xffffffffu, acc[kk2][0], src2);
            float s03 = __shfl_sync(0xffffffffu, acc[kk2][1], src2);
            float s10 = __shfl_sync(0xffffffffu, acc[kk2][2], src1);
            float s11 = __shfl_sync(0xffffffffu, acc[kk2][3], src1);
            float s12 = __shfl_sync(0xffffffffu, acc[kk2][2], src2);
            float s13 = __shfl_sync(0xffffffffu, acc[kk2][3], src2);
            float a0 = oddc ? s01 : s00;
            float a1 = oddc ? s11 : s10;
            float a2 = oddc ? s03 : s02;
            float a3 = oddc ? s13 : s12;
            uint32_t ah[4], al[4];
            tf32_split(a0, ah[0], al[0]);
            tf32_split(a1, ah[1], al[1]);
            tf32_split(a2, ah[2], al[2]);
            tf32_split(a3, ah[3], al[3]);
            const int kkG = (hbase >> 3) + kk2;
#pragma unroll
            for (int p = 0; p < 2; p++) {
                uint32_t off = (uint32_t)(p * 16 + ldsmRow) * (VSTRIDE * 4)
                             + ldsmCol + (uint32_t)kkG * 32;
                uint32_t bh0, bh1, bh2, bh3, bl0, bl1, bl2, bl3;
                LDSM_X4(bh0, bh1, bh2, bh3, vtHiB + off);
                LDSM_X4(bl0, bl1, bl2, bl3, vtLoB + off);
                MMA_TF32(pv[2 * p],     ah[0], ah[1], ah[2], ah[3], bh0, bh1);
                MMA_TF32(pv[2 * p],     ah[0], ah[1], ah[2], ah[3], bl0, bl1);
                MMA_TF32(pv[2 * p],     al[0], al[1], al[2], al[3], bh0, bh1);
                MMA_TF32(pv[2 * p + 1], ah[0], ah[1], ah[2], ah[3], bh2, bh3);
                MMA_TF32(pv[2 * p + 1], ah[0], ah[1], ah[2], ah[3], bl2, bl3);
                MMA_TF32(pv[2 * p + 1], al[0], al[1], al[2], al[3], bh2, bh3);
            }
        }
    }

    if (half == 1) {
        float* pb = pvb + (pair * 32 + lane) * PVSTR;
#pragma unroll
        for (int nt = 0; nt < 4; nt++) {
            *(float2*)(pb + nt * 4)     = make_float2(pv[nt][0], pv[nt][1]);
            *(float2*)(pb + nt * 4 + 2) = make_float2(pv[nt][2], pv[nt][3]);
        }
    }
    __syncthreads();
    if (half == 0) {
        const float inv0 = 1.f / (sm0 + sumb[(pair * 2 + 1) * 16 + g]);
        const float inv1 = 1.f / (sm1 + sumb[(pair * 2 + 1) * 16 + g + 8]);
        const float* pb = pvb + (pair * 32 + lane) * PVSTR;
        float* o0 = out + ((size_t)b * NTOK + R0 + g) * CDIM + h * DHEAD + 2 * t;
        float* o1 = o0 + (size_t)8 * CDIM;
#pragma unroll
        for (int nt = 0; nt < 4; nt++) {
            float2 q0 = *(const float2*)(pb + nt * 4);
            float2 q1 = *(const float2*)(pb + nt * 4 + 2);
            *(float2*)(o0 + 8 * nt) = make_float2((pv[nt][0] + q0.x) * inv0,
                                                  (pv[nt][1] + q0.y) * inv0);
            *(float2*)(o1 + 8 * nt) = make_float2((pv[nt][2] + q1.x) * inv1,
                                                  (pv[nt][3] + q1.y) * inv1);
        }
    }
}

// =========================================================================
// launch
// =========================================================================
extern "C" void kernel_launch(void* const* d_in, const int* in_sizes, int n_in,
                              void* d_out, int out_size)
{
    const float* x           = (const float*)d_in[0];
    const float* mask        = (const float*)d_in[1];
    const float* qkv_w       = (const float*)d_in[2];
    const float* logit_scale = (const float*)d_in[3];
    const float* cpb_w1      = (const float*)d_in[4];
    const float* cpb_b1      = (const float*)d_in[5];
    const float* cpb_w2      = (const float*)d_in[6];
    const float* proj_w      = (const float*)d_in[7];
    const float* proj_b      = (const float*)d_in[8];
    const float* rel_table   = (const float*)d_in[9];
    const int*   rel_index   = (const int*)d_in[10];
    float* out = (float*)d_out;

    float *qkv, *att, *tbl, *bias;
    cudaGetSymbolAddress((void**)&qkv,  g_qkv);
    cudaGetSymbolAddress((void**)&att,  g_att);
    cudaGetSymbolAddress((void**)&tbl,  g_tbl);
    cudaGetSymbolAddress((void**)&bias, g_bias);

    cudaFuncSetAttribute(gemm_f16_nt<false>,
                         cudaFuncAttributeMaxDynamicSharedMemorySize, GT_SMEM_BYTES);
    cudaFuncSetAttribute(gemm_f16_nt<true>,
                         cudaFuncAttributeMaxDynamicSharedMemorySize, GT_SMEM_BYTES);
    cudaFuncSetAttribute(attn_tc2_kernel,
                         cudaFuncAttributeMaxDynamicSharedMemorySize, ATTN_SMEM_BYTES);

    // 1) QKV projection: 73728 x 1536 x 512 (fp16 m16n8k16)
    {
        dim3 grid(QKVC / 256, MROWS / 128);
        gemm_f16_nt<false><<<grid, 256, GT_SMEM_BYTES>>>(x, qkv_w, nullptr, qkv,
                                                         MROWS, QKVC, CDIM);
    }

    // 2) relative position bias table + gather
    cpb_tbl_kernel<<<NPOS, CPBH>>>(rel_table, cpb_w1, cpb_b1, cpb_w2, tbl);
    {
        int tot = HEADS * NTOK * NTOK;
        bias_gather_kernel<<<(tot + 255) / 256, 256>>>(tbl, rel_index, bias);
    }

    // 3) tensor-core attention v2 (unchanged)
    {
        dim3 grid(HEADS, BWIN);
        attn_tc2_kernel<<<grid, 576, ATTN_SMEM_BYTES>>>(qkv, bias, mask, logit_scale, att);
    }

    // 4) output projection: 73728 x 512 x 512 (fp16 m16n8k16)
    {
        dim3 grid(CDIM / 256, MROWS / 128);
        gemm_f16_nt<true><<<grid, 256, GT_SMEM_BYTES>>>(att, proj_w, proj_b, out,
                                                        MROWS, CDIM, CDIM);
    }
}

// round 8
// speedup vs baseline: 4.4099x; 1.1217x over previous
#include <cuda_runtime.h>
#include <cuda_bf16.h>
#include <cuda_fp16.h>
#include <math.h>
#include <stdint.h>

// ---------------- problem constants ----------------
#define BWIN   512
#define NTOK   144
#define CDIM   512
#define HEADS  16
#define DHEAD  32
#define NW     64
#define MROWS  (BWIN * NTOK)        // 73728
#define QKVC   (3 * CDIM)           // 1536
#define NPOS   (23 * 23)
#define CPBH   512

// ---------------- scratch ----------------
__device__ float g_qkv [(size_t)MROWS * QKVC];
__device__ float g_att [(size_t)MROWS * CDIM];
__device__ float g_tbl [NPOS * HEADS];
__device__ float g_bias[(size_t)HEADS * NTOK * NTOK];

__device__ __forceinline__ uint32_t s2u(const void* p) {
    return (uint32_t)__cvta_generic_to_shared(p);
}
__device__ __forceinline__ uint2 f4_to_h4(float4 v) {
    __half2 h0 = __float22half2_rn(make_float2(v.x, v.y));
    __half2 h1 = __float22half2_rn(make_float2(v.z, v.w));
    uint2 u;
    u.x = *(uint32_t*)&h0;
    u.y = *(uint32_t*)&h1;
    return u;
}
// split x,y into fp16 hi pair + fp16 residual pair
__device__ __forceinline__ void split_pack(float x, float y, uint32_t& hi, uint32_t& lo) {
    __half hx = __float2half_rn(x), hy = __float2half_rn(y);
    __half2 h = __halves2half2(hx, hy);
    hi = *(uint32_t*)&h;
    __half2 l = __floats2half2_rn(x - __half2float(hx), y - __half2float(hy));
    lo = *(uint32_t*)&l;
}

#define MMA_F16(d, a0,a1,a2,a3, b0,b1)                                         \
    asm volatile("mma.sync.aligned.m16n8k16.row.col.f32.f16.f16.f32 "          \
                 "{%0,%1,%2,%3},{%4,%5,%6,%7},{%8,%9},{%0,%1,%2,%3};"          \
                 : "+f"(d[0]), "+f"(d[1]), "+f"(d[2]), "+f"(d[3])              \
                 : "r"(a0), "r"(a1), "r"(a2), "r"(a3), "r"(b0), "r"(b1))

#define LDSM_X4(r0,r1,r2,r3, addr)                                             \
    asm volatile("ldmatrix.sync.aligned.m8n8.x4.shared.b16 {%0,%1,%2,%3}, [%4];" \
                 : "=r"(r0), "=r"(r1), "=r"(r2), "=r"(r3) : "r"(addr))

// =========================================================================
// FP16 tensor-core GEMM (NT) — unchanged from R7 (proven)
// =========================================================================
#define GBK    32
#define GLDH   40
#define ABUFH  (128 * GLDH)
#define BBUFH  (256 * GLDH)
#define GT_SMEM_BYTES ((2 * ABUFH + 2 * BBUFH) * 2)   // 61440

template <bool HAS_BIAS>
__global__ __launch_bounds__(256, 1)
void gemm_f16_nt(const float* __restrict__ A,
                 const float* __restrict__ B,
                 const float* __restrict__ bias,
                 float* __restrict__ C,
                 int M, int N, int K)
{
    extern __shared__ __align__(16) __half gsm[];
    __half* As = gsm;
    __half* Bs = gsm + 2 * ABUFH;

    const int tid  = threadIdx.x;
    const int lane = tid & 31;
    const int warp = tid >> 5;
    const int warpM = (warp & 1) * 64;
    const int warpN = (warp >> 1) * 64;
    const int rowBase = blockIdx.y * 128;
    const int colBase = blockIdx.x * 256;

    const int r  = tid >> 3;
    const int kq = tid & 7;
    const float* Ag = A + (size_t)(rowBase + r) * K + kq * 4;
    const float* Bg = B + (size_t)(colBase + r) * K + kq * 4;

    float4 ra[4], rb[8];

    float acc[4][8][4];
#pragma unroll
    for (int mi = 0; mi < 4; mi++)
#pragma unroll
        for (int ni = 0; ni < 8; ni++)
#pragma unroll
            for (int c = 0; c < 4; c++) acc[mi][ni][c] = 0.f;

    const uint32_t aOff = (uint32_t)((warpM + (lane & 7) + ((lane >> 3) & 1) * 8) * (GLDH * 2))
                        + (uint32_t)(lane >> 4) * 16;
    const uint32_t bOff = (uint32_t)((warpN + (lane & 7) + ((lane & 16) ? 8 : 0)) * (GLDH * 2))
                        + (uint32_t)((lane >> 3) & 1) * 16;
    const uint32_t asBase = s2u(As);
    const uint32_t bsBase = s2u(Bs);

#define G_LOAD(it)  {                                                \
        const float* ap = Ag + (it) * GBK;                           \
        const float* bp = Bg + (it) * GBK;                           \
        ra[0] = *(const float4*)(ap);                                \
        ra[1] = *(const float4*)(ap + (size_t)32 * K);               \
        ra[2] = *(const float4*)(ap + (size_t)64 * K);               \
        ra[3] = *(const float4*)(ap + (size_t)96 * K);               \
        rb[0] = *(const float4*)(bp);                                \
        rb[1] = *(const float4*)(bp + (size_t)32 * K);               \
        rb[2] = *(const float4*)(bp + (size_t)64 * K);               \
        rb[3] = *(const float4*)(bp + (size_t)96 * K);               \
        rb[4] = *(const float4*)(bp + (size_t)128 * K);              \
        rb[5] = *(const float4*)(bp + (size_t)160 * K);              \
        rb[6] = *(const float4*)(bp + (size_t)192 * K);              \
        rb[7] = *(const float4*)(bp + (size_t)224 * K);              \
    }
#define G_STS(buf)  {                                                           \
        _Pragma("unroll")                                                       \
        for (int i = 0; i < 4; i++)                                             \
            *(uint2*)&As[(buf) * ABUFH + (r + 32 * i) * GLDH + kq * 4] = f4_to_h4(ra[i]); \
        _Pragma("unroll")                                                       \
        for (int i = 0; i < 8; i++)                                             \
            *(uint2*)&Bs[(buf) * BBUFH + (r + 32 * i) * GLDH + kq * 4] = f4_to_h4(rb[i]); \
    }

    G_LOAD(0); G_STS(0); __syncthreads();

    const int NIT = K / GBK;
    for (int it = 0; it < NIT; ++it) {
        const int buf = it & 1;
        if (it + 1 < NIT) G_LOAD(it + 1);

        const uint32_t aB = asBase + (uint32_t)buf * (ABUFH * 2);
        const uint32_t bB = bsBase + (uint32_t)buf * (BBUFH * 2);

#pragma unroll
        for (int kk = 0; kk < 2; kk++) {
            uint32_t a[4][4], bf[8][2];
#pragma unroll
            for (int mi = 0; mi < 4; mi++) {
                uint32_t addr = aB + aOff + (uint32_t)(mi * 16 * GLDH * 2) + (uint32_t)(kk * 32);
                LDSM_X4(a[mi][0], a[mi][1], a[mi][2], a[mi][3], addr);
            }
#pragma unroll
            for (int p = 0; p < 4; p++) {
                uint32_t addr = bB + bOff + (uint32_t)(p * 16 * GLDH * 2) + (uint32_t)(kk * 32);
                uint32_t r0, r1, r2, r3;
                LDSM_X4(r0, r1, r2, r3, addr);
                bf[2 * p][0] = r0; bf[2 * p][1] = r1;
                bf[2 * p + 1][0] = r2; bf[2 * p + 1][1] = r3;
            }
#pragma unroll
            for (int mi = 0; mi < 4; mi++)
#pragma unroll
                for (int ni = 0; ni < 8; ni++)
                    MMA_F16(acc[mi][ni], a[mi][0], a[mi][1], a[mi][2], a[mi][3],
                            bf[ni][0], bf[ni][1]);
        }
        if (it + 1 < NIT) G_STS(buf ^ 1);
        __syncthreads();
    }

    const int g  = lane >> 2;
    const int cq = (lane & 3) * 2;
#pragma unroll
    for (int mi = 0; mi < 4; mi++) {
        const int row0 = rowBase + warpM + mi * 16 + g;
#pragma unroll
        for (int ni = 0; ni < 8; ni++) {
            const int col = colBase + warpN + ni * 8 + cq;
            float b0 = 0.f, b1 = 0.f;
            if (HAS_BIAS) { b0 = bias[col]; b1 = bias[col + 1]; }
            *(float2*)&C[(size_t)row0 * N + col] =
                make_float2(acc[mi][ni][0] + b0, acc[mi][ni][1] + b1);
            *(float2*)&C[(size_t)(row0 + 8) * N + col] =
                make_float2(acc[mi][ni][2] + b0, acc[mi][ni][3] + b1);
        }
    }
#undef G_LOAD
#undef G_STS
}

// =========================================================================
// CPB MLP table + bias gather (tiny, unchanged)
// =========================================================================
__global__ __launch_bounds__(512)
void cpb_tbl_kernel(const float* __restrict__ rel_table,
                    const float* __restrict__ w1,
                    const float* __restrict__ b1,
                    const float* __restrict__ w2,
                    float* __restrict__ tbl)
{
    __shared__ float hid[CPBH];
    int p = blockIdx.x;
    float t0 = rel_table[2 * p], t1 = rel_table[2 * p + 1];
    int j = threadIdx.x;
    hid[j] = fmaxf(t0 * w1[2 * j] + t1 * w1[2 * j + 1] + b1[j], 0.f);
    __syncthreads();

    int warp = j >> 5, lane = j & 31;
    const float* w2h = w2 + warp * CPBH;
    float s = 0.f;
#pragma unroll
    for (int q = lane; q < CPBH; q += 32) s += hid[q] * w2h[q];
#pragma unroll
    for (int o = 16; o > 0; o >>= 1) s += __shfl_xor_sync(0xffffffffu, s, o);
    if (lane == 0) tbl[p * HEADS + warp] = s;
}

__global__ void bias_gather_kernel(const float* __restrict__ tbl,
                                   const int* __restrict__ rel_index,
                                   float* __restrict__ bias)
{
    int t = blockIdx.x * blockDim.x + threadIdx.x;
    const int TOT = HEADS * NTOK * NTOK;
    if (t >= TOT) return;
    int h  = t / (NTOK * NTOK);
    int ij = t % (NTOK * NTOK);
    float x = tbl[rel_index[ij] * HEADS + h];
    bias[(size_t)h * NTOK * NTOK + ij] = 16.f / (1.f + __expf(-x));
}

// =========================================================================
// Window attention v3: split-FP16 (hi+lo) mma.m16n8k16, 18 warps / CTA.
// Warp pair (p, p+9) owns query rows [16p,16p+16); half0 -> key cols 0..63,
// half1 -> 64..143. Local-max softmax per half; halves merged with
// exp(m_local - M) factors in the epilogue. Score fragments feed PV A-frags
// directly (no shuffles).
// =========================================================================
#define KSTR_H 40                            // halves per K row (32 + 8 pad)
#define VSTR_H 152                           // halves per V^T row (144 + 8 pad)
#define PVSTR  18

#define AK_KHI 0
#define AK_KLO (AK_KHI + NTOK * KSTR_H * 2)          // 11520
#define AK_VHI (AK_KLO + NTOK * KSTR_H * 2)          // 23040
#define AK_VLO (AK_VHI + DHEAD * VSTR_H * 2)         // 32768
#define AK_PVB (AK_VLO + DHEAD * VSTR_H * 2)         // 42496
#define AK_SUM (AK_PVB + 9 * 32 * PVSTR * 4)         // 63232
#define ATTN_SMEM_BYTES (AK_SUM + 9 * 2 * 32 * 4)    // 65536

__global__ __launch_bounds__(576, 1)
void attn_tc3_kernel(const float* __restrict__ qkv,
                     const float* __restrict__ bias,
                     const float* __restrict__ mask,
                     const float* __restrict__ logit_scale,
                     float* __restrict__ out)
{
    extern __shared__ __align__(16) char dsm[];

    const int h = blockIdx.x;
    const int b = blockIdx.y;
    const int w = b & (NW - 1);

    const int tid  = threadIdx.x;
    const int lane = tid & 31;
    const int warp = tid >> 5;           // 0..17
    const int pair = warp % 9;
    const int half = warp / 9;           // 0: cols 0..63, 1: 64..143
    const int ng   = half ? 5 : 4;       // 16-col groups owned
    const int hbase = half ? 64 : 0;
    const int g  = lane >> 2;
    const int t  = lane & 3;
    const int R0 = pair * 16;

    const float scale = __expf(fminf(logit_scale[h], 4.60517018598809f));
    const float* base = qkv + (size_t)b * NTOK * QKVC + h * DHEAD;

    __half* knHi = (__half*)(dsm + AK_KHI);
    __half* knLo = (__half*)(dsm + AK_KLO);
    __half* vtHi = (__half*)(dsm + AK_VHI);
    __half* vtLo = (__half*)(dsm + AK_VLO);
    float*  pvb  = (float*)(dsm + AK_PVB);
    float*  sumb = (float*)(dsm + AK_SUM);
    const uint32_t knHiB = s2u(knHi);
    const uint32_t knLoB = s2u(knLo);
    const uint32_t vtHiB = s2u(vtHi);
    const uint32_t vtLoB = s2u(vtLo);

    // ---------- load K (normalized, hi/lo fp16) and V^T (hi/lo fp16) ----
#pragma unroll
    for (int i = 0; i < 8; i++) {
        int j = warp * 8 + i;
        float kv = base[(size_t)j * QKVC + CDIM + lane];
        float s = kv * kv;
#pragma unroll
        for (int o = 16; o > 0; o >>= 1) s += __shfl_xor_sync(0xffffffffu, s, o);
        kv *= rsqrtf(s);
        __half khi = __float2half_rn(kv);
        knHi[j * KSTR_H + lane] = khi;
        knLo[j * KSTR_H + lane] = __float2half_rn(kv - __half2float(khi));

        float vv = base[(size_t)j * QKVC + 2 * CDIM + lane];
        __half vhi = __float2half_rn(vv);
        vtHi[lane * VSTR_H + j] = vhi;
        vtLo[lane * VSTR_H + j] = __float2half_rn(vv - __half2float(vhi));
    }

    // ---------- Q fragments (normalized + scaled, split fp16) ----------
    // qah/qal[kc][0..3]: m16n8k16 A fragment for k-chunk kc (dhead 0..15 / 16..31)
    uint32_t qah[2][4], qal[2][4];
    {
        const float* q0 = base + (size_t)(R0 + g) * QKVC;
        const float* q1 = base + (size_t)(R0 + g + 8) * QKVC;
        float e0[2][4], e1[2][4];
#pragma unroll
        for (int kc = 0; kc < 2; kc++) {
            e0[kc][0] = q0[16 * kc + 2 * t];     e0[kc][1] = q0[16 * kc + 2 * t + 1];
            e0[kc][2] = q0[16 * kc + 8 + 2 * t]; e0[kc][3] = q0[16 * kc + 9 + 2 * t];
            e1[kc][0] = q1[16 * kc + 2 * t];     e1[kc][1] = q1[16 * kc + 2 * t + 1];
            e1[kc][2] = q1[16 * kc + 8 + 2 * t]; e1[kc][3] = q1[16 * kc + 9 + 2 * t];
        }
        float s0 = 0.f, s1 = 0.f;
#pragma unroll
        for (int kc = 0; kc < 2; kc++)
#pragma unroll
            for (int i = 0; i < 4; i++) {
                s0 += e0[kc][i] * e0[kc][i];
                s1 += e1[kc][i] * e1[kc][i];
            }
        s0 += __shfl_xor_sync(0xffffffffu, s0, 1);
        s0 += __shfl_xor_sync(0xffffffffu, s0, 2);
        s1 += __shfl_xor_sync(0xffffffffu, s1, 1);
        s1 += __shfl_xor_sync(0xffffffffu, s1, 2);
        float r0 = rsqrtf(s0) * scale, r1 = rsqrtf(s1) * scale;
#pragma unroll
        for (int kc = 0; kc < 2; kc++) {
            split_pack(e0[kc][0] * r0, e0[kc][1] * r0, qah[kc][0], qal[kc][0]);
            split_pack(e1[kc][0] * r1, e1[kc][1] * r1, qah[kc][1], qal[kc][1]);
            split_pack(e0[kc][2] * r0, e0[kc][3] * r0, qah[kc][2], qal[kc][2]);
            split_pack(e1[kc][2] * r1, e1[kc][3] * r1, qah[kc][3], qal[kc][3]);
        }
    }
    __syncthreads();

    // ---------- QK^T (split fp16): acc[2*ng][4] ----------
    float acc[10][4];
#pragma unroll
    for (int nt = 0; nt < 10; nt++)
#pragma unroll
        for (int c = 0; c < 4; c++) acc[nt][c] = 0.f;

    const uint32_t ldsmRow = (uint32_t)((lane & 7) + ((lane & 16) ? 8 : 0));
    const uint32_t ldsmCol = (uint32_t)((lane >> 3) & 1) * 16;

#pragma unroll
    for (int kc = 0; kc < 2; kc++) {
#pragma unroll
        for (int gI = 0; gI < 5; gI++) {
            if (gI < ng) {
                uint32_t off = (uint32_t)(hbase + gI * 16 + ldsmRow) * (KSTR_H * 2)
                             + ldsmCol + (uint32_t)kc * 32;
                uint32_t bh0, bh1, bh2, bh3, bl0, bl1, bl2, bl3;
                LDSM_X4(bh0, bh1, bh2, bh3, knHiB + off);
                LDSM_X4(bl0, bl1, bl2, bl3, knLoB + off);
                MMA_F16(acc[2 * gI],     qah[kc][0], qah[kc][1], qah[kc][2], qah[kc][3], bh0, bh1);
                MMA_F16(acc[2 * gI],     qah[kc][0], qah[kc][1], qah[kc][2], qah[kc][3], bl0, bl1);
                MMA_F16(acc[2 * gI],     qal[kc][0], qal[kc][1], qal[kc][2], qal[kc][3], bh0, bh1);
                MMA_F16(acc[2 * gI + 1], qah[kc][0], qah[kc][1], qah[kc][2], qah[kc][3], bh2, bh3);
                MMA_F16(acc[2 * gI + 1], qah[kc][0], qah[kc][1], qah[kc][2], qah[kc][3], bl2, bl3);
                MMA_F16(acc[2 * gI + 1], qal[kc][0], qal[kc][1], qal[kc][2], qal[kc][3], bh2, bh3);
            }
        }
    }

    // ---------- bias + mask, local max, exp, local sums ----------
    float mx0 = -1e30f, mx1 = -1e30f, sm0 = 0.f, sm1 = 0.f;
    {
        const float* biasR0 = bias + (size_t)h * NTOK * NTOK + (size_t)(R0 + g) * NTOK + hbase + 2 * t;
        const float* biasR1 = biasR0 + 8 * NTOK;
        const float* maskR0 = mask + (size_t)w * NTOK * NTOK + (size_t)(R0 + g) * NTOK + hbase + 2 * t;
        const float* maskR1 = maskR0 + 8 * NTOK;
#pragma unroll
        for (int nt = 0; nt < 10; nt++) {
            if (nt < 2 * ng) {
                float2 bb0 = *(const float2*)(biasR0 + 8 * nt);
                float2 mm0 = *(const float2*)(maskR0 + 8 * nt);
                float2 bb1 = *(const float2*)(biasR1 + 8 * nt);
                float2 mm1 = *(const float2*)(maskR1 + 8 * nt);
                acc[nt][0] += bb0.x + mm0.x;
                acc[nt][1] += bb0.y + mm0.y;
                acc[nt][2] += bb1.x + mm1.x;
                acc[nt][3] += bb1.y + mm1.y;
                mx0 = fmaxf(mx0, fmaxf(acc[nt][0], acc[nt][1]));
                mx1 = fmaxf(mx1, fmaxf(acc[nt][2], acc[nt][3]));
            }
        }
        mx0 = fmaxf(mx0, __shfl_xor_sync(0xffffffffu, mx0, 1));
        mx0 = fmaxf(mx0, __shfl_xor_sync(0xffffffffu, mx0, 2));
        mx1 = fmaxf(mx1, __shfl_xor_sync(0xffffffffu, mx1, 1));
        mx1 = fmaxf(mx1, __shfl_xor_sync(0xffffffffu, mx1, 2));
#pragma unroll
        for (int nt = 0; nt < 10; nt++) {
            if (nt < 2 * ng) {
                acc[nt][0] = __expf(acc[nt][0] - mx0);
                acc[nt][1] = __expf(acc[nt][1] - mx0);
                acc[nt][2] = __expf(acc[nt][2] - mx1);
                acc[nt][3] = __expf(acc[nt][3] - mx1);
                sm0 += acc[nt][0] + acc[nt][1];
                sm1 += acc[nt][2] + acc[nt][3];
            }
        }
        sm0 += __shfl_xor_sync(0xffffffffu, sm0, 1);
        sm0 += __shfl_xor_sync(0xffffffffu, sm0, 2);
        sm1 += __shfl_xor_sync(0xffffffffu, sm1, 1);
        sm1 += __shfl_xor_sync(0xffffffffu, sm1, 2);
        if (t == 0) {
            float* sb = sumb + (pair * 2 + half) * 32;
            sb[g]          = sm0;
            sb[g + 8]      = sm1;
            sb[16 + g]     = mx0;
            sb[16 + g + 8] = mx1;
        }
    }

    // ---------- PV (split fp16; score fragments ARE the A fragments) ----
    float pv[4][4];
#pragma unroll
    for (int nt = 0; nt < 4; nt++)
#pragma unroll
        for (int c = 0; c < 4; c++) pv[nt][c] = 0.f;

#pragma unroll
    for (int kc2 = 0; kc2 < 5; kc2++) {
        if (kc2 < ng) {
            uint32_t ph[4], pl[4];
            split_pack(acc[2 * kc2][0],     acc[2 * kc2][1],     ph[0], pl[0]);
            split_pack(acc[2 * kc2][2],     acc[2 * kc2][3],     ph[1], pl[1]);
            split_pack(acc[2 * kc2 + 1][0], acc[2 * kc2 + 1][1], ph[2], pl[2]);
            split_pack(acc[2 * kc2 + 1][2], acc[2 * kc2 + 1][3], ph[3], pl[3]);
            const uint32_t gk = (uint32_t)((hbase >> 4) + kc2);
#pragma unroll
            for (int p = 0; p < 2; p++) {
                uint32_t off = (uint32_t)(p * 16 + ldsmRow) * (VSTR_H * 2)
                             + ldsmCol + gk * 32;
                uint32_t bh0, bh1, bh2, bh3, bl0, bl1, bl2, bl3;
                LDSM_X4(bh0, bh1, bh2, bh3, vtHiB + off);
                LDSM_X4(bl0, bl1, bl2, bl3, vtLoB + off);
                MMA_F16(pv[2 * p],     ph[0], ph[1], ph[2], ph[3], bh0, bh1);
                MMA_F16(pv[2 * p],     ph[0], ph[1], ph[2], ph[3], bl0, bl1);
                MMA_F16(pv[2 * p],     pl[0], pl[1], pl[2], pl[3], bh0, bh1);
                MMA_F16(pv[2 * p + 1], ph[0], ph[1], ph[2], ph[3], bh2, bh3);
                MMA_F16(pv[2 * p + 1], ph[0], ph[1], ph[2], ph[3], bl2, bl3);
                MMA_F16(pv[2 * p + 1], pl[0], pl[1], pl[2], pl[3], bh2, bh3);
            }
        }
    }

    // ---------- pairwise combine (max-corrected) + epilogue ----------
    if (half == 1) {
        float* pb = pvb + (pair * 32 + lane) * PVSTR;
#pragma unroll
        for (int nt = 0; nt < 4; nt++) {
            *(float2*)(pb + nt * 4)     = make_float2(pv[nt][0], pv[nt][1]);
            *(float2*)(pb + nt * 4 + 2) = make_float2(pv[nt][2], pv[nt][3]);
        }
    }
    __syncthreads();
    if (half == 0) {
        const float* sbO = sumb + (pair * 2 + 1) * 32;
        const float smO0 = sbO[g],      mxO0 = sbO[16 + g];
        const float smO1 = sbO[g + 8],  mxO1 = sbO[16 + g + 8];
        const float M0 = fmaxf(mx0, mxO0);
        const float M1 = fmaxf(mx1, mxO1);
        const float fl0 = __expf(mx0 - M0), fo0 = __expf(mxO0 - M0);
        const float fl1 = __expf(mx1 - M1), fo1 = __expf(mxO1 - M1);
        const float inv0 = 1.f / (sm0 * fl0 + smO0 * fo0);
        const float inv1 = 1.f / (sm1 * fl1 + smO1 * fo1);
        const float* pb = pvb + (pair * 32 + lane) * PVSTR;
        float* o0 = out + ((size_t)b * NTOK + R0 + g) * CDIM + h * DHEAD + 2 * t;
        float* o1 = o0 + (size_t)8 * CDIM;
#pragma unroll
        for (int nt = 0; nt < 4; nt++) {
            float2 q0 = *(const float2*)(pb + nt * 4);
            float2 q1 = *(const float2*)(pb + nt * 4 + 2);
            *(float2*)(o0 + 8 * nt) = make_float2((pv[nt][0] * fl0 + q0.x * fo0) * inv0,
                                                  (pv[nt][1] * fl0 + q0.y * fo0) * inv0);
            *(float2*)(o1 + 8 * nt) = make_float2((pv[nt][2] * fl1 + q1.x * fo1) * inv1,
                                                  (pv[nt][3] * fl1 + q1.y * fo1) * inv1);
        }
    }
}

// =========================================================================
// launch
// =========================================================================
extern "C" void kernel_launch(void* const* d_in, const int* in_sizes, int n_in,
                              void* d_out, int out_size)
{
    const float* x           = (const float*)d_in[0];
    const float* mask        = (const float*)d_in[1];
    const float* qkv_w       = (const float*)d_in[2];
    const float* logit_scale = (const float*)d_in[3];
    const float* cpb_w1      = (const float*)d_in[4];
    const float* cpb_b1      = (const float*)d_in[5];
    const float* cpb_w2      = (const float*)d_in[6];
    const float* proj_w      = (const float*)d_in[7];
    const float* proj_b      = (const float*)d_in[8];
    const float* rel_table   = (const float*)d_in[9];
    const int*   rel_index   = (const int*)d_in[10];
    float* out = (float*)d_out;

    float *qkv, *att, *tbl, *bias;
    cudaGetSymbolAddress((void**)&qkv,  g_qkv);
    cudaGetSymbolAddress((void**)&att,  g_att);
    cudaGetSymbolAddress((void**)&tbl,  g_tbl);
    cudaGetSymbolAddress((void**)&bias, g_bias);

    cudaFuncSetAttribute(gemm_f16_nt<false>,
                         cudaFuncAttributeMaxDynamicSharedMemorySize, GT_SMEM_BYTES);
    cudaFuncSetAttribute(gemm_f16_nt<true>,
                         cudaFuncAttributeMaxDynamicSharedMemorySize, GT_SMEM_BYTES);
    cudaFuncSetAttribute(attn_tc3_kernel,
                         cudaFuncAttributeMaxDynamicSharedMemorySize, ATTN_SMEM_BYTES);

    // 1) QKV projection (fp16 m16n8k16)
    {
        dim3 grid(QKVC / 256, MROWS / 128);
        gemm_f16_nt<false><<<grid, 256, GT_SMEM_BYTES>>>(x, qkv_w, nullptr, qkv,
                                                         MROWS, QKVC, CDIM);
    }

    // 2) relative position bias table + gather
    cpb_tbl_kernel<<<NPOS, CPBH>>>(rel_table, cpb_w1, cpb_b1, cpb_w2, tbl);
    {
        int tot = HEADS * NTOK * NTOK;
        bias_gather_kernel<<<(tot + 255) / 256, 256>>>(tbl, rel_index, bias);
    }

    // 3) split-FP16 tensor-core attention
    {
        dim3 grid(HEADS, BWIN);
        attn_tc3_kernel<<<grid, 576, ATTN_SMEM_BYTES>>>(qkv, bias, mask, logit_scale, att);
    }

    // 4) output projection (fp16 m16n8k16)
    {
        dim3 grid(CDIM / 256, MROWS / 128);
        gemm_f16_nt<true><<<grid, 256, GT_SMEM_BYTES>>>(att, proj_w, proj_b, out,
                                                        MROWS, CDIM, CDIM);
    }
}

// round 9
// speedup vs baseline: 4.6414x; 1.0525x over previous
#include <cuda_runtime.h>
#include <cuda_bf16.h>
#include <cuda_fp16.h>
#include <math.h>
#include <stdint.h>

// ---------------- problem constants ----------------
#define BWIN   512
#define NTOK   144
#define CDIM   512
#define HEADS  16
#define DHEAD  32
#define NW     64
#define MROWS  (BWIN * NTOK)        // 73728
#define QKVC   (3 * CDIM)           // 1536
#define NPOS   (23 * 23)
#define CPBH   512

// ---------------- scratch ----------------
__device__ float g_qkv [(size_t)MROWS * QKVC];
__device__ float g_att [(size_t)MROWS * CDIM];
__device__ float g_tbl [NPOS * HEADS];
__device__ float g_bias[(size_t)HEADS * NTOK * NTOK];

__device__ __forceinline__ uint32_t s2u(const void* p) {
    return (uint32_t)__cvta_generic_to_shared(p);
}
__device__ __forceinline__ uint2 f4_to_h4(float4 v) {
    __half2 h0 = __float22half2_rn(make_float2(v.x, v.y));
    __half2 h1 = __float22half2_rn(make_float2(v.z, v.w));
    uint2 u;
    u.x = *(uint32_t*)&h0;
    u.y = *(uint32_t*)&h1;
    return u;
}
// split x,y into fp16 hi pair + fp16 residual pair
__device__ __forceinline__ void split_pack(float x, float y, uint32_t& hi, uint32_t& lo) {
    __half hx = __float2half_rn(x), hy = __float2half_rn(y);
    __half2 h = __halves2half2(hx, hy);
    hi = *(uint32_t*)&h;
    __half2 l = __floats2half2_rn(x - __half2float(hx), y - __half2float(hy));
    lo = *(uint32_t*)&l;
}
__device__ __forceinline__ uint32_t pack_h2(float x, float y) {
    __half2 h = __floats2half2_rn(x, y);
    return *(uint32_t*)&h;
}

#define MMA_F16(d, a0,a1,a2,a3, b0,b1)                                         \
    asm volatile("mma.sync.aligned.m16n8k16.row.col.f32.f16.f16.f32 "          \
                 "{%0,%1,%2,%3},{%4,%5,%6,%7},{%8,%9},{%0,%1,%2,%3};"          \
                 : "+f"(d[0]), "+f"(d[1]), "+f"(d[2]), "+f"(d[3])              \
                 : "r"(a0), "r"(a1), "r"(a2), "r"(a3), "r"(b0), "r"(b1))

#define LDSM_X4(r0,r1,r2,r3, addr)                                             \
    asm volatile("ldmatrix.sync.aligned.m8n8.x4.shared.b16 {%0,%1,%2,%3}, [%4];" \
                 : "=r"(r0), "=r"(r1), "=r"(r2), "=r"(r3) : "r"(addr))

// =========================================================================
// FP16 tensor-core GEMM (NT) — unchanged (proven R7/R8)
// =========================================================================
#define GBK    32
#define GLDH   40
#define ABUFH  (128 * GLDH)
#define BBUFH  (256 * GLDH)
#define GT_SMEM_BYTES ((2 * ABUFH + 2 * BBUFH) * 2)   // 61440

template <bool HAS_BIAS>
__global__ __launch_bounds__(256, 1)
void gemm_f16_nt(const float* __restrict__ A,
                 const float* __restrict__ B,
                 const float* __restrict__ bias,
                 float* __restrict__ C,
                 int M, int N, int K)
{
    extern __shared__ __align__(16) __half gsm[];
    __half* As = gsm;
    __half* Bs = gsm + 2 * ABUFH;

    const int tid  = threadIdx.x;
    const int lane = tid & 31;
    const int warp = tid >> 5;
    const int warpM = (warp & 1) * 64;
    const int warpN = (warp >> 1) * 64;
    const int rowBase = blockIdx.y * 128;
    const int colBase = blockIdx.x * 256;

    const int r  = tid >> 3;
    const int kq = tid & 7;
    const float* Ag = A + (size_t)(rowBase + r) * K + kq * 4;
    const float* Bg = B + (size_t)(colBase + r) * K + kq * 4;

    float4 ra[4], rb[8];

    float acc[4][8][4];
#pragma unroll
    for (int mi = 0; mi < 4; mi++)
#pragma unroll
        for (int ni = 0; ni < 8; ni++)
#pragma unroll
            for (int c = 0; c < 4; c++) acc[mi][ni][c] = 0.f;

    const uint32_t aOff = (uint32_t)((warpM + (lane & 7) + ((lane >> 3) & 1) * 8) * (GLDH * 2))
                        + (uint32_t)(lane >> 4) * 16;
    const uint32_t bOff = (uint32_t)((warpN + (lane & 7) + ((lane & 16) ? 8 : 0)) * (GLDH * 2))
                        + (uint32_t)((lane >> 3) & 1) * 16;
    const uint32_t asBase = s2u(As);
    const uint32_t bsBase = s2u(Bs);

#define G_LOAD(it)  {                                                \
        const float* ap = Ag + (it) * GBK;                           \
        const float* bp = Bg + (it) * GBK;                           \
        ra[0] = *(const float4*)(ap);                                \
        ra[1] = *(const float4*)(ap + (size_t)32 * K);               \
        ra[2] = *(const float4*)(ap + (size_t)64 * K);               \
        ra[3] = *(const float4*)(ap + (size_t)96 * K);               \
        rb[0] = *(const float4*)(bp);                                \
        rb[1] = *(const float4*)(bp + (size_t)32 * K);               \
        rb[2] = *(const float4*)(bp + (size_t)64 * K);               \
        rb[3] = *(const float4*)(bp + (size_t)96 * K);               \
        rb[4] = *(const float4*)(bp + (size_t)128 * K);              \
        rb[5] = *(const float4*)(bp + (size_t)160 * K);              \
        rb[6] = *(const float4*)(bp + (size_t)192 * K);              \
        rb[7] = *(const float4*)(bp + (size_t)224 * K);              \
    }
#define G_STS(buf)  {                                                           \
        _Pragma("unroll")                                                       \
        for (int i = 0; i < 4; i++)                                             \
            *(uint2*)&As[(buf) * ABUFH + (r + 32 * i) * GLDH + kq * 4] = f4_to_h4(ra[i]); \
        _Pragma("unroll")                                                       \
        for (int i = 0; i < 8; i++)                                             \
            *(uint2*)&Bs[(buf) * BBUFH + (r + 32 * i) * GLDH + kq * 4] = f4_to_h4(rb[i]); \
    }

    G_LOAD(0); G_STS(0); __syncthreads();

    const int NIT = K / GBK;
    for (int it = 0; it < NIT; ++it) {
        const int buf = it & 1;
        if (it + 1 < NIT) G_LOAD(it + 1);

        const uint32_t aB = asBase + (uint32_t)buf * (ABUFH * 2);
        const uint32_t bB = bsBase + (uint32_t)buf * (BBUFH * 2);

#pragma unroll
        for (int kk = 0; kk < 2; kk++) {
            uint32_t a[4][4], bf[8][2];
#pragma unroll
            for (int mi = 0; mi < 4; mi++) {
                uint32_t addr = aB + aOff + (uint32_t)(mi * 16 * GLDH * 2) + (uint32_t)(kk * 32);
                LDSM_X4(a[mi][0], a[mi][1], a[mi][2], a[mi][3], addr);
            }
#pragma unroll
            for (int p = 0; p < 4; p++) {
                uint32_t addr = bB + bOff + (uint32_t)(p * 16 * GLDH * 2) + (uint32_t)(kk * 32);
                uint32_t r0, r1, r2, r3;
                LDSM_X4(r0, r1, r2, r3, addr);
                bf[2 * p][0] = r0; bf[2 * p][1] = r1;
                bf[2 * p + 1][0] = r2; bf[2 * p + 1][1] = r3;
            }
#pragma unroll
            for (int mi = 0; mi < 4; mi++)
#pragma unroll
                for (int ni = 0; ni < 8; ni++)
                    MMA_F16(acc[mi][ni], a[mi][0], a[mi][1], a[mi][2], a[mi][3],
                            bf[ni][0], bf[ni][1]);
        }
        if (it + 1 < NIT) G_STS(buf ^ 1);
        __syncthreads();
    }

    const int g  = lane >> 2;
    const int cq = (lane & 3) * 2;
#pragma unroll
    for (int mi = 0; mi < 4; mi++) {
        const int row0 = rowBase + warpM + mi * 16 + g;
#pragma unroll
        for (int ni = 0; ni < 8; ni++) {
            const int col = colBase + warpN + ni * 8 + cq;
            float b0 = 0.f, b1 = 0.f;
            if (HAS_BIAS) { b0 = bias[col]; b1 = bias[col + 1]; }
            *(float2*)&C[(size_t)row0 * N + col] =
                make_float2(acc[mi][ni][0] + b0, acc[mi][ni][1] + b1);
            *(float2*)&C[(size_t)(row0 + 8) * N + col] =
                make_float2(acc[mi][ni][2] + b0, acc[mi][ni][3] + b1);
        }
    }
#undef G_LOAD
#undef G_STS
}

// =========================================================================
// CPB MLP table + bias gather (tiny, unchanged)
// =========================================================================
__global__ __launch_bounds__(512)
void cpb_tbl_kernel(const float* __restrict__ rel_table,
                    const float* __restrict__ w1,
                    const float* __restrict__ b1,
                    const float* __restrict__ w2,
                    float* __restrict__ tbl)
{
    __shared__ float hid[CPBH];
    int p = blockIdx.x;
    float t0 = rel_table[2 * p], t1 = rel_table[2 * p + 1];
    int j = threadIdx.x;
    hid[j] = fmaxf(t0 * w1[2 * j] + t1 * w1[2 * j + 1] + b1[j], 0.f);
    __syncthreads();

    int warp = j >> 5, lane = j & 31;
    const float* w2h = w2 + warp * CPBH;
    float s = 0.f;
#pragma unroll
    for (int q = lane; q < CPBH; q += 32) s += hid[q] * w2h[q];
#pragma unroll
    for (int o = 16; o > 0; o >>= 1) s += __shfl_xor_sync(0xffffffffu, s, o);
    if (lane == 0) tbl[p * HEADS + warp] = s;
}

__global__ void bias_gather_kernel(const float* __restrict__ tbl,
                                   const int* __restrict__ rel_index,
                                   float* __restrict__ bias)
{
    int t = blockIdx.x * blockDim.x + threadIdx.x;
    const int TOT = HEADS * NTOK * NTOK;
    if (t >= TOT) return;
    int h  = t / (NTOK * NTOK);
    int ij = t % (NTOK * NTOK);
    float x = tbl[rel_index[ij] * HEADS + h];
    bias[(size_t)h * NTOK * NTOK + ij] = 16.f / (1.f + __expf(-x));
}

// =========================================================================
// Window attention v4: QK^T split-FP16 (3 MMA terms), PV plain FP16
// (P_hi, V_hi only — error ~3.4e-4, inside budget). 18 warps / CTA.
// =========================================================================
#define KSTR_H 40                            // halves per K row (32 + 8 pad)
#define VSTR_H 152                           // halves per V^T row (144 + 8 pad)
#define PVSTR  18

#define AK_KHI 0
#define AK_KLO (AK_KHI + NTOK * KSTR_H * 2)          // 11520
#define AK_VHI (AK_KLO + NTOK * KSTR_H * 2)          // 23040
#define AK_PVB (AK_VHI + DHEAD * VSTR_H * 2)         // 32768
#define AK_SUM (AK_PVB + 9 * 32 * PVSTR * 4)         // 53504
#define ATTN_SMEM_BYTES (AK_SUM + 9 * 2 * 32 * 4)    // 55808

__global__ __launch_bounds__(576, 1)
void attn_tc4_kernel(const float* __restrict__ qkv,
                     const float* __restrict__ bias,
                     const float* __restrict__ mask,
                     const float* __restrict__ logit_scale,
                     float* __restrict__ out)
{
    extern __shared__ __align__(16) char dsm[];

    const int h = blockIdx.x;
    const int b = blockIdx.y;
    const int w = b & (NW - 1);

    const int tid  = threadIdx.x;
    const int lane = tid & 31;
    const int warp = tid >> 5;           // 0..17
    const int pair = warp % 9;
    const int half = warp / 9;           // 0: cols 0..63, 1: 64..143
    const int ng   = half ? 5 : 4;
    const int hbase = half ? 64 : 0;
    const int g  = lane >> 2;
    const int t  = lane & 3;
    const int R0 = pair * 16;

    const float scale = __expf(fminf(logit_scale[h], 4.60517018598809f));
    const float* base = qkv + (size_t)b * NTOK * QKVC + h * DHEAD;

    __half* knHi = (__half*)(dsm + AK_KHI);
    __half* knLo = (__half*)(dsm + AK_KLO);
    __half* vtHi = (__half*)(dsm + AK_VHI);
    float*  pvb  = (float*)(dsm + AK_PVB);
    float*  sumb = (float*)(dsm + AK_SUM);
    const uint32_t knHiB = s2u(knHi);
    const uint32_t knLoB = s2u(knLo);
    const uint32_t vtHiB = s2u(vtHi);

    // ---------- load K (normalized, hi/lo fp16) and V^T (hi fp16) ----
#pragma unroll
    for (int i = 0; i < 8; i++) {
        int j = warp * 8 + i;
        float kv = base[(size_t)j * QKVC + CDIM + lane];
        float s = kv * kv;
#pragma unroll
        for (int o = 16; o > 0; o >>= 1) s += __shfl_xor_sync(0xffffffffu, s, o);
        kv *= rsqrtf(s);
        __half khi = __float2half_rn(kv);
        knHi[j * KSTR_H + lane] = khi;
        knLo[j * KSTR_H + lane] = __float2half_rn(kv - __half2float(khi));

        float vv = base[(size_t)j * QKVC + 2 * CDIM + lane];
        vtHi[lane * VSTR_H + j] = __float2half_rn(vv);
    }

    // ---------- Q fragments (normalized + scaled, split fp16) ----------
    uint32_t qah[2][4], qal[2][4];
    {
        const float* q0 = base + (size_t)(R0 + g) * QKVC;
        const float* q1 = base + (size_t)(R0 + g + 8) * QKVC;
        float e0[2][4], e1[2][4];
#pragma unroll
        for (int kc = 0; kc < 2; kc++) {
            e0[kc][0] = q0[16 * kc + 2 * t];     e0[kc][1] = q0[16 * kc + 2 * t + 1];
            e0[kc][2] = q0[16 * kc + 8 + 2 * t]; e0[kc][3] = q0[16 * kc + 9 + 2 * t];
            e1[kc][0] = q1[16 * kc + 2 * t];     e1[kc][1] = q1[16 * kc + 2 * t + 1];
            e1[kc][2] = q1[16 * kc + 8 + 2 * t]; e1[kc][3] = q1[16 * kc + 9 + 2 * t];
        }
        float s0 = 0.f, s1 = 0.f;
#pragma unroll
        for (int kc = 0; kc < 2; kc++)
#pragma unroll
            for (int i = 0; i < 4; i++) {
                s0 += e0[kc][i] * e0[kc][i];
                s1 += e1[kc][i] * e1[kc][i];
            }
        s0 += __shfl_xor_sync(0xffffffffu, s0, 1);
        s0 += __shfl_xor_sync(0xffffffffu, s0, 2);
        s1 += __shfl_xor_sync(0xffffffffu, s1, 1);
        s1 += __shfl_xor_sync(0xffffffffu, s1, 2);
        float r0 = rsqrtf(s0) * scale, r1 = rsqrtf(s1) * scale;
#pragma unroll
        for (int kc = 0; kc < 2; kc++) {
            split_pack(e0[kc][0] * r0, e0[kc][1] * r0, qah[kc][0], qal[kc][0]);
            split_pack(e1[kc][0] * r1, e1[kc][1] * r1, qah[kc][1], qal[kc][1]);
            split_pack(e0[kc][2] * r0, e0[kc][3] * r0, qah[kc][2], qal[kc][2]);
            split_pack(e1[kc][2] * r1, e1[kc][3] * r1, qah[kc][3], qal[kc][3]);
        }
    }
    __syncthreads();

    // ---------- QK^T (split fp16, 3 terms): acc[2*ng][4] ----------
    float acc[10][4];
#pragma unroll
    for (int nt = 0; nt < 10; nt++)
#pragma unroll
        for (int c = 0; c < 4; c++) acc[nt][c] = 0.f;

    const uint32_t ldsmRow = (uint32_t)((lane & 7) + ((lane & 16) ? 8 : 0));
    const uint32_t ldsmCol = (uint32_t)((lane >> 3) & 1) * 16;

#pragma unroll
    for (int kc = 0; kc < 2; kc++) {
#pragma unroll
        for (int gI = 0; gI < 5; gI++) {
            if (gI < ng) {
                uint32_t off = (uint32_t)(hbase + gI * 16 + ldsmRow) * (KSTR_H * 2)
                             + ldsmCol + (uint32_t)kc * 32;
                uint32_t bh0, bh1, bh2, bh3, bl0, bl1, bl2, bl3;
                LDSM_X4(bh0, bh1, bh2, bh3, knHiB + off);
                LDSM_X4(bl0, bl1, bl2, bl3, knLoB + off);
                MMA_F16(acc[2 * gI],     qah[kc][0], qah[kc][1], qah[kc][2], qah[kc][3], bh0, bh1);
                MMA_F16(acc[2 * gI],     qah[kc][0], qah[kc][1], qah[kc][2], qah[kc][3], bl0, bl1);
                MMA_F16(acc[2 * gI],     qal[kc][0], qal[kc][1], qal[kc][2], qal[kc][3], bh0, bh1);
                MMA_F16(acc[2 * gI + 1], qah[kc][0], qah[kc][1], qah[kc][2], qah[kc][3], bh2, bh3);
                MMA_F16(acc[2 * gI + 1], qah[kc][0], qah[kc][1], qah[kc][2], qah[kc][3], bl2, bl3);
                MMA_F16(acc[2 * gI + 1], qal[kc][0], qal[kc][1], qal[kc][2], qal[kc][3], bh2, bh3);
            }
        }
    }

    // ---------- bias + mask, local max, exp, local sums ----------
    float mx0 = -1e30f, mx1 = -1e30f, sm0 = 0.f, sm1 = 0.f;
    {
        const float* biasR0 = bias + (size_t)h * NTOK * NTOK + (size_t)(R0 + g) * NTOK + hbase + 2 * t;
        const float* biasR1 = biasR0 + 8 * NTOK;
        const float* maskR0 = mask + (size_t)w * NTOK * NTOK + (size_t)(R0 + g) * NTOK + hbase + 2 * t;
        const float* maskR1 = maskR0 + 8 * NTOK;
#pragma unroll
        for (int nt = 0; nt < 10; nt++) {
            if (nt < 2 * ng) {
                float2 bb0 = *(const float2*)(biasR0 + 8 * nt);
                float2 mm0 = *(const float2*)(maskR0 + 8 * nt);
                float2 bb1 = *(const float2*)(biasR1 + 8 * nt);
                float2 mm1 = *(const float2*)(maskR1 + 8 * nt);
                acc[nt][0] += bb0.x + mm0.x;
                acc[nt][1] += bb0.y + mm0.y;
                acc[nt][2] += bb1.x + mm1.x;
                acc[nt][3] += bb1.y + mm1.y;
                mx0 = fmaxf(mx0, fmaxf(acc[nt][0], acc[nt][1]));
                mx1 = fmaxf(mx1, fmaxf(acc[nt][2], acc[nt][3]));
            }
        }
        mx0 = fmaxf(mx0, __shfl_xor_sync(0xffffffffu, mx0, 1));
        mx0 = fmaxf(mx0, __shfl_xor_sync(0xffffffffu, mx0, 2));
        mx1 = fmaxf(mx1, __shfl_xor_sync(0xffffffffu, mx1, 1));
        mx1 = fmaxf(mx1, __shfl_xor_sync(0xffffffffu, mx1, 2));
#pragma unroll
        for (int nt = 0; nt < 10; nt++) {
            if (nt < 2 * ng) {
                acc[nt][0] = __expf(acc[nt][0] - mx0);
                acc[nt][1] = __expf(acc[nt][1] - mx0);
                acc[nt][2] = __expf(acc[nt][2] - mx1);
                acc[nt][3] = __expf(acc[nt][3] - mx1);
                sm0 += acc[nt][0] + acc[nt][1];
                sm1 += acc[nt][2] + acc[nt][3];
            }
        }
        sm0 += __shfl_xor_sync(0xffffffffu, sm0, 1);
        sm0 += __shfl_xor_sync(0xffffffffu, sm0, 2);
        sm1 += __shfl_xor_sync(0xffffffffu, sm1, 1);
        sm1 += __shfl_xor_sync(0xffffffffu, sm1, 2);
        if (t == 0) {
            float* sb = sumb + (pair * 2 + half) * 32;
            sb[g]          = sm0;
            sb[g + 8]      = sm1;
            sb[16 + g]     = mx0;
            sb[16 + g + 8] = mx1;
        }
    }

    // ---------- PV (plain fp16: P_hi x V_hi) ----------
    float pv[4][4];
#pragma unroll
    for (int nt = 0; nt < 4; nt++)
#pragma unroll
        for (int c = 0; c < 4; c++) pv[nt][c] = 0.f;

#pragma unroll
    for (int kc2 = 0; kc2 < 5; kc2++) {
        if (kc2 < ng) {
            uint32_t ph[4];
            ph[0] = pack_h2(acc[2 * kc2][0],     acc[2 * kc2][1]);
            ph[1] = pack_h2(acc[2 * kc2][2],     acc[2 * kc2][3]);
            ph[2] = pack_h2(acc[2 * kc2 + 1][0], acc[2 * kc2 + 1][1]);
            ph[3] = pack_h2(acc[2 * kc2 + 1][2], acc[2 * kc2 + 1][3]);
            const uint32_t gk = (uint32_t)((hbase >> 4) + kc2);
#pragma unroll
            for (int p = 0; p < 2; p++) {
                uint32_t off = (uint32_t)(p * 16 + ldsmRow) * (VSTR_H * 2)
                             + ldsmCol + gk * 32;
                uint32_t bh0, bh1, bh2, bh3;
                LDSM_X4(bh0, bh1, bh2, bh3, vtHiB + off);
                MMA_F16(pv[2 * p],     ph[0], ph[1], ph[2], ph[3], bh0, bh1);
                MMA_F16(pv[2 * p + 1], ph[0], ph[1], ph[2], ph[3], bh2, bh3);
            }
        }
    }

    // ---------- pairwise combine (max-corrected) + epilogue ----------
    if (half == 1) {
        float* pb = pvb + (pair * 32 + lane) * PVSTR;
#pragma unroll
        for (int nt = 0; nt < 4; nt++) {
            *(float2*)(pb + nt * 4)     = make_float2(pv[nt][0], pv[nt][1]);
            *(float2*)(pb + nt * 4 + 2) = make_float2(pv[nt][2], pv[nt][3]);
        }
    }
    __syncthreads();
    if (half == 0) {
        const float* sbO = sumb + (pair * 2 + 1) * 32;
        const float smO0 = sbO[g],      mxO0 = sbO[16 + g];
        const float smO1 = sbO[g + 8],  mxO1 = sbO[16 + g + 8];
        const float M0 = fmaxf(mx0, mxO0);
        const float M1 = fmaxf(mx1, mxO1);
        const float fl0 = __expf(mx0 - M0), fo0 = __expf(mxO0 - M0);
        const float fl1 = __expf(mx1 - M1), fo1 = __expf(mxO1 - M1);
        const float inv0 = 1.f / (sm0 * fl0 + smO0 * fo0);
        const float inv1 = 1.f / (sm1 * fl1 + smO1 * fo1);
        const float* pb = pvb + (pair * 32 + lane) * PVSTR;
        float* o0 = out + ((size_t)b * NTOK + R0 + g) * CDIM + h * DHEAD + 2 * t;
        float* o1 = o0 + (size_t)8 * CDIM;
#pragma unroll
        for (int nt = 0; nt < 4; nt++) {
            float2 q0 = *(const float2*)(pb + nt * 4);
            float2 q1 = *(const float2*)(pb + nt * 4 + 2);
            *(float2*)(o0 + 8 * nt) = make_float2((pv[nt][0] * fl0 + q0.x * fo0) * inv0,
                                                  (pv[nt][1] * fl0 + q0.y * fo0) * inv0);
            *(float2*)(o1 + 8 * nt) = make_float2((pv[nt][2] * fl1 + q1.x * fo1) * inv1,
                                                  (pv[nt][3] * fl1 + q1.y * fo1) * inv1);
        }
    }
}

// =========================================================================
// launch
// =========================================================================
extern "C" void kernel_launch(void* const* d_in, const int* in_sizes, int n_in,
                              void* d_out, int out_size)
{
    const float* x           = (const float*)d_in[0];
    const float* mask        = (const float*)d_in[1];
    const float* qkv_w       = (const float*)d_in[2];
    const float* logit_scale = (const float*)d_in[3];
    const float* cpb_w1      = (const float*)d_in[4];
    const float* cpb_b1      = (const float*)d_in[5];
    const float* cpb_w2      = (const float*)d_in[6];
    const float* proj_w      = (const float*)d_in[7];
    const float* proj_b      = (const float*)d_in[8];
    const float* rel_table   = (const float*)d_in[9];
    const int*   rel_index   = (const int*)d_in[10];
    float* out = (float*)d_out;

    float *qkv, *att, *tbl, *bias;
    cudaGetSymbolAddress((void**)&qkv,  g_qkv);
    cudaGetSymbolAddress((void**)&att,  g_att);
    cudaGetSymbolAddress((void**)&tbl,  g_tbl);
    cudaGetSymbolAddress((void**)&bias, g_bias);

    cudaFuncSetAttribute(gemm_f16_nt<false>,
                         cudaFuncAttributeMaxDynamicSharedMemorySize, GT_SMEM_BYTES);
    cudaFuncSetAttribute(gemm_f16_nt<true>,
                         cudaFuncAttributeMaxDynamicSharedMemorySize, GT_SMEM_BYTES);
    cudaFuncSetAttribute(attn_tc4_kernel,
                         cudaFuncAttributeMaxDynamicSharedMemorySize, ATTN_SMEM_BYTES);

    // 1) QKV projection (fp16 m16n8k16)
    {
        dim3 grid(QKVC / 256, MROWS / 128);
        gemm_f16_nt<false><<<grid, 256, GT_SMEM_BYTES>>>(x, qkv_w, nullptr, qkv,
                                                         MROWS, QKVC, CDIM);
    }

    // 2) relative position bias table + gather
    cpb_tbl_kernel<<<NPOS, CPBH>>>(rel_table, cpb_w1, cpb_b1, cpb_w2, tbl);
    {
        int tot = HEADS * NTOK * NTOK;
        bias_gather_kernel<<<(tot + 255) / 256, 256>>>(tbl, rel_index, bias);
    }

    // 3) attention v4 (split-fp16 QK, plain-fp16 PV)
    {
        dim3 grid(HEADS, BWIN);
        attn_tc4_kernel<<<grid, 576, ATTN_SMEM_BYTES>>>(qkv, bias, mask, logit_scale, att);
    }

    // 4) output projection (fp16 m16n8k16)
    {
        dim3 grid(CDIM / 256, MROWS / 128);
        gemm_f16_nt<true><<<grid, 256, GT_SMEM_BYTES>>>(att, proj_w, proj_b, out,
                                                        MROWS, CDIM, CDIM);
    }
}

// round 10
// speedup vs baseline: 4.6463x; 1.0010x over previous
#include <cuda_runtime.h>
#include <cuda_bf16.h>
#include <cuda_fp16.h>
#include <math.h>
#include <stdint.h>

// ---------------- problem constants ----------------
#define BWIN   512
#define NTOK   144
#define CDIM   512
#define HEADS  16
#define DHEAD  32
#define NW     64
#define MROWS  (BWIN * NTOK)        // 73728
#define QKVC   (3 * CDIM)           // 1536
#define NPOS   (23 * 23)
#define CPBH   512

// ---------------- scratch ----------------
__device__ float g_qkv [(size_t)MROWS * QKVC];
__device__ float g_att [(size_t)MROWS * CDIM];
__device__ float g_tbl [NPOS * HEADS];
__device__ float g_bias[(size_t)HEADS * NTOK * NTOK];

__device__ __forceinline__ uint32_t s2u(const void* p) {
    return (uint32_t)__cvta_generic_to_shared(p);
}
__device__ __forceinline__ uint2 f4_to_h4(float4 v) {
    __half2 h0 = __float22half2_rn(make_float2(v.x, v.y));
    __half2 h1 = __float22half2_rn(make_float2(v.z, v.w));
    uint2 u;
    u.x = *(uint32_t*)&h0;
    u.y = *(uint32_t*)&h1;
    return u;
}
__device__ __forceinline__ void split_pack(float x, float y, uint32_t& hi, uint32_t& lo) {
    __half hx = __float2half_rn(x), hy = __float2half_rn(y);
    __half2 h = __halves2half2(hx, hy);
    hi = *(uint32_t*)&h;
    __half2 l = __floats2half2_rn(x - __half2float(hx), y - __half2float(hy));
    lo = *(uint32_t*)&l;
}
__device__ __forceinline__ uint32_t pack_h2(float x, float y) {
    __half2 h = __floats2half2_rn(x, y);
    return *(uint32_t*)&h;
}

#define MMA_F16(d, a0,a1,a2,a3, b0,b1)                                         \
    asm volatile("mma.sync.aligned.m16n8k16.row.col.f32.f16.f16.f32 "          \
                 "{%0,%1,%2,%3},{%4,%5,%6,%7},{%8,%9},{%0,%1,%2,%3};"          \
                 : "+f"(d[0]), "+f"(d[1]), "+f"(d[2]), "+f"(d[3])              \
                 : "r"(a0), "r"(a1), "r"(a2), "r"(a3), "r"(b0), "r"(b1))

#define LDSM_X4(r0,r1,r2,r3, addr)                                             \
    asm volatile("ldmatrix.sync.aligned.m8n8.x4.shared.b16 {%0,%1,%2,%3}, [%4];" \
                 : "=r"(r0), "=r"(r1), "=r"(r2), "=r"(r3) : "r"(addr))

// =========================================================================
// FP16 tensor-core GEMM v3 (NT): CTA 128x256, 512 threads / 16 warps,
// warp tile 32x64 (acc = 64 regs) — 4 warps/SMSP to hide mma+mem latency.
// Same smem geometry / ldmatrix formulas as the proven 8-warp version.
// =========================================================================
#define GBK    32
#define GLDH   40
#define ABUFH  (128 * GLDH)
#define BBUFH  (256 * GLDH)
#define GT_SMEM_BYTES ((2 * ABUFH + 2 * BBUFH) * 2)   // 61440

template <bool HAS_BIAS>
__global__ __launch_bounds__(512, 1)
void gemm_f16_nt(const float* __restrict__ A,
                 const float* __restrict__ B,
                 const float* __restrict__ bias,
                 float* __restrict__ C,
                 int M, int N, int K)
{
    extern __shared__ __align__(16) __half gsm[];
    __half* As = gsm;
    __half* Bs = gsm + 2 * ABUFH;

    const int tid  = threadIdx.x;
    const int lane = tid & 31;
    const int warp = tid >> 5;               // 0..15
    const int warpM = (warp & 3) * 32;       // 4 M tiles of 32
    const int warpN = (warp >> 2) * 64;      // 4 N tiles of 64
    const int rowBase = blockIdx.y * 128;
    const int colBase = blockIdx.x * 256;

    // global staging: r = tid>>3 (0..63), kq = float4 slot (0..7)
    const int r  = tid >> 3;
    const int kq = tid & 7;
    const float* Ag = A + (size_t)(rowBase + r) * K + kq * 4;
    const float* Bg = B + (size_t)(colBase + r) * K + kq * 4;

    float4 ra[2], rb[4];

    float acc[2][8][4];
#pragma unroll
    for (int mi = 0; mi < 2; mi++)
#pragma unroll
        for (int ni = 0; ni < 8; ni++)
#pragma unroll
            for (int c = 0; c < 4; c++) acc[mi][ni][c] = 0.f;

    const uint32_t aOff = (uint32_t)((warpM + (lane & 7) + ((lane >> 3) & 1) * 8) * (GLDH * 2))
                        + (uint32_t)(lane >> 4) * 16;
    const uint32_t bOff = (uint32_t)((warpN + (lane & 7) + ((lane & 16) ? 8 : 0)) * (GLDH * 2))
                        + (uint32_t)((lane >> 3) & 1) * 16;
    const uint32_t asBase = s2u(As);
    const uint32_t bsBase = s2u(Bs);

#define G_LOAD(it)  {                                                \
        const float* ap = Ag + (it) * GBK;                           \
        const float* bp = Bg + (it) * GBK;                           \
        ra[0] = *(const float4*)(ap);                                \
        ra[1] = *(const float4*)(ap + (size_t)64 * K);               \
        rb[0] = *(const float4*)(bp);                                \
        rb[1] = *(const float4*)(bp + (size_t)64 * K);               \
        rb[2] = *(const float4*)(bp + (size_t)128 * K);              \
        rb[3] = *(const float4*)(bp + (size_t)192 * K);              \
    }
#define G_STS(buf)  {                                                           \
        _Pragma("unroll")                                                       \
        for (int i = 0; i < 2; i++)                                             \
            *(uint2*)&As[(buf) * ABUFH + (r + 64 * i) * GLDH + kq * 4] = f4_to_h4(ra[i]); \
        _Pragma("unroll")                                                       \
        for (int i = 0; i < 4; i++)                                             \
            *(uint2*)&Bs[(buf) * BBUFH + (r + 64 * i) * GLDH + kq * 4] = f4_to_h4(rb[i]); \
    }

    G_LOAD(0); G_STS(0); __syncthreads();

    const int NIT = K / GBK;
    for (int it = 0; it < NIT; ++it) {
        const int buf = it & 1;
        if (it + 1 < NIT) G_LOAD(it + 1);

        const uint32_t aB = asBase + (uint32_t)buf * (ABUFH * 2);
        const uint32_t bB = bsBase + (uint32_t)buf * (BBUFH * 2);

#pragma unroll
        for (int kk = 0; kk < 2; kk++) {
            uint32_t a[2][4], bf[8][2];
#pragma unroll
            for (int mi = 0; mi < 2; mi++) {
                uint32_t addr = aB + aOff + (uint32_t)(mi * 16 * GLDH * 2) + (uint32_t)(kk * 32);
                LDSM_X4(a[mi][0], a[mi][1], a[mi][2], a[mi][3], addr);
            }
#pragma unroll
            for (int p = 0; p < 4; p++) {
                uint32_t addr = bB + bOff + (uint32_t)(p * 16 * GLDH * 2) + (uint32_t)(kk * 32);
                uint32_t r0, r1, r2, r3;
                LDSM_X4(r0, r1, r2, r3, addr);
                bf[2 * p][0] = r0; bf[2 * p][1] = r1;
                bf[2 * p + 1][0] = r2; bf[2 * p + 1][1] = r3;
            }
#pragma unroll
            for (int mi = 0; mi < 2; mi++)
#pragma unroll
                for (int ni = 0; ni < 8; ni++)
                    MMA_F16(acc[mi][ni], a[mi][0], a[mi][1], a[mi][2], a[mi][3],
                            bf[ni][0], bf[ni][1]);
        }
        if (it + 1 < NIT) G_STS(buf ^ 1);
        __syncthreads();
    }

    const int g  = lane >> 2;
    const int cq = (lane & 3) * 2;
#pragma unroll
    for (int mi = 0; mi < 2; mi++) {
        const int row0 = rowBase + warpM + mi * 16 + g;
#pragma unroll
        for (int ni = 0; ni < 8; ni++) {
            const int col = colBase + warpN + ni * 8 + cq;
            float b0 = 0.f, b1 = 0.f;
            if (HAS_BIAS) { b0 = bias[col]; b1 = bias[col + 1]; }
            *(float2*)&C[(size_t)row0 * N + col] =
                make_float2(acc[mi][ni][0] + b0, acc[mi][ni][1] + b1);
            *(float2*)&C[(size_t)(row0 + 8) * N + col] =
                make_float2(acc[mi][ni][2] + b0, acc[mi][ni][3] + b1);
        }
    }
#undef G_LOAD
#undef G_STS
}

// =========================================================================
// CPB MLP table + bias gather (tiny, unchanged)
// =========================================================================
__global__ __launch_bounds__(512)
void cpb_tbl_kernel(const float* __restrict__ rel_table,
                    const float* __restrict__ w1,
                    const float* __restrict__ b1,
                    const float* __restrict__ w2,
                    float* __restrict__ tbl)
{
    __shared__ float hid[CPBH];
    int p = blockIdx.x;
    float t0 = rel_table[2 * p], t1 = rel_table[2 * p + 1];
    int j = threadIdx.x;
    hid[j] = fmaxf(t0 * w1[2 * j] + t1 * w1[2 * j + 1] + b1[j], 0.f);
    __syncthreads();

    int warp = j >> 5, lane = j & 31;
    const float* w2h = w2 + warp * CPBH;
    float s = 0.f;
#pragma unroll
    for (int q = lane; q < CPBH; q += 32) s += hid[q] * w2h[q];
#pragma unroll
    for (int o = 16; o > 0; o >>= 1) s += __shfl_xor_sync(0xffffffffu, s, o);
    if (lane == 0) tbl[p * HEADS + warp] = s;
}

__global__ void bias_gather_kernel(const float* __restrict__ tbl,
                                   const int* __restrict__ rel_index,
                                   float* __restrict__ bias)
{
    int t = blockIdx.x * blockDim.x + threadIdx.x;
    const int TOT = HEADS * NTOK * NTOK;
    if (t >= TOT) return;
    int h  = t / (NTOK * NTOK);
    int ij = t % (NTOK * NTOK);
    float x = tbl[rel_index[ij] * HEADS + h];
    bias[(size_t)h * NTOK * NTOK + ij] = 16.f / (1.f + __expf(-x));
}

// =========================================================================
// Window attention v4 — unchanged from R9 (passing at 486 us)
// =========================================================================
#define KSTR_H 40
#define VSTR_H 152
#define PVSTR  18

#define AK_KHI 0
#define AK_KLO (AK_KHI + NTOK * KSTR_H * 2)
#define AK_VHI (AK_KLO + NTOK * KSTR_H * 2)
#define AK_PVB (AK_VHI + DHEAD * VSTR_H * 2)
#define AK_SUM (AK_PVB + 9 * 32 * PVSTR * 4)
#define ATTN_SMEM_BYTES (AK_SUM + 9 * 2 * 32 * 4)

__global__ __launch_bounds__(576, 1)
void attn_tc4_kernel(const float* __restrict__ qkv,
                     const float* __restrict__ bias,
                     const float* __restrict__ mask,
                     const float* __restrict__ logit_scale,
                     float* __restrict__ out)
{
    extern __shared__ __align__(16) char dsm[];

    const int h = blockIdx.x;
    const int b = blockIdx.y;
    const int w = b & (NW - 1);

    const int tid  = threadIdx.x;
    const int lane = tid & 31;
    const int warp = tid >> 5;
    const int pair = warp % 9;
    const int half = warp / 9;
    const int ng   = half ? 5 : 4;
    const int hbase = half ? 64 : 0;
    const int g  = lane >> 2;
    const int t  = lane & 3;
    const int R0 = pair * 16;

    const float scale = __expf(fminf(logit_scale[h], 4.60517018598809f));
    const float* base = qkv + (size_t)b * NTOK * QKVC + h * DHEAD;

    __half* knHi = (__half*)(dsm + AK_KHI);
    __half* knLo = (__half*)(dsm + AK_KLO);
    __half* vtHi = (__half*)(dsm + AK_VHI);
    float*  pvb  = (float*)(dsm + AK_PVB);
    float*  sumb = (float*)(dsm + AK_SUM);
    const uint32_t knHiB = s2u(knHi);
    const uint32_t knLoB = s2u(knLo);
    const uint32_t vtHiB = s2u(vtHi);

#pragma unroll
    for (int i = 0; i < 8; i++) {
        int j = warp * 8 + i;
        float kv = base[(size_t)j * QKVC + CDIM + lane];
        float s = kv * kv;
#pragma unroll
        for (int o = 16; o > 0; o >>= 1) s += __shfl_xor_sync(0xffffffffu, s, o);
        kv *= rsqrtf(s);
        __half khi = __float2half_rn(kv);
        knHi[j * KSTR_H + lane] = khi;
        knLo[j * KSTR_H + lane] = __float2half_rn(kv - __half2float(khi));

        float vv = base[(size_t)j * QKVC + 2 * CDIM + lane];
        vtHi[lane * VSTR_H + j] = __float2half_rn(vv);
    }

    uint32_t qah[2][4], qal[2][4];
    {
        const float* q0 = base + (size_t)(R0 + g) * QKVC;
        const float* q1 = base + (size_t)(R0 + g + 8) * QKVC;
        float e0[2][4], e1[2][4];
#pragma unroll
        for (int kc = 0; kc < 2; kc++) {
            e0[kc][0] = q0[16 * kc + 2 * t];     e0[kc][1] = q0[16 * kc + 2 * t + 1];
            e0[kc][2] = q0[16 * kc + 8 + 2 * t]; e0[kc][3] = q0[16 * kc + 9 + 2 * t];
            e1[kc][0] = q1[16 * kc + 2 * t];     e1[kc][1] = q1[16 * kc + 2 * t + 1];
            e1[kc][2] = q1[16 * kc + 8 + 2 * t]; e1[kc][3] = q1[16 * kc + 9 + 2 * t];
        }
        float s0 = 0.f, s1 = 0.f;
#pragma unroll
        for (int kc = 0; kc < 2; kc++)
#pragma unroll
            for (int i = 0; i < 4; i++) {
                s0 += e0[kc][i] * e0[kc][i];
                s1 += e1[kc][i] * e1[kc][i];
            }
        s0 += __shfl_xor_sync(0xffffffffu, s0, 1);
        s0 += __shfl_xor_sync(0xffffffffu, s0, 2);
        s1 += __shfl_xor_sync(0xffffffffu, s1, 1);
        s1 += __shfl_xor_sync(0xffffffffu, s1, 2);
        float r0 = rsqrtf(s0) * scale, r1 = rsqrtf(s1) * scale;
#pragma unroll
        for (int kc = 0; kc < 2; kc++) {
            split_pack(e0[kc][0] * r0, e0[kc][1] * r0, qah[kc][0], qal[kc][0]);
            split_pack(e1[kc][0] * r1, e1[kc][1] * r1, qah[kc][1], qal[kc][1]);
            split_pack(e0[kc][2] * r0, e0[kc][3] * r0, qah[kc][2], qal[kc][2]);
            split_pack(e1[kc][2] * r1, e1[kc][3] * r1, qah[kc][3], qal[kc][3]);
        }
    }
    __syncthreads();

    float acc[10][4];
#pragma unroll
    for (int nt = 0; nt < 10; nt++)
#pragma unroll
        for (int c = 0; c < 4; c++) acc[nt][c] = 0.f;

    const uint32_t ldsmRow = (uint32_t)((lane & 7) + ((lane & 16) ? 8 : 0));
    const uint32_t ldsmCol = (uint32_t)((lane >> 3) & 1) * 16;

#pragma unroll
    for (int kc = 0; kc < 2; kc++) {
#pragma unroll
        for (int gI = 0; gI < 5; gI++) {
            if (gI < ng) {
                uint32_t off = (uint32_t)(hbase + gI * 16 + ldsmRow) * (KSTR_H * 2)
                             + ldsmCol + (uint32_t)kc * 32;
                uint32_t bh0, bh1, bh2, bh3, bl0, bl1, bl2, bl3;
                LDSM_X4(bh0, bh1, bh2, bh3, knHiB + off);
                LDSM_X4(bl0, bl1, bl2, bl3, knLoB + off);
                MMA_F16(acc[2 * gI],     qah[kc][0], qah[kc][1], qah[kc][2], qah[kc][3], bh0, bh1);
                MMA_F16(acc[2 * gI],     qah[kc][0], qah[kc][1], qah[kc][2], qah[kc][3], bl0, bl1);
                MMA_F16(acc[2 * gI],     qal[kc][0], qal[kc][1], qal[kc][2], qal[kc][3], bh0, bh1);
                MMA_F16(acc[2 * gI + 1], qah[kc][0], qah[kc][1], qah[kc][2], qah[kc][3], bh2, bh3);
                MMA_F16(acc[2 * gI + 1], qah[kc][0], qah[kc][1], qah[kc][2], qah[kc][3], bl2, bl3);
                MMA_F16(acc[2 * gI + 1], qal[kc][0], qal[kc][1], qal[kc][2], qal[kc][3], bh2, bh3);
            }
        }
    }

    float mx0 = -1e30f, mx1 = -1e30f, sm0 = 0.f, sm1 = 0.f;
    {
        const float* biasR0 = bias + (size_t)h * NTOK * NTOK + (size_t)(R0 + g) * NTOK + hbase + 2 * t;
        const float* biasR1 = biasR0 + 8 * NTOK;
        const float* maskR0 = mask + (size_t)w * NTOK * NTOK + (size_t)(R0 + g) * NTOK + hbase + 2 * t;
        const float* maskR1 = maskR0 + 8 * NTOK;
#pragma unroll
        for (int nt = 0; nt < 10; nt++) {
            if (nt < 2 * ng) {
                float2 bb0 = *(const float2*)(biasR0 + 8 * nt);
                float2 mm0 = *(const float2*)(maskR0 + 8 * nt);
                float2 bb1 = *(const float2*)(biasR1 + 8 * nt);
                float2 mm1 = *(const float2*)(maskR1 + 8 * nt);
                acc[nt][0] += bb0.x + mm0.x;
                acc[nt][1] += bb0.y + mm0.y;
                acc[nt][2] += bb1.x + mm1.x;
                acc[nt][3] += bb1.y + mm1.y;
                mx0 = fmaxf(mx0, fmaxf(acc[nt][0], acc[nt][1]));
                mx1 = fmaxf(mx1, fmaxf(acc[nt][2], acc[nt][3]));
            }
        }
        mx0 = fmaxf(mx0, __shfl_xor_sync(0xffffffffu, mx0, 1));
        mx0 = fmaxf(mx0, __shfl_xor_sync(0xffffffffu, mx0, 2));
        mx1 = fmaxf(mx1, __shfl_xor_sync(0xffffffffu, mx1, 1));
        mx1 = fmaxf(mx1, __shfl_xor_sync(0xffffffffu, mx1, 2));
#pragma unroll
        for (int nt = 0; nt < 10; nt++) {
            if (nt < 2 * ng) {
                acc[nt][0] = __expf(acc[nt][0] - mx0);
                acc[nt][1] = __expf(acc[nt][1] - mx0);
                acc[nt][2] = __expf(acc[nt][2] - mx1);
                acc[nt][3] = __expf(acc[nt][3] - mx1);
                sm0 += acc[nt][0] + acc[nt][1];
                sm1 += acc[nt][2] + acc[nt][3];
            }
        }
        sm0 += __shfl_xor_sync(0xffffffffu, sm0, 1);
        sm0 += __shfl_xor_sync(0xffffffffu, sm0, 2);
        sm1 += __shfl_xor_sync(0xffffffffu, sm1, 1);
        sm1 += __shfl_xor_sync(0xffffffffu, sm1, 2);
        if (t == 0) {
            float* sb = sumb + (pair * 2 + half) * 32;
            sb[g]          = sm0;
            sb[g + 8]      = sm1;
            sb[16 + g]     = mx0;
            sb[16 + g + 8] = mx1;
        }
    }

    float pv[4][4];
#pragma unroll
    for (int nt = 0; nt < 4; nt++)
#pragma unroll
        for (int c = 0; c < 4; c++) pv[nt][c] = 0.f;

#pragma unroll
    for (int kc2 = 0; kc2 < 5; kc2++) {
        if (kc2 < ng) {
            uint32_t ph[4];
            ph[0] = pack_h2(acc[2 * kc2][0],     acc[2 * kc2][1]);
            ph[1] = pack_h2(acc[2 * kc2][2],     acc[2 * kc2][3]);
            ph[2] = pack_h2(acc[2 * kc2 + 1][0], acc[2 * kc2 + 1][1]);
            ph[3] = pack_h2(acc[2 * kc2 + 1][2], acc[2 * kc2 + 1][3]);
            const uint32_t gk = (uint32_t)((hbase >> 4) + kc2);
#pragma unroll
            for (int p = 0; p < 2; p++) {
                uint32_t off = (uint32_t)(p * 16 + ldsmRow) * (VSTR_H * 2)
                             + ldsmCol + gk * 32;
                uint32_t bh0, bh1, bh2, bh3;
                LDSM_X4(bh0, bh1, bh2, bh3, vtHiB + off);
                MMA_F16(pv[2 * p],     ph[0], ph[1], ph[2], ph[3], bh0, bh1);
                MMA_F16(pv[2 * p + 1], ph[0], ph[1], ph[2], ph[3], bh2, bh3);
            }
        }
    }

    if (half == 1) {
        float* pb = pvb + (pair * 32 + lane) * PVSTR;
#pragma unroll
        for (int nt = 0; nt < 4; nt++) {
            *(float2*)(pb + nt * 4)     = make_float2(pv[nt][0], pv[nt][1]);
            *(float2*)(pb + nt * 4 + 2) = make_float2(pv[nt][2], pv[nt][3]);
        }
    }
    __syncthreads();
    if (half == 0) {
        const float* sbO = sumb + (pair * 2 + 1) * 32;
        const float smO0 = sbO[g],      mxO0 = sbO[16 + g];
        const float smO1 = sbO[g + 8],  mxO1 = sbO[16 + g + 8];
        const float M0 = fmaxf(mx0, mxO0);
        const float M1 = fmaxf(mx1, mxO1);
        const float fl0 = __expf(mx0 - M0), fo0 = __expf(mxO0 - M0);
        const float fl1 = __expf(mx1 - M1), fo1 = __expf(mxO1 - M1);
        const float inv0 = 1.f / (sm0 * fl0 + smO0 * fo0);
        const float inv1 = 1.f / (sm1 * fl1 + smO1 * fo1);
        const float* pb = pvb + (pair * 32 + lane) * PVSTR;
        float* o0 = out + ((size_t)b * NTOK + R0 + g) * CDIM + h * DHEAD + 2 * t;
        float* o1 = o0 + (size_t)8 * CDIM;
#pragma unroll
        for (int nt = 0; nt < 4; nt++) {
            float2 q0 = *(const float2*)(pb + nt * 4);
            float2 q1 = *(const float2*)(pb + nt * 4 + 2);
            *(float2*)(o0 + 8 * nt) = make_float2((pv[nt][0] * fl0 + q0.x * fo0) * inv0,
                                                  (pv[nt][1] * fl0 + q0.y * fo0) * inv0);
            *(float2*)(o1 + 8 * nt) = make_float2((pv[nt][2] * fl1 + q1.x * fo1) * inv1,
                                                  (pv[nt][3] * fl1 + q1.y * fo1) * inv1);
        }
    }
}

// =========================================================================
// launch
// =========================================================================
extern "C" void kernel_launch(void* const* d_in, const int* in_sizes, int n_in,
                              void* d_out, int out_size)
{
    const float* x           = (const float*)d_in[0];
    const float* mask        = (const float*)d_in[1];
    const float* qkv_w       = (const float*)d_in[2];
    const float* logit_scale = (const float*)d_in[3];
    const float* cpb_w1      = (const float*)d_in[4];
    const float* cpb_b1      = (const float*)d_in[5];
    const float* cpb_w2      = (const float*)d_in[6];
    const float* proj_w      = (const float*)d_in[7];
    const float* proj_b      = (const float*)d_in[8];
    const float* rel_table   = (const float*)d_in[9];
    const int*   rel_index   = (const int*)d_in[10];
    float* out = (float*)d_out;

    float *qkv, *att, *tbl, *bias;
    cudaGetSymbolAddress((void**)&qkv,  g_qkv);
    cudaGetSymbolAddress((void**)&att,  g_att);
    cudaGetSymbolAddress((void**)&tbl,  g_tbl);
    cudaGetSymbolAddress((void**)&bias, g_bias);

    cudaFuncSetAttribute(gemm_f16_nt<false>,
                         cudaFuncAttributeMaxDynamicSharedMemorySize, GT_SMEM_BYTES);
    cudaFuncSetAttribute(gemm_f16_nt<true>,
                         cudaFuncAttributeMaxDynamicSharedMemorySize, GT_SMEM_BYTES);
    cudaFuncSetAttribute(attn_tc4_kernel,
                         cudaFuncAttributeMaxDynamicSharedMemorySize, ATTN_SMEM_BYTES);

    // 1) QKV projection (fp16 m16n8k16, 16 warps)
    {
        dim3 grid(QKVC / 256, MROWS / 128);
        gemm_f16_nt<false><<<grid, 512, GT_SMEM_BYTES>>>(x, qkv_w, nullptr, qkv,
                                                         MROWS, QKVC, CDIM);
    }

    // 2) relative position bias table + gather
    cpb_tbl_kernel<<<NPOS, CPBH>>>(rel_table, cpb_w1, cpb_b1, cpb_w2, tbl);
    {
        int tot = HEADS * NTOK * NTOK;
        bias_gather_kernel<<<(tot + 255) / 256, 256>>>(tbl, rel_index, bias);
    }

    // 3) attention v4 (unchanged)
    {
        dim3 grid(HEADS, BWIN);
        attn_tc4_kernel<<<grid, 576, ATTN_SMEM_BYTES>>>(qkv, bias, mask, logit_scale, att);
    }

    // 4) output projection (fp16 m16n8k16, 16 warps)
    {
        dim3 grid(CDIM / 256, MROWS / 128);
        gemm_f16_nt<true><<<grid, 512, GT_SMEM_BYTES>>>(att, proj_w, proj_b, out,
                                                        MROWS, CDIM, CDIM);
    }
}